// round 1
// baseline (speedup 1.0000x reference)
#include <cuda_runtime.h>
#include <math.h>

// Problem constants
#define BB   4
#define SS   2048
#define DD   1024
#define HH   16
#define DKK  64
#define MM   (BB*SS)          // 8192 rows

// Scratch: Q,K,V in [B,H,S,DK], X (attention out) in [B,S,D]
__device__ float g_q[(size_t)BB*HH*SS*DKK];
__device__ float g_k[(size_t)BB*HH*SS*DKK];
__device__ float g_v[(size_t)BB*HH*SS*DKK];
__device__ float g_x[(size_t)BB*SS*DD];

// ---------------------------------------------------------------------------
// SGEMM:  Y = (A @ W^T + bias) * alpha
//   A: [M, K] row-major (K = 1024), W: [N, K] row-major, bias: [N]
//   head_layout != 0  -> write Y[m][n] into [B,H,S,DK] layout
//   head_layout == 0  -> write Y[m][n] into [M, N] row-major
// Block tile 128x128, K-tile 16, 256 threads, 8x8 per-thread micro-tile.
// ---------------------------------------------------------------------------
__global__ __launch_bounds__(256) void gemm_kernel(
    const float* __restrict__ A,
    const float* __restrict__ W,
    const float* __restrict__ bias,
    float* __restrict__ Y,
    float alpha, int head_layout)
{
    const int K = DD;
    __shared__ float As[16][132];   // [k][m], padded
    __shared__ float Bs[16][132];   // [k][n], padded

    const int tid = threadIdx.x;
    const int tx  = tid & 15;       // 0..15 -> 8 cols each
    const int ty  = tid >> 4;       // 0..15 -> 8 rows each
    const int bm  = blockIdx.y * 128;
    const int bn  = blockIdx.x * 128;

    float acc[8][8];
    #pragma unroll
    for (int i = 0; i < 8; i++)
        #pragma unroll
        for (int j = 0; j < 8; j++) acc[i][j] = 0.0f;

    for (int k0 = 0; k0 < K; k0 += 16) {
        // Load A tile (128x16) and W tile (128x16), transposed into smem.
        #pragma unroll
        for (int r = 0; r < 2; r++) {
            int lin = tid + r * 256;        // 0..511
            int row = lin >> 2;             // 0..127
            int kq  = (lin & 3) << 2;       // 0,4,8,12
            float4 va = *(const float4*)&A[(size_t)(bm + row) * K + k0 + kq];
            As[kq + 0][row] = va.x;
            As[kq + 1][row] = va.y;
            As[kq + 2][row] = va.z;
            As[kq + 3][row] = va.w;
            float4 vb = *(const float4*)&W[(size_t)(bn + row) * K + k0 + kq];
            Bs[kq + 0][row] = vb.x;
            Bs[kq + 1][row] = vb.y;
            Bs[kq + 2][row] = vb.z;
            Bs[kq + 3][row] = vb.w;
        }
        __syncthreads();

        #pragma unroll
        for (int kk = 0; kk < 16; kk++) {
            float a[8], b[8];
            *(float4*)&a[0] = *(float4*)&As[kk][ty * 8];
            *(float4*)&a[4] = *(float4*)&As[kk][ty * 8 + 4];
            *(float4*)&b[0] = *(float4*)&Bs[kk][tx * 8];
            *(float4*)&b[4] = *(float4*)&Bs[kk][tx * 8 + 4];
            #pragma unroll
            for (int i = 0; i < 8; i++)
                #pragma unroll
                for (int j = 0; j < 8; j++)
                    acc[i][j] = fmaf(a[i], b[j], acc[i][j]);
        }
        __syncthreads();
    }

    // Epilogue
    #pragma unroll
    for (int i = 0; i < 8; i++) {
        int m = bm + ty * 8 + i;
        #pragma unroll
        for (int j = 0; j < 8; j++) {
            int n = bn + tx * 8 + j;
            float val = (acc[i][j] + bias[n]) * alpha;
            if (head_layout) {
                int b  = m / SS;
                int s  = m - b * SS;
                int h  = n >> 6;        // / DK
                int dk = n & 63;
                g_dummy_noop:;
                ((float*)Y)[(((size_t)(b * HH + h)) * SS + s) * DKK + dk] = val;
            } else {
                ((float*)Y)[(size_t)m * DD + n] = val;
            }
        }
    }
}

// ---------------------------------------------------------------------------
// Flash attention (fp32). One block = one (b,h) pair x one 64-query tile.
// 256 threads as 16x16; each thread owns a 4x4 tile of the 64x64 score/O
// matrices. Online softmax across 32 key tiles of 64.
// Q is pre-scaled by 1/sqrt(DK) in the projection.
// smem (dynamic): Qs[64][68] (d-major), Ks[64][68] (d-major),
//                 Vs[64][68] (k-major), Ps[64][68] (k-major)
// ---------------------------------------------------------------------------
#define AST 68   // smem row stride (floats), 16B-aligned

__global__ __launch_bounds__(256) void attn_kernel(
    const float* __restrict__ Q,
    const float* __restrict__ Kh,
    const float* __restrict__ V,
    float* __restrict__ X)
{
    extern __shared__ float sm[];
    float* Qs = sm;
    float* Ks = sm + 64 * AST;
    float* Vs = sm + 2 * 64 * AST;
    float* Ps = sm + 3 * 64 * AST;

    const int tid = threadIdx.x;
    const int tx  = tid & 15;
    const int ty  = tid >> 4;
    const int qt  = blockIdx.x;       // 0..31  query tile
    const int bh  = blockIdx.y;       // 0..63  b*H+h
    const int h   = bh & (HH - 1);
    const int bb  = bh / HH;

    const float* Qbase = Q + ((size_t)bh * SS + qt * 64) * DKK;
    const float* Kbase = Kh + (size_t)bh * SS * DKK;
    const float* Vbase = V + (size_t)bh * SS * DKK;

    // Load Q tile transposed: Qs[d][i]
    #pragma unroll
    for (int r = 0; r < 4; r++) {
        int lin = tid + r * 256;          // 0..1023
        int i   = lin >> 4;               // row 0..63
        int dq  = (lin & 15) << 2;        // 0..60 step 4
        float4 v4 = *(const float4*)&Qbase[(size_t)i * DKK + dq];
        Qs[(dq + 0) * AST + i] = v4.x;
        Qs[(dq + 1) * AST + i] = v4.y;
        Qs[(dq + 2) * AST + i] = v4.z;
        Qs[(dq + 3) * AST + i] = v4.w;
    }

    float o[4][4];
    float mrow[4], lrow[4];
    #pragma unroll
    for (int ii = 0; ii < 4; ii++) {
        mrow[ii] = -1e30f;
        lrow[ii] = 0.0f;
        #pragma unroll
        for (int jj = 0; jj < 4; jj++) o[ii][jj] = 0.0f;
    }

    for (int t = 0; t < SS / 64; t++) {
        __syncthreads();   // protect Ks/Vs/Ps against readers of prev iter (and Qs load)
        // Load K tile transposed Ks[d][j], V tile natural Vs[j][d]
        #pragma unroll
        for (int r = 0; r < 4; r++) {
            int lin = tid + r * 256;
            int j   = lin >> 4;
            int dq  = (lin & 15) << 2;
            float4 kv = *(const float4*)&Kbase[(size_t)(t * 64 + j) * DKK + dq];
            Ks[(dq + 0) * AST + j] = kv.x;
            Ks[(dq + 1) * AST + j] = kv.y;
            Ks[(dq + 2) * AST + j] = kv.z;
            Ks[(dq + 3) * AST + j] = kv.w;
            float4 vv = *(const float4*)&Vbase[(size_t)(t * 64 + j) * DKK + dq];
            *(float4*)&Vs[j * AST + dq] = vv;
        }
        __syncthreads();

        // Scores: s[4][4] = Q(rows ty*4..) . K(cols tx*4..)
        float s[4][4];
        #pragma unroll
        for (int ii = 0; ii < 4; ii++)
            #pragma unroll
            for (int jj = 0; jj < 4; jj++) s[ii][jj] = 0.0f;

        #pragma unroll 8
        for (int d = 0; d < 64; d++) {
            float4 q4 = *(const float4*)&Qs[d * AST + ty * 4];
            float4 k4 = *(const float4*)&Ks[d * AST + tx * 4];
            float qa[4] = {q4.x, q4.y, q4.z, q4.w};
            float kb[4] = {k4.x, k4.y, k4.z, k4.w};
            #pragma unroll
            for (int ii = 0; ii < 4; ii++)
                #pragma unroll
                for (int jj = 0; jj < 4; jj++)
                    s[ii][jj] = fmaf(qa[ii], kb[jj], s[ii][jj]);
        }

        // Online softmax update (row groups = 16 lanes sharing ty)
        #pragma unroll
        for (int ii = 0; ii < 4; ii++) {
            float rm = fmaxf(fmaxf(s[ii][0], s[ii][1]), fmaxf(s[ii][2], s[ii][3]));
            #pragma unroll
            for (int w = 8; w >= 1; w >>= 1)
                rm = fmaxf(rm, __shfl_xor_sync(0xffffffffu, rm, w, 16));
            float mnew = fmaxf(mrow[ii], rm);
            float c = __expf(mrow[ii] - mnew);
            float rs = 0.0f;
            #pragma unroll
            for (int jj = 0; jj < 4; jj++) {
                s[ii][jj] = __expf(s[ii][jj] - mnew);
                rs += s[ii][jj];
            }
            #pragma unroll
            for (int w = 8; w >= 1; w >>= 1)
                rs += __shfl_xor_sync(0xffffffffu, rs, w, 16);
            lrow[ii] = lrow[ii] * c + rs;
            mrow[ii] = mnew;
            #pragma unroll
            for (int jj = 0; jj < 4; jj++) o[ii][jj] *= c;
        }

        // Stage P transposed: Ps[j][i]
        #pragma unroll
        for (int jj = 0; jj < 4; jj++)
            #pragma unroll
            for (int ii = 0; ii < 4; ii++)
                Ps[(tx * 4 + jj) * AST + ty * 4 + ii] = s[ii][jj];
        __syncthreads();

        // O += P @ V : rows ty*4.., cols(dk) tx*4..
        #pragma unroll 8
        for (int j = 0; j < 64; j++) {
            float4 p4 = *(const float4*)&Ps[j * AST + ty * 4];
            float4 v4 = *(const float4*)&Vs[j * AST + tx * 4];
            float pa[4] = {p4.x, p4.y, p4.z, p4.w};
            float vb[4] = {v4.x, v4.y, v4.z, v4.w};
            #pragma unroll
            for (int ii = 0; ii < 4; ii++)
                #pragma unroll
                for (int jj = 0; jj < 4; jj++)
                    o[ii][jj] = fmaf(pa[ii], vb[jj], o[ii][jj]);
        }
    }

    // Epilogue: X[b][s][h*64 + dk] = o / l
    float* Xb = X + ((size_t)bb * SS + qt * 64) * DD + h * DKK;
    #pragma unroll
    for (int ii = 0; ii < 4; ii++) {
        int i = ty * 4 + ii;
        float inv = 1.0f / lrow[ii];
        #pragma unroll
        for (int jj = 0; jj < 4; jj++) {
            Xb[(size_t)i * DD + tx * 4 + jj] = o[ii][jj] * inv;
        }
    }
}

// ---------------------------------------------------------------------------
extern "C" void kernel_launch(void* const* d_in, const int* in_sizes, int n_in,
                              void* d_out, int out_size)
{
    const float* query = (const float*)d_in[0];
    const float* key_  = (const float*)d_in[1];
    const float* value = (const float*)d_in[2];
    const float* Wq    = (const float*)d_in[3];
    const float* bq    = (const float*)d_in[4];
    const float* Wk    = (const float*)d_in[5];
    const float* bk    = (const float*)d_in[6];
    const float* Wv    = (const float*)d_in[7];
    const float* bv    = (const float*)d_in[8];
    const float* Wo    = (const float*)d_in[9];
    const float* bo    = (const float*)d_in[10];
    float* out = (float*)d_out;

    float *q, *k, *v, *x;
    cudaGetSymbolAddress((void**)&q, g_q);
    cudaGetSymbolAddress((void**)&k, g_k);
    cudaGetSymbolAddress((void**)&v, g_v);
    cudaGetSymbolAddress((void**)&x, g_x);

    const int attn_smem = 4 * 64 * AST * (int)sizeof(float);   // 69632 B
    cudaFuncSetAttribute(attn_kernel,
                         cudaFuncAttributeMaxDynamicSharedMemorySize, attn_smem);

    dim3 ggrid(DD / 128, MM / 128);   // 8 x 64

    // Projections (Q pre-scaled by 1/sqrt(DK) = 1/8)
    gemm_kernel<<<ggrid, 256>>>(query, Wq, bq, q, 0.125f, 1);
    gemm_kernel<<<ggrid, 256>>>(key_,  Wk, bk, k, 1.0f,   1);
    gemm_kernel<<<ggrid, 256>>>(value, Wv, bv, v, 1.0f,   1);

    // Attention
    attn_kernel<<<dim3(SS / 64, BB * HH), 256, attn_smem>>>(q, k, v, x);

    // Output projection -> d_out
    gemm_kernel<<<ggrid, 256>>>(x, Wo, bo, out, 1.0f, 0);
}

// round 2
// speedup vs baseline: 1.0759x; 1.0759x over previous
#include <cuda_runtime.h>
#include <math.h>
#include <stdint.h>

// Problem constants
#define BB   4
#define SS   2048
#define DD   1024
#define HH   16
#define DKK  64
#define MM   (BB*SS)          // 8192 rows

// Scratch: Q,K,V in [B,H,S,DK], X (attention out) in [B,S,D]
__device__ float g_q[(size_t)BB*HH*SS*DKK];
__device__ float g_k[(size_t)BB*HH*SS*DKK];
__device__ float g_v[(size_t)BB*HH*SS*DKK];
__device__ float g_x[(size_t)BB*SS*DD];

// ---------------------------------------------------------------------------
// tf32 helpers
// ---------------------------------------------------------------------------
__device__ __forceinline__ uint32_t f2tf(float x) {
    uint32_t u;
    asm("cvt.rna.tf32.f32 %0, %1;" : "=r"(u) : "f"(x));
    return u;
}

// D(16x8,f32) += A(16x8,tf32) * B(8x8,tf32)
__device__ __forceinline__ void mma8(float* d, const uint32_t* a, const uint32_t* b) {
    asm("mma.sync.aligned.m16n8k8.row.col.f32.tf32.tf32.f32 "
        "{%0,%1,%2,%3}, {%4,%5,%6,%7}, {%8,%9}, {%0,%1,%2,%3};"
        : "+f"(d[0]), "+f"(d[1]), "+f"(d[2]), "+f"(d[3])
        : "r"(a[0]), "r"(a[1]), "r"(a[2]), "r"(a[3]),
          "r"(b[0]), "r"(b[1]));
}

// ---------------------------------------------------------------------------
// 3xTF32 SGEMM:  Y = (A @ W^T + bias) * alpha
//   A: [M,1024] row-major, W: [N,1024] row-major, bias: [N]
//   head_layout: write [B,H,S,DK] layout, else [M,N] row-major.
// Block 128x128, BK=16, 256 threads (8 warps), warp tile 64x32 (4x4 m16n8).
// ---------------------------------------------------------------------------
#define SA 20   // smem row stride (floats): (r*20+q) mod 32 conflict-free

__global__ __launch_bounds__(256) void gemm_tf32(
    const float* __restrict__ A,
    const float* __restrict__ W,
    const float* __restrict__ bias,
    float* __restrict__ Y,
    float alpha, int head_layout)
{
    __shared__ float As[128 * SA];
    __shared__ float Bs[128 * SA];

    const int tid  = threadIdx.x;
    const int lane = tid & 31;
    const int wrp  = tid >> 5;
    const int wy   = wrp & 1;          // m-warp (0..1), 64 rows
    const int wx   = wrp >> 1;         // n-warp (0..3), 32 cols
    const int r    = lane >> 2;        // 0..7
    const int q    = lane & 3;         // 0..3
    const int bm   = blockIdx.y * 128;
    const int bn   = blockIdx.x * 128;

    float c[4][4][4];
    #pragma unroll
    for (int mt = 0; mt < 4; mt++)
        #pragma unroll
        for (int nt = 0; nt < 4; nt++)
            #pragma unroll
            for (int i = 0; i < 4; i++) c[mt][nt][i] = 0.0f;

    for (int kt = 0; kt < DD; kt += 16) {
        // Stage A/W tiles (128x16) into smem, raw fp32.
        #pragma unroll
        for (int rr = 0; rr < 2; rr++) {
            int lin = tid + rr * 256;      // 0..511
            int row = lin >> 2;            // 0..127
            int kq  = (lin & 3) << 2;      // 0,4,8,12
            *(float4*)&As[row * SA + kq] =
                *(const float4*)&A[(size_t)(bm + row) * DD + kt + kq];
            *(float4*)&Bs[row * SA + kq] =
                *(const float4*)&W[(size_t)(bn + row) * DD + kt + kq];
        }
        __syncthreads();

        #pragma unroll
        for (int ks = 0; ks < 16; ks += 8) {
            uint32_t ah[4][4], al[4][4], bh[4][2], bl[4][2];
            #pragma unroll
            for (int mt = 0; mt < 4; mt++) {
                int m0 = wy * 64 + mt * 16 + r;
                float f0 = As[m0 * SA + ks + q];
                float f1 = As[(m0 + 8) * SA + ks + q];
                float f2 = As[m0 * SA + ks + q + 4];
                float f3 = As[(m0 + 8) * SA + ks + q + 4];
                ah[mt][0] = f2tf(f0); al[mt][0] = f2tf(f0 - __uint_as_float(ah[mt][0]));
                ah[mt][1] = f2tf(f1); al[mt][1] = f2tf(f1 - __uint_as_float(ah[mt][1]));
                ah[mt][2] = f2tf(f2); al[mt][2] = f2tf(f2 - __uint_as_float(ah[mt][2]));
                ah[mt][3] = f2tf(f3); al[mt][3] = f2tf(f3 - __uint_as_float(ah[mt][3]));
            }
            #pragma unroll
            for (int nt = 0; nt < 4; nt++) {
                int n0 = wx * 32 + nt * 8 + r;
                float f0 = Bs[n0 * SA + ks + q];
                float f1 = Bs[n0 * SA + ks + q + 4];
                bh[nt][0] = f2tf(f0); bl[nt][0] = f2tf(f0 - __uint_as_float(bh[nt][0]));
                bh[nt][1] = f2tf(f1); bl[nt][1] = f2tf(f1 - __uint_as_float(bh[nt][1]));
            }
            #pragma unroll
            for (int mt = 0; mt < 4; mt++)
                #pragma unroll
                for (int nt = 0; nt < 4; nt++) {
                    mma8(c[mt][nt], al[mt], bh[nt]);
                    mma8(c[mt][nt], ah[mt], bl[nt]);
                    mma8(c[mt][nt], ah[mt], bh[nt]);
                }
        }
        __syncthreads();
    }

    // Epilogue: C frag (reg0:(r,2q) reg1:(r,2q+1) reg2:(r+8,2q) reg3:(r+8,2q+1))
    #pragma unroll
    for (int mt = 0; mt < 4; mt++) {
        #pragma unroll
        for (int nt = 0; nt < 4; nt++) {
            #pragma unroll
            for (int i = 0; i < 4; i++) {
                int m = bm + wy * 64 + mt * 16 + r + ((i & 2) ? 8 : 0);
                int n = bn + wx * 32 + nt * 8 + 2 * q + (i & 1);
                float val = (c[mt][nt][i] + bias[n]) * alpha;
                if (head_layout) {
                    int b  = m >> 11;         // / SS
                    int s  = m & (SS - 1);
                    int h  = n >> 6;          // / DK
                    int dk = n & 63;
                    Y[(((size_t)(b * HH + h)) * SS + s) * DKK + dk] = val;
                } else {
                    Y[(size_t)m * DD + n] = val;
                }
            }
        }
    }
}

// ---------------------------------------------------------------------------
// 3xTF32 flash attention. One block = one (b,h) x 64-query tile.
// 128 threads (4 warps); each warp owns 16 query rows x all 64 keys/dims.
// Q fragments live in registers for the whole kernel; K/V staged in smem
// (fp32, split to tf32 hi/lo at fragment load). Online softmax.
// ---------------------------------------------------------------------------
#define KST 68   // Ks[key][dk]  : (r*4+q)   conflict-free frag loads
#define VST 72   // Vs[key][dk]  : (q*8+r)   conflict-free frag loads
#define PST 68   // Ps[row][key] : (r*4+q)   conflict-free frag loads

__global__ __launch_bounds__(128) void attn_tf32(
    const float* __restrict__ Q,
    const float* __restrict__ Kh,
    const float* __restrict__ V,
    float* __restrict__ X)
{
    extern __shared__ float sm[];
    float* Ks = sm;                      // 64*68
    float* Vs = Ks + 64 * KST;           // 64*72
    float* Ps = Vs + 64 * VST;           // 64*68

    const int tid  = threadIdx.x;
    const int lane = tid & 31;
    const int w    = tid >> 5;           // warp 0..3 -> query rows w*16..
    const int r    = lane >> 2;          // 0..7
    const int q    = lane & 3;           // 0..3
    const int qt   = blockIdx.x;         // 0..31
    const int bh   = blockIdx.y;         // 0..63
    const int h    = bh & (HH - 1);
    const int bb   = bh >> 4;

    const float* Qbase = Q + ((size_t)bh * SS + qt * 64 + w * 16) * DKK;
    const float* Kbase = Kh + (size_t)bh * SS * DKK;
    const float* Vbase = V + (size_t)bh * SS * DKK;

    // Preload Q fragments (m16 x k64 = 8 k-steps), split hi/lo. 64 regs.
    uint32_t qh[8][4], ql[8][4];
    #pragma unroll
    for (int kt = 0; kt < 8; kt++) {
        int k0 = kt * 8;
        float f0 = Qbase[(size_t)r * DKK + k0 + q];
        float f1 = Qbase[(size_t)(r + 8) * DKK + k0 + q];
        float f2 = Qbase[(size_t)r * DKK + k0 + q + 4];
        float f3 = Qbase[(size_t)(r + 8) * DKK + k0 + q + 4];
        qh[kt][0] = f2tf(f0); ql[kt][0] = f2tf(f0 - __uint_as_float(qh[kt][0]));
        qh[kt][1] = f2tf(f1); ql[kt][1] = f2tf(f1 - __uint_as_float(qh[kt][1]));
        qh[kt][2] = f2tf(f2); ql[kt][2] = f2tf(f2 - __uint_as_float(qh[kt][2]));
        qh[kt][3] = f2tf(f3); ql[kt][3] = f2tf(f3 - __uint_as_float(qh[kt][3]));
    }

    float o[8][4];                       // 8 d-tiles (n8) x 4 regs
    #pragma unroll
    for (int dt = 0; dt < 8; dt++)
        #pragma unroll
        for (int i = 0; i < 4; i++) o[dt][i] = 0.0f;
    float mrow[2] = {-1e30f, -1e30f};    // rows r, r+8
    float lrow[2] = {0.0f, 0.0f};

    for (int t = 0; t < SS / 64; t++) {
        __syncthreads();   // all warps done reading Ks/Vs from prev iter
        // Stage K/V tile (64 keys x 64 dims), raw fp32, float4 I/O.
        #pragma unroll
        for (int rr = 0; rr < 8; rr++) {
            int lin = tid + rr * 128;     // 0..1023
            int j   = lin >> 4;           // key 0..63
            int dq  = (lin & 15) << 2;    // 0..60
            float4 kv = *(const float4*)&Kbase[(size_t)(t * 64 + j) * DKK + dq];
            *(float4*)&Ks[j * KST + dq] = kv;
            float4 vv = *(const float4*)&Vbase[(size_t)(t * 64 + j) * DKK + dq];
            *(float4*)&Vs[j * VST + dq] = vv;
        }
        __syncthreads();

        // ---- S = Q K^T  (16 x 64 per warp), 3xTF32 ----
        float s[8][4];
        #pragma unroll
        for (int nt = 0; nt < 8; nt++)
            #pragma unroll
            for (int i = 0; i < 4; i++) s[nt][i] = 0.0f;

        #pragma unroll
        for (int kt = 0; kt < 8; kt++) {
            int k0 = kt * 8;
            #pragma unroll
            for (int nt = 0; nt < 8; nt++) {
                int krow = nt * 8 + r;
                float f0 = Ks[krow * KST + k0 + q];
                float f1 = Ks[krow * KST + k0 + q + 4];
                uint32_t bhf[2], blf[2];
                bhf[0] = f2tf(f0); blf[0] = f2tf(f0 - __uint_as_float(bhf[0]));
                bhf[1] = f2tf(f1); blf[1] = f2tf(f1 - __uint_as_float(bhf[1]));
                mma8(s[nt], ql[kt], bhf);
                mma8(s[nt], qh[kt], blf);
                mma8(s[nt], qh[kt], bhf);
            }
        }

        // ---- online softmax (rows r / r+8 per thread; 4-lane groups) ----
        #pragma unroll
        for (int half = 0; half < 2; half++) {
            float rm = -1e30f;
            #pragma unroll
            for (int nt = 0; nt < 8; nt++)
                rm = fmaxf(rm, fmaxf(s[nt][2 * half], s[nt][2 * half + 1]));
            rm = fmaxf(rm, __shfl_xor_sync(0xffffffffu, rm, 1));
            rm = fmaxf(rm, __shfl_xor_sync(0xffffffffu, rm, 2));
            float mnew  = fmaxf(mrow[half], rm);
            float scale = __expf(mrow[half] - mnew);
            float rs = 0.0f;
            #pragma unroll
            for (int nt = 0; nt < 8; nt++) {
                s[nt][2 * half]     = __expf(s[nt][2 * half] - mnew);
                s[nt][2 * half + 1] = __expf(s[nt][2 * half + 1] - mnew);
                rs += s[nt][2 * half] + s[nt][2 * half + 1];
            }
            rs += __shfl_xor_sync(0xffffffffu, rs, 1);
            rs += __shfl_xor_sync(0xffffffffu, rs, 2);
            lrow[half] = lrow[half] * scale + rs;
            mrow[half] = mnew;
            #pragma unroll
            for (int dt = 0; dt < 8; dt++) {
                o[dt][2 * half]     *= scale;
                o[dt][2 * half + 1] *= scale;
            }
        }

        // ---- stage P (warp-private rows) ----
        #pragma unroll
        for (int nt = 0; nt < 8; nt++) {
            int col = nt * 8 + 2 * q;
            Ps[(w * 16 + r) * PST + col]         = s[nt][0];
            Ps[(w * 16 + r) * PST + col + 1]     = s[nt][1];
            Ps[(w * 16 + r + 8) * PST + col]     = s[nt][2];
            Ps[(w * 16 + r + 8) * PST + col + 1] = s[nt][3];
        }
        __syncwarp();

        // ---- O += P V  (16 x 64 per warp), 3xTF32 ----
        #pragma unroll
        for (int kt = 0; kt < 8; kt++) {
            int k0 = kt * 8;
            float p0 = Ps[(w * 16 + r) * PST + k0 + q];
            float p1 = Ps[(w * 16 + r + 8) * PST + k0 + q];
            float p2 = Ps[(w * 16 + r) * PST + k0 + q + 4];
            float p3 = Ps[(w * 16 + r + 8) * PST + k0 + q + 4];
            uint32_t ph[4], pl[4];
            ph[0] = f2tf(p0); pl[0] = f2tf(p0 - __uint_as_float(ph[0]));
            ph[1] = f2tf(p1); pl[1] = f2tf(p1 - __uint_as_float(ph[1]));
            ph[2] = f2tf(p2); pl[2] = f2tf(p2 - __uint_as_float(ph[2]));
            ph[3] = f2tf(p3); pl[3] = f2tf(p3 - __uint_as_float(ph[3]));
            #pragma unroll
            for (int dt = 0; dt < 8; dt++) {
                float f0 = Vs[(k0 + q) * VST + dt * 8 + r];
                float f1 = Vs[(k0 + q + 4) * VST + dt * 8 + r];
                uint32_t vh[2], vl[2];
                vh[0] = f2tf(f0); vl[0] = f2tf(f0 - __uint_as_float(vh[0]));
                vh[1] = f2tf(f1); vl[1] = f2tf(f1 - __uint_as_float(vh[1]));
                mma8(o[dt], pl[0] == 0 ? pl : pl, vh);   // D += Plo*Vhi
                mma8(o[dt], ph, vl);                     // D += Phi*Vlo
                mma8(o[dt], ph, vh);                     // D += Phi*Vhi
            }
        }
    }

    // Epilogue: X[b][s][h*64+dk] = o / l
    float inv0 = 1.0f / lrow[0];
    float inv1 = 1.0f / lrow[1];
    float* Xb = X + ((size_t)bb * SS + qt * 64 + w * 16) * DD + h * DKK;
    #pragma unroll
    for (int dt = 0; dt < 8; dt++) {
        int col = dt * 8 + 2 * q;
        Xb[(size_t)r * DD + col]           = o[dt][0] * inv0;
        Xb[(size_t)r * DD + col + 1]       = o[dt][1] * inv0;
        Xb[(size_t)(r + 8) * DD + col]     = o[dt][2] * inv1;
        Xb[(size_t)(r + 8) * DD + col + 1] = o[dt][3] * inv1;
    }
}

// ---------------------------------------------------------------------------
extern "C" void kernel_launch(void* const* d_in, const int* in_sizes, int n_in,
                              void* d_out, int out_size)
{
    const float* query = (const float*)d_in[0];
    const float* key_  = (const float*)d_in[1];
    const float* value = (const float*)d_in[2];
    const float* Wq    = (const float*)d_in[3];
    const float* bq    = (const float*)d_in[4];
    const float* Wk    = (const float*)d_in[5];
    const float* bk    = (const float*)d_in[6];
    const float* Wv    = (const float*)d_in[7];
    const float* bv    = (const float*)d_in[8];
    const float* Wo    = (const float*)d_in[9];
    const float* bo    = (const float*)d_in[10];
    float* out = (float*)d_out;

    float *q, *k, *v, *x;
    cudaGetSymbolAddress((void**)&q, g_q);
    cudaGetSymbolAddress((void**)&k, g_k);
    cudaGetSymbolAddress((void**)&v, g_v);
    cudaGetSymbolAddress((void**)&x, g_x);

    const int attn_smem = (64 * KST + 64 * VST + 64 * PST) * (int)sizeof(float); // 53248
    cudaFuncSetAttribute(attn_tf32,
                         cudaFuncAttributeMaxDynamicSharedMemorySize, attn_smem);

    dim3 ggrid(DD / 128, MM / 128);   // 8 x 64

    // Projections (Q pre-scaled by 1/sqrt(DK) = 1/8)
    gemm_tf32<<<ggrid, 256>>>(query, Wq, bq, q, 0.125f, 1);
    gemm_tf32<<<ggrid, 256>>>(key_,  Wk, bk, k, 1.0f,   1);
    gemm_tf32<<<ggrid, 256>>>(value, Wv, bv, v, 1.0f,   1);

    // Attention
    attn_tf32<<<dim3(SS / 64, BB * HH), 128, attn_smem>>>(q, k, v, x);

    // Output projection -> d_out
    gemm_tf32<<<ggrid, 256>>>(x, Wo, bo, out, 1.0f, 0);
}

// round 4
// speedup vs baseline: 1.3014x; 1.2096x over previous
#include <cuda_runtime.h>
#include <math.h>
#include <stdint.h>

// Problem constants
#define BB   4
#define SS   2048
#define DD   1024
#define HH   16
#define DKK  64
#define MM   (BB*SS)          // 8192 rows

// Scratch: Q,K,V in [B,H,S,DK], X (attention out) in [B,S,D]
__device__ float g_q[(size_t)BB*HH*SS*DKK];
__device__ float g_k[(size_t)BB*HH*SS*DKK];
__device__ float g_v[(size_t)BB*HH*SS*DKK];
__device__ float g_x[(size_t)BB*SS*DD];

// ---------------------------------------------------------------------------
// tf32 helpers
// ---------------------------------------------------------------------------
__device__ __forceinline__ uint32_t f2tf(float x) {
    uint32_t u;
    asm("cvt.rna.tf32.f32 %0, %1;" : "=r"(u) : "f"(x));
    return u;
}
// split x into hi (tf32-rounded, as float bits) and lo residual (tf32, float bits)
__device__ __forceinline__ void split_tf(float x, float& hi, float& lo) {
    uint32_t h = f2tf(x);
    hi = __uint_as_float(h);
    lo = __uint_as_float(f2tf(x - hi));
}

// D(16x8,f32) += A(16x8,tf32) * B(8x8,tf32)
__device__ __forceinline__ void mma8(float* d, const uint32_t* a, const uint32_t* b) {
    asm("mma.sync.aligned.m16n8k8.row.col.f32.tf32.tf32.f32 "
        "{%0,%1,%2,%3}, {%4,%5,%6,%7}, {%8,%9}, {%0,%1,%2,%3};"
        : "+f"(d[0]), "+f"(d[1]), "+f"(d[2]), "+f"(d[3])
        : "r"(a[0]), "r"(a[1]), "r"(a[2]), "r"(a[3]),
          "r"(b[0]), "r"(b[1]));
}

// ---------------------------------------------------------------------------
// 3xTF32 SGEMM core:  Y = (A @ W^T + bias) * alpha
// Block 128x128, BK=16, 256 threads (8 warps), warp tile 64x32.
// smem holds PRE-SPLIT hi/lo planes: each element converted once per tile.
// ---------------------------------------------------------------------------
#define SA 20   // smem row stride (floats): (r*20+q) mod 32 bijective

struct GemmArgs {
    const float* A; const float* W; const float* bias;
    float* Y; float alpha; int head_layout;
};

__device__ __forceinline__ void gemm_core(const GemmArgs& g)
{
    __shared__ float Ash[128 * SA], Asl[128 * SA];
    __shared__ float Bsh[128 * SA], Bsl[128 * SA];

    const int tid  = threadIdx.x;
    const int lane = tid & 31;
    const int wrp  = tid >> 5;
    const int wy   = wrp & 1;          // m-warp (0..1), 64 rows
    const int wx   = wrp >> 1;         // n-warp (0..3), 32 cols
    const int r    = lane >> 2;        // 0..7
    const int q    = lane & 3;         // 0..3
    const int bm   = blockIdx.y * 128;
    const int bn   = blockIdx.x * 128;

    float c[4][4][4];
    #pragma unroll
    for (int mt = 0; mt < 4; mt++)
        #pragma unroll
        for (int nt = 0; nt < 4; nt++)
            #pragma unroll
            for (int i = 0; i < 4; i++) c[mt][nt][i] = 0.0f;

    for (int kt = 0; kt < DD; kt += 16) {
        // Stage + split A/W tiles (128x16) into hi/lo smem planes.
        #pragma unroll
        for (int rr = 0; rr < 2; rr++) {
            int lin = tid + rr * 256;      // 0..511
            int row = lin >> 2;            // 0..127
            int kq  = (lin & 3) << 2;      // 0,4,8,12
            float4 va = *(const float4*)&g.A[(size_t)(bm + row) * DD + kt + kq];
            float4 ha, la;
            split_tf(va.x, ha.x, la.x); split_tf(va.y, ha.y, la.y);
            split_tf(va.z, ha.z, la.z); split_tf(va.w, ha.w, la.w);
            *(float4*)&Ash[row * SA + kq] = ha;
            *(float4*)&Asl[row * SA + kq] = la;
            float4 vb = *(const float4*)&g.W[(size_t)(bn + row) * DD + kt + kq];
            float4 hb, lb;
            split_tf(vb.x, hb.x, lb.x); split_tf(vb.y, hb.y, lb.y);
            split_tf(vb.z, hb.z, lb.z); split_tf(vb.w, hb.w, lb.w);
            *(float4*)&Bsh[row * SA + kq] = hb;
            *(float4*)&Bsl[row * SA + kq] = lb;
        }
        __syncthreads();

        #pragma unroll
        for (int ks = 0; ks < 16; ks += 8) {
            uint32_t ah[4][4], al[4][4], bh[4][2], bl[4][2];
            #pragma unroll
            for (int mt = 0; mt < 4; mt++) {
                int m0 = wy * 64 + mt * 16 + r;
                int i0 = m0 * SA + ks + q;
                int i1 = (m0 + 8) * SA + ks + q;
                ah[mt][0] = __float_as_uint(Ash[i0]);
                ah[mt][1] = __float_as_uint(Ash[i1]);
                ah[mt][2] = __float_as_uint(Ash[i0 + 4]);
                ah[mt][3] = __float_as_uint(Ash[i1 + 4]);
                al[mt][0] = __float_as_uint(Asl[i0]);
                al[mt][1] = __float_as_uint(Asl[i1]);
                al[mt][2] = __float_as_uint(Asl[i0 + 4]);
                al[mt][3] = __float_as_uint(Asl[i1 + 4]);
            }
            #pragma unroll
            for (int nt = 0; nt < 4; nt++) {
                int n0 = (wx * 32 + nt * 8 + r) * SA + ks + q;
                bh[nt][0] = __float_as_uint(Bsh[n0]);
                bh[nt][1] = __float_as_uint(Bsh[n0 + 4]);
                bl[nt][0] = __float_as_uint(Bsl[n0]);
                bl[nt][1] = __float_as_uint(Bsl[n0 + 4]);
            }
            #pragma unroll
            for (int mt = 0; mt < 4; mt++)
                #pragma unroll
                for (int nt = 0; nt < 4; nt++) {
                    mma8(c[mt][nt], al[mt], bh[nt]);
                    mma8(c[mt][nt], ah[mt], bl[nt]);
                    mma8(c[mt][nt], ah[mt], bh[nt]);
                }
        }
        __syncthreads();
    }

    // Epilogue: frag reg pairs (i, i+1) are columns (2q, 2q+1) -> float2 stores
    #pragma unroll
    for (int mt = 0; mt < 4; mt++) {
        #pragma unroll
        for (int nt = 0; nt < 4; nt++) {
            int n = bn + wx * 32 + nt * 8 + 2 * q;
            float b0 = g.bias[n], b1 = g.bias[n + 1];
            #pragma unroll
            for (int half = 0; half < 2; half++) {
                int m = bm + wy * 64 + mt * 16 + r + half * 8;
                float2 val;
                val.x = (c[mt][nt][2 * half]     + b0) * g.alpha;
                val.y = (c[mt][nt][2 * half + 1] + b1) * g.alpha;
                if (g.head_layout) {
                    int b  = m >> 11;         // / SS
                    int s  = m & (SS - 1);
                    int h  = n >> 6;          // / DK
                    int dk = n & 63;
                    *(float2*)&g.Y[(((size_t)(b * HH + h)) * SS + s) * DKK + dk] = val;
                } else {
                    *(float2*)&g.Y[(size_t)m * DD + n] = val;
                }
            }
        }
    }
}

// Fused QKV projection: blockIdx.z selects which projection.
__global__ __launch_bounds__(256, 1) void gemm_qkv(GemmArgs g0, GemmArgs g1, GemmArgs g2)
{
    if (blockIdx.z == 0)      gemm_core(g0);
    else if (blockIdx.z == 1) gemm_core(g1);
    else                      gemm_core(g2);
}

__global__ __launch_bounds__(256, 1) void gemm_one(GemmArgs g0)
{
    gemm_core(g0);
}

// ---------------------------------------------------------------------------
// 3xTF32 flash attention. One block = one (b,h) x 64-query tile.
// 128 threads (4 warps); warp owns 16 query rows x all 64 keys/dims.
// K/V staged PRE-SPLIT (hi/lo planes) in smem: converted once, not per warp.
// Q fragments in registers for the whole kernel. Online softmax.
// ---------------------------------------------------------------------------
#define KST 68   // K planes [key][dk] : addr%32 = r*4+q  bijective
#define VST 72   // V planes [key][dk] : addr%32 = q*8+r  bijective
#define PST 68   // Ps [row][key]      : read addr%32 = r*4+q bijective

__global__ __launch_bounds__(128, 2) void attn_tf32(
    const float* __restrict__ Q,
    const float* __restrict__ Kh,
    const float* __restrict__ V,
    float* __restrict__ X)
{
    extern __shared__ float sm[];
    float* Ksh = sm;
    float* Ksl = Ksh + 64 * KST;
    float* Vsh = Ksl + 64 * KST;
    float* Vsl = Vsh + 64 * VST;
    float* Ps  = Vsl + 64 * VST;

    const int tid  = threadIdx.x;
    const int lane = tid & 31;
    const int w    = tid >> 5;           // warp 0..3 -> query rows w*16..
    const int r    = lane >> 2;          // 0..7
    const int q    = lane & 3;           // 0..3
    const int qt   = blockIdx.x;         // 0..31
    const int bh   = blockIdx.y;         // 0..63
    const int h    = bh & (HH - 1);
    const int bb   = bh >> 4;

    const float* Qbase = Q + ((size_t)bh * SS + qt * 64 + w * 16) * DKK;
    const float* Kbase = Kh + (size_t)bh * SS * DKK;
    const float* Vbase = V + (size_t)bh * SS * DKK;

    // Preload Q fragments (m16 x k64 = 8 k-steps), split hi/lo. 64 regs.
    uint32_t qh[8][4], ql[8][4];
    #pragma unroll
    for (int kt = 0; kt < 8; kt++) {
        int k0 = kt * 8;
        float f0 = Qbase[(size_t)r * DKK + k0 + q];
        float f1 = Qbase[(size_t)(r + 8) * DKK + k0 + q];
        float f2 = Qbase[(size_t)r * DKK + k0 + q + 4];
        float f3 = Qbase[(size_t)(r + 8) * DKK + k0 + q + 4];
        float hi, lo;
        split_tf(f0, hi, lo); qh[kt][0] = __float_as_uint(hi); ql[kt][0] = __float_as_uint(lo);
        split_tf(f1, hi, lo); qh[kt][1] = __float_as_uint(hi); ql[kt][1] = __float_as_uint(lo);
        split_tf(f2, hi, lo); qh[kt][2] = __float_as_uint(hi); ql[kt][2] = __float_as_uint(lo);
        split_tf(f3, hi, lo); qh[kt][3] = __float_as_uint(hi); ql[kt][3] = __float_as_uint(lo);
    }

    float o[8][4];                       // 8 d-tiles (n8) x 4 regs
    #pragma unroll
    for (int dt = 0; dt < 8; dt++)
        #pragma unroll
        for (int i = 0; i < 4; i++) o[dt][i] = 0.0f;
    float mrow[2] = {-1e30f, -1e30f};    // rows r, r+8
    float lrow[2] = {0.0f, 0.0f};

    for (int t = 0; t < SS / 64; t++) {
        __syncthreads();   // all warps done reading K/V planes from prev iter
        // Stage + split K/V tile (64 keys x 64 dims) into hi/lo planes.
        #pragma unroll
        for (int rr = 0; rr < 8; rr++) {
            int lin = tid + rr * 128;     // 0..1023
            int j   = lin >> 4;           // key 0..63
            int dq  = (lin & 15) << 2;    // 0..60
            float4 kv = *(const float4*)&Kbase[(size_t)(t * 64 + j) * DKK + dq];
            float4 kh4, kl4;
            split_tf(kv.x, kh4.x, kl4.x); split_tf(kv.y, kh4.y, kl4.y);
            split_tf(kv.z, kh4.z, kl4.z); split_tf(kv.w, kh4.w, kl4.w);
            *(float4*)&Ksh[j * KST + dq] = kh4;
            *(float4*)&Ksl[j * KST + dq] = kl4;
            float4 vv = *(const float4*)&Vbase[(size_t)(t * 64 + j) * DKK + dq];
            float4 vh4, vl4;
            split_tf(vv.x, vh4.x, vl4.x); split_tf(vv.y, vh4.y, vl4.y);
            split_tf(vv.z, vh4.z, vl4.z); split_tf(vv.w, vh4.w, vl4.w);
            *(float4*)&Vsh[j * VST + dq] = vh4;
            *(float4*)&Vsl[j * VST + dq] = vl4;
        }
        __syncthreads();

        // ---- S = Q K^T  (16 x 64 per warp), 3xTF32, pure LDS+MMA ----
        float s[8][4];
        #pragma unroll
        for (int nt = 0; nt < 8; nt++)
            #pragma unroll
            for (int i = 0; i < 4; i++) s[nt][i] = 0.0f;

        #pragma unroll
        for (int kt = 0; kt < 8; kt++) {
            int k0 = kt * 8;
            #pragma unroll
            for (int nt = 0; nt < 8; nt++) {
                int idx = (nt * 8 + r) * KST + k0 + q;
                uint32_t bhf[2], blf[2];
                bhf[0] = __float_as_uint(Ksh[idx]);
                bhf[1] = __float_as_uint(Ksh[idx + 4]);
                blf[0] = __float_as_uint(Ksl[idx]);
                blf[1] = __float_as_uint(Ksl[idx + 4]);
                mma8(s[nt], ql[kt], bhf);
                mma8(s[nt], qh[kt], blf);
                mma8(s[nt], qh[kt], bhf);
            }
        }

        // ---- online softmax (rows r / r+8; 4-lane row groups) ----
        #pragma unroll
        for (int half = 0; half < 2; half++) {
            float rm = -1e30f;
            #pragma unroll
            for (int nt = 0; nt < 8; nt++)
                rm = fmaxf(rm, fmaxf(s[nt][2 * half], s[nt][2 * half + 1]));
            rm = fmaxf(rm, __shfl_xor_sync(0xffffffffu, rm, 1));
            rm = fmaxf(rm, __shfl_xor_sync(0xffffffffu, rm, 2));
            float mnew  = fmaxf(mrow[half], rm);
            float scale = __expf(mrow[half] - mnew);
            float rs = 0.0f;
            #pragma unroll
            for (int nt = 0; nt < 8; nt++) {
                s[nt][2 * half]     = __expf(s[nt][2 * half] - mnew);
                s[nt][2 * half + 1] = __expf(s[nt][2 * half + 1] - mnew);
                rs += s[nt][2 * half] + s[nt][2 * half + 1];
            }
            rs += __shfl_xor_sync(0xffffffffu, rs, 1);
            rs += __shfl_xor_sync(0xffffffffu, rs, 2);
            lrow[half] = lrow[half] * scale + rs;
            mrow[half] = mnew;
            #pragma unroll
            for (int dt = 0; dt < 8; dt++) {
                o[dt][2 * half]     *= scale;
                o[dt][2 * half + 1] *= scale;
            }
        }

        // ---- stage P (warp-private rows) ----
        #pragma unroll
        for (int nt = 0; nt < 8; nt++) {
            int col = nt * 8 + 2 * q;
            Ps[(w * 16 + r) * PST + col]         = s[nt][0];
            Ps[(w * 16 + r) * PST + col + 1]     = s[nt][1];
            Ps[(w * 16 + r + 8) * PST + col]     = s[nt][2];
            Ps[(w * 16 + r + 8) * PST + col + 1] = s[nt][3];
        }
        __syncwarp();

        // ---- O += P V  (16 x 64 per warp), 3xTF32 ----
        #pragma unroll
        for (int kt = 0; kt < 8; kt++) {
            int k0 = kt * 8;
            float p0 = Ps[(w * 16 + r) * PST + k0 + q];
            float p1 = Ps[(w * 16 + r + 8) * PST + k0 + q];
            float p2 = Ps[(w * 16 + r) * PST + k0 + q + 4];
            float p3 = Ps[(w * 16 + r + 8) * PST + k0 + q + 4];
            uint32_t ph[4], pl[4];
            float hi, lo;
            split_tf(p0, hi, lo); ph[0] = __float_as_uint(hi); pl[0] = __float_as_uint(lo);
            split_tf(p1, hi, lo); ph[1] = __float_as_uint(hi); pl[1] = __float_as_uint(lo);
            split_tf(p2, hi, lo); ph[2] = __float_as_uint(hi); pl[2] = __float_as_uint(lo);
            split_tf(p3, hi, lo); ph[3] = __float_as_uint(hi); pl[3] = __float_as_uint(lo);
            #pragma unroll
            for (int dt = 0; dt < 8; dt++) {
                int idx = (k0 + q) * VST + dt * 8 + r;
                int idx2 = (k0 + q + 4) * VST + dt * 8 + r;
                uint32_t vh[2], vl[2];
                vh[0] = __float_as_uint(Vsh[idx]);
                vh[1] = __float_as_uint(Vsh[idx2]);
                vl[0] = __float_as_uint(Vsl[idx]);
                vl[1] = __float_as_uint(Vsl[idx2]);
                mma8(o[dt], pl, vh);
                mma8(o[dt], ph, vl);
                mma8(o[dt], ph, vh);
            }
        }
    }

    // Epilogue: X[b][s][h*64+dk] = o / l  (float2 stores)
    float inv0 = 1.0f / lrow[0];
    float inv1 = 1.0f / lrow[1];
    float* Xb = X + ((size_t)bb * SS + qt * 64 + w * 16) * DD + h * DKK;
    #pragma unroll
    for (int dt = 0; dt < 8; dt++) {
        int col = dt * 8 + 2 * q;
        float2 v0 = make_float2(o[dt][0] * inv0, o[dt][1] * inv0);
        float2 v1 = make_float2(o[dt][2] * inv1, o[dt][3] * inv1);
        *(float2*)&Xb[(size_t)r * DD + col]       = v0;
        *(float2*)&Xb[(size_t)(r + 8) * DD + col] = v1;
    }
}

// ---------------------------------------------------------------------------
extern "C" void kernel_launch(void* const* d_in, const int* in_sizes, int n_in,
                              void* d_out, int out_size)
{
    const float* query = (const float*)d_in[0];
    const float* key_  = (const float*)d_in[1];
    const float* value = (const float*)d_in[2];
    const float* Wq    = (const float*)d_in[3];
    const float* bq    = (const float*)d_in[4];
    const float* Wk    = (const float*)d_in[5];
    const float* bk    = (const float*)d_in[6];
    const float* Wv    = (const float*)d_in[7];
    const float* bv    = (const float*)d_in[8];
    const float* Wo    = (const float*)d_in[9];
    const float* bo    = (const float*)d_in[10];
    float* out = (float*)d_out;

    float *q, *k, *v, *x;
    cudaGetSymbolAddress((void**)&q, g_q);
    cudaGetSymbolAddress((void**)&k, g_k);
    cudaGetSymbolAddress((void**)&v, g_v);
    cudaGetSymbolAddress((void**)&x, g_x);

    const int attn_smem = (2 * 64 * KST + 2 * 64 * VST + 64 * PST) * (int)sizeof(float); // 89088
    cudaFuncSetAttribute(attn_tf32,
                         cudaFuncAttributeMaxDynamicSharedMemorySize, attn_smem);

    // Fused Q/K/V projections (Q pre-scaled by 1/sqrt(DK) = 1/8)
    GemmArgs gq = { query, Wq, bq, q, 0.125f, 1 };
    GemmArgs gk = { key_,  Wk, bk, k, 1.0f,   1 };
    GemmArgs gv = { value, Wv, bv, v, 1.0f,   1 };
    gemm_qkv<<<dim3(DD / 128, MM / 128, 3), 256>>>(gq, gk, gv);

    // Attention
    attn_tf32<<<dim3(SS / 64, BB * HH), 128, attn_smem>>>(q, k, v, x);

    // Output projection -> d_out
    GemmArgs go = { x, Wo, bo, out, 1.0f, 0 };
    gemm_one<<<dim3(DD / 128, MM / 128), 256>>>(go);
}

// round 5
// speedup vs baseline: 2.4611x; 1.8910x over previous
#include <cuda_runtime.h>
#include <cuda_bf16.h>
#include <math.h>
#include <stdint.h>

// Problem constants
#define BB   4
#define SS   2048
#define DD   1024
#define HH   16
#define DKK  64
#define MM   (BB*SS)          // 8192 rows

// Scratch: Q,K in [B,H,S,DK]; V in [B,H,DK,S] (dk-major!); X in [B,S,D]
__device__ float g_q[(size_t)BB*HH*SS*DKK];
__device__ float g_k[(size_t)BB*HH*SS*DKK];
__device__ float g_v[(size_t)BB*HH*DKK*SS];
__device__ float g_x[(size_t)BB*SS*DD];

// ---------------------------------------------------------------------------
// bf16 helpers
// ---------------------------------------------------------------------------
__device__ __forceinline__ uint32_t packbf(__nv_bfloat16 x, __nv_bfloat16 y) {
    return (uint32_t)__bfloat16_as_ushort(x) |
           ((uint32_t)__bfloat16_as_ushort(y) << 16);
}
// split (x,y) into packed hi pair and packed lo-residual pair
__device__ __forceinline__ void split2(float x, float y, uint32_t& h, uint32_t& l) {
    __nv_bfloat16 hx = __float2bfloat16(x);
    __nv_bfloat16 hy = __float2bfloat16(y);
    __nv_bfloat16 lx = __float2bfloat16(x - __bfloat162float(hx));
    __nv_bfloat16 ly = __float2bfloat16(y - __bfloat162float(hy));
    h = packbf(hx, hy);
    l = packbf(lx, ly);
}

// D(16x8,f32) += A(16x16,bf16) * B(16x8,bf16)
__device__ __forceinline__ void mma16(float* d, const uint32_t* a, const uint32_t* b) {
    asm("mma.sync.aligned.m16n8k16.row.col.f32.bf16.bf16.f32 "
        "{%0,%1,%2,%3}, {%4,%5,%6,%7}, {%8,%9}, {%0,%1,%2,%3};"
        : "+f"(d[0]), "+f"(d[1]), "+f"(d[2]), "+f"(d[3])
        : "r"(a[0]), "r"(a[1]), "r"(a[2]), "r"(a[3]),
          "r"(b[0]), "r"(b[1]));
}

// ---------------------------------------------------------------------------
// bf16x3 SGEMM core:  Y = (A @ W^T + bias) * alpha
// Block 128x128, BK=32, 256 threads (8 warps), warp tile 64x32.
// smem: bf16x2 hi/lo planes, 16 k-pairs per row, word stride 20 (conflict-free
// fragment loads: (r*20+q) mod 32 bijective over the warp).
// head_layout: 0 -> [M,N]; 1 -> [B,H,S,DK]; 2 -> [B,H,DK,S]
// ---------------------------------------------------------------------------
#define GWS 20

struct GemmArgs {
    const float* A; const float* W; const float* bias;
    float* Y; float alpha; int head_layout;
};

__device__ __forceinline__ void gemm_core(const GemmArgs& g)
{
    __shared__ uint32_t A0[128 * GWS], A1[128 * GWS];
    __shared__ uint32_t B0[128 * GWS], B1[128 * GWS];

    const int tid  = threadIdx.x;
    const int lane = tid & 31;
    const int wrp  = tid >> 5;
    const int wy   = wrp & 1;          // m-warp (0..1), 64 rows
    const int wx   = wrp >> 1;         // n-warp (0..3), 32 cols
    const int r    = lane >> 2;        // 0..7
    const int q    = lane & 3;         // 0..3
    const int bm   = blockIdx.y * 128;
    const int bn   = blockIdx.x * 128;

    float c[4][4][4];
    #pragma unroll
    for (int mt = 0; mt < 4; mt++)
        #pragma unroll
        for (int nt = 0; nt < 4; nt++)
            #pragma unroll
            for (int i = 0; i < 4; i++) c[mt][nt][i] = 0.0f;

    for (int kt = 0; kt < DD; kt += 32) {
        // Stage + split A/W tiles (128x32) into bf16 hi/lo planes.
        #pragma unroll
        for (int rr = 0; rr < 4; rr++) {
            int lin = tid + rr * 256;      // 0..1023
            int row = lin >> 3;            // 0..127
            int f4  = lin & 7;             // float4 index (4 k-elems = 2 pairs)
            float4 va = *(const float4*)&g.A[(size_t)(bm + row) * DD + kt + f4 * 4];
            uint32_t h0, l0, h1, l1;
            split2(va.x, va.y, h0, l0);
            split2(va.z, va.w, h1, l1);
            A0[row * GWS + f4 * 2]     = h0;
            A0[row * GWS + f4 * 2 + 1] = h1;
            A1[row * GWS + f4 * 2]     = l0;
            A1[row * GWS + f4 * 2 + 1] = l1;
            float4 vb = *(const float4*)&g.W[(size_t)(bn + row) * DD + kt + f4 * 4];
            split2(vb.x, vb.y, h0, l0);
            split2(vb.z, vb.w, h1, l1);
            B0[row * GWS + f4 * 2]     = h0;
            B0[row * GWS + f4 * 2 + 1] = h1;
            B1[row * GWS + f4 * 2]     = l0;
            B1[row * GWS + f4 * 2 + 1] = l1;
        }
        __syncthreads();

        #pragma unroll
        for (int ks = 0; ks < 2; ks++) {
            const int koff = ks * 8;
            uint32_t bh[4][2], bl[4][2];
            #pragma unroll
            for (int nt = 0; nt < 4; nt++) {
                int idx = (wx * 32 + nt * 8 + r) * GWS + koff + q;
                bh[nt][0] = B0[idx];
                bh[nt][1] = B0[idx + 4];
                bl[nt][0] = B1[idx];
                bl[nt][1] = B1[idx + 4];
            }
            #pragma unroll
            for (int mt = 0; mt < 4; mt++) {
                int idx0 = (wy * 64 + mt * 16 + r) * GWS + koff + q;
                int idx1 = idx0 + 8 * GWS;
                uint32_t ah[4], al[4];
                ah[0] = A0[idx0]; ah[1] = A0[idx1];
                ah[2] = A0[idx0 + 4]; ah[3] = A0[idx1 + 4];
                al[0] = A1[idx0]; al[1] = A1[idx1];
                al[2] = A1[idx0 + 4]; al[3] = A1[idx1 + 4];
                #pragma unroll
                for (int nt = 0; nt < 4; nt++) {
                    mma16(c[mt][nt], al, bh[nt]);
                    mma16(c[mt][nt], ah, bl[nt]);
                    mma16(c[mt][nt], ah, bh[nt]);
                }
            }
        }
        __syncthreads();
    }

    // Epilogue
    #pragma unroll
    for (int mt = 0; mt < 4; mt++) {
        #pragma unroll
        for (int nt = 0; nt < 4; nt++) {
            int n = bn + wx * 32 + nt * 8 + 2 * q;
            float b0 = g.bias[n], b1 = g.bias[n + 1];
            #pragma unroll
            for (int half = 0; half < 2; half++) {
                int m = bm + wy * 64 + mt * 16 + r + half * 8;
                float vx = (c[mt][nt][2 * half]     + b0) * g.alpha;
                float vy = (c[mt][nt][2 * half + 1] + b1) * g.alpha;
                if (g.head_layout == 0) {
                    *(float2*)&g.Y[(size_t)m * DD + n] = make_float2(vx, vy);
                } else {
                    int b  = m >> 11;         // / SS
                    int s  = m & (SS - 1);
                    int h  = n >> 6;          // / DK
                    int dk = n & 63;
                    if (g.head_layout == 1) {
                        *(float2*)&g.Y[(((size_t)(b * HH + h)) * SS + s) * DKK + dk]
                            = make_float2(vx, vy);
                    } else {
                        // [B,H,DK,S]
                        size_t base = ((size_t)(b * HH + h) * DKK + dk) * SS + s;
                        g.Y[base]      = vx;
                        g.Y[base + SS] = vy;
                    }
                }
            }
        }
    }
}

__global__ __launch_bounds__(256, 2) void gemm_qkv(GemmArgs g0, GemmArgs g1, GemmArgs g2)
{
    if (blockIdx.z == 0)      gemm_core(g0);
    else if (blockIdx.z == 1) gemm_core(g1);
    else                      gemm_core(g2);
}

__global__ __launch_bounds__(256, 2) void gemm_one(GemmArgs g0)
{
    gemm_core(g0);
}

// ---------------------------------------------------------------------------
// bf16x3 flash attention. One block = one (b,h) x 64-query tile.
// 128 threads (4 warps); warp owns 16 query rows x all 64 keys/dims.
// K staged [key][dk-pairs], V staged [dk][key-pairs] (V is dk-major in gmem).
// P never touches smem: QK^T accumulator registers ARE the PV A-fragments.
// ---------------------------------------------------------------------------
#define KWS 36   // word stride: (r*36+q)%32 = r*4+q bijective
#define VWS 36

__global__ __launch_bounds__(128, 3) void attn_bf16(
    const float* __restrict__ Q,
    const float* __restrict__ Kh,
    const float* __restrict__ V,
    float* __restrict__ X)
{
    __shared__ uint32_t K0[64 * KWS], K1[64 * KWS];
    __shared__ uint32_t V0[64 * VWS], V1[64 * VWS];

    const int tid  = threadIdx.x;
    const int lane = tid & 31;
    const int w    = tid >> 5;           // warp 0..3 -> query rows w*16..
    const int r    = lane >> 2;          // 0..7
    const int q    = lane & 3;           // 0..3
    const int qt   = blockIdx.x;         // 0..31
    const int bh   = blockIdx.y;         // 0..63
    const int h    = bh & (HH - 1);
    const int bb   = bh >> 4;

    const float* Qbase = Q + ((size_t)bh * SS + qt * 64 + w * 16) * DKK;
    const float* Kbase = Kh + (size_t)bh * SS * DKK;
    const float* Vbase = V + (size_t)bh * DKK * SS;   // [dk][s]

    // Preload Q fragments: 4 k-steps of 16 dims, hi/lo packed pairs. 32 regs.
    uint32_t qh[4][4], ql[4][4];
    #pragma unroll
    for (int kt = 0; kt < 4; kt++) {
        int k0 = kt * 16;
        float2 f0 = *(const float2*)&Qbase[(size_t)r * DKK + k0 + 2 * q];
        float2 f1 = *(const float2*)&Qbase[(size_t)(r + 8) * DKK + k0 + 2 * q];
        float2 f2 = *(const float2*)&Qbase[(size_t)r * DKK + k0 + 2 * q + 8];
        float2 f3 = *(const float2*)&Qbase[(size_t)(r + 8) * DKK + k0 + 2 * q + 8];
        split2(f0.x, f0.y, qh[kt][0], ql[kt][0]);
        split2(f1.x, f1.y, qh[kt][1], ql[kt][1]);
        split2(f2.x, f2.y, qh[kt][2], ql[kt][2]);
        split2(f3.x, f3.y, qh[kt][3], ql[kt][3]);
    }

    float o[8][4];
    #pragma unroll
    for (int dt = 0; dt < 8; dt++)
        #pragma unroll
        for (int i = 0; i < 4; i++) o[dt][i] = 0.0f;
    float mrow[2] = {-1e30f, -1e30f};
    float lrow[2] = {0.0f, 0.0f};

    for (int t = 0; t < SS / 64; t++) {
        __syncthreads();
        // Stage K tile (64 keys x 64 dk) and V tile (64 dk x 64 keys).
        #pragma unroll
        for (int rr = 0; rr < 8; rr++) {
            int lin = tid + rr * 128;     // 0..1023
            int row = lin >> 4;           // 0..63 (key for K, dk for V)
            int c4  = (lin & 15) << 2;    // 0..60
            float4 kv = *(const float4*)&Kbase[(size_t)(t * 64 + row) * DKK + c4];
            uint32_t h0, l0, h1, l1;
            split2(kv.x, kv.y, h0, l0);
            split2(kv.z, kv.w, h1, l1);
            K0[row * KWS + (c4 >> 1)]     = h0;
            K0[row * KWS + (c4 >> 1) + 1] = h1;
            K1[row * KWS + (c4 >> 1)]     = l0;
            K1[row * KWS + (c4 >> 1) + 1] = l1;
            float4 vv = *(const float4*)&Vbase[(size_t)row * SS + t * 64 + c4];
            split2(vv.x, vv.y, h0, l0);
            split2(vv.z, vv.w, h1, l1);
            V0[row * VWS + (c4 >> 1)]     = h0;
            V0[row * VWS + (c4 >> 1) + 1] = h1;
            V1[row * VWS + (c4 >> 1)]     = l0;
            V1[row * VWS + (c4 >> 1) + 1] = l1;
        }
        __syncthreads();

        // ---- S = Q K^T (16 x 64 per warp), bf16x3 ----
        float s[8][4];
        #pragma unroll
        for (int nt = 0; nt < 8; nt++)
            #pragma unroll
            for (int i = 0; i < 4; i++) s[nt][i] = 0.0f;

        #pragma unroll
        for (int kt = 0; kt < 4; kt++) {
            const int koff = kt * 8;
            #pragma unroll
            for (int nt = 0; nt < 8; nt++) {
                int idx = (nt * 8 + r) * KWS + koff + q;
                uint32_t bhf[2], blf[2];
                bhf[0] = K0[idx]; bhf[1] = K0[idx + 4];
                blf[0] = K1[idx]; blf[1] = K1[idx + 4];
                mma16(s[nt], ql[kt], bhf);
                mma16(s[nt], qh[kt], blf);
                mma16(s[nt], qh[kt], bhf);
            }
        }

        // ---- online softmax (rows r / r+8; 4-lane row groups) ----
        #pragma unroll
        for (int half = 0; half < 2; half++) {
            float rm = -1e30f;
            #pragma unroll
            for (int nt = 0; nt < 8; nt++)
                rm = fmaxf(rm, fmaxf(s[nt][2 * half], s[nt][2 * half + 1]));
            rm = fmaxf(rm, __shfl_xor_sync(0xffffffffu, rm, 1));
            rm = fmaxf(rm, __shfl_xor_sync(0xffffffffu, rm, 2));
            float mnew  = fmaxf(mrow[half], rm);
            float scale = __expf(mrow[half] - mnew);
            float rs = 0.0f;
            #pragma unroll
            for (int nt = 0; nt < 8; nt++) {
                s[nt][2 * half]     = __expf(s[nt][2 * half] - mnew);
                s[nt][2 * half + 1] = __expf(s[nt][2 * half + 1] - mnew);
                rs += s[nt][2 * half] + s[nt][2 * half + 1];
            }
            rs += __shfl_xor_sync(0xffffffffu, rs, 1);
            rs += __shfl_xor_sync(0xffffffffu, rs, 2);
            lrow[half] = lrow[half] * scale + rs;
            mrow[half] = mnew;
            #pragma unroll
            for (int dt = 0; dt < 8; dt++) {
                o[dt][2 * half]     *= scale;
                o[dt][2 * half + 1] *= scale;
            }
        }

        // ---- O += P V : P splits live in registers (QK frag layout == A frag) ----
        #pragma unroll
        for (int kt = 0; kt < 4; kt++) {
            uint32_t ph[4], pl[4];
            split2(s[2 * kt][0],     s[2 * kt][1],     ph[0], pl[0]);
            split2(s[2 * kt][2],     s[2 * kt][3],     ph[1], pl[1]);
            split2(s[2 * kt + 1][0], s[2 * kt + 1][1], ph[2], pl[2]);
            split2(s[2 * kt + 1][2], s[2 * kt + 1][3], ph[3], pl[3]);
            #pragma unroll
            for (int dt = 0; dt < 8; dt++) {
                int idx = (dt * 8 + r) * VWS + kt * 8 + q;
                uint32_t vh[2], vl[2];
                vh[0] = V0[idx]; vh[1] = V0[idx + 4];
                vl[0] = V1[idx]; vl[1] = V1[idx + 4];
                mma16(o[dt], pl, vh);
                mma16(o[dt], ph, vl);
                mma16(o[dt], ph, vh);
            }
        }
    }

    // Epilogue: X[b][s][h*64+dk] = o / l  (float2 stores)
    float inv0 = 1.0f / lrow[0];
    float inv1 = 1.0f / lrow[1];
    float* Xb = X + ((size_t)bb * SS + qt * 64 + w * 16) * DD + h * DKK;
    #pragma unroll
    for (int dt = 0; dt < 8; dt++) {
        int col = dt * 8 + 2 * q;
        *(float2*)&Xb[(size_t)r * DD + col]
            = make_float2(o[dt][0] * inv0, o[dt][1] * inv0);
        *(float2*)&Xb[(size_t)(r + 8) * DD + col]
            = make_float2(o[dt][2] * inv1, o[dt][3] * inv1);
    }
}

// ---------------------------------------------------------------------------
extern "C" void kernel_launch(void* const* d_in, const int* in_sizes, int n_in,
                              void* d_out, int out_size)
{
    const float* query = (const float*)d_in[0];
    const float* key_  = (const float*)d_in[1];
    const float* value = (const float*)d_in[2];
    const float* Wq    = (const float*)d_in[3];
    const float* bq    = (const float*)d_in[4];
    const float* Wk    = (const float*)d_in[5];
    const float* bk    = (const float*)d_in[6];
    const float* Wv    = (const float*)d_in[7];
    const float* bv    = (const float*)d_in[8];
    const float* Wo    = (const float*)d_in[9];
    const float* bo    = (const float*)d_in[10];
    float* out = (float*)d_out;

    float *q, *k, *v, *x;
    cudaGetSymbolAddress((void**)&q, g_q);
    cudaGetSymbolAddress((void**)&k, g_k);
    cudaGetSymbolAddress((void**)&v, g_v);
    cudaGetSymbolAddress((void**)&x, g_x);

    // Fused Q/K/V projections (Q pre-scaled by 1/sqrt(DK) = 1/8; V -> dk-major)
    GemmArgs gq = { query, Wq, bq, q, 0.125f, 1 };
    GemmArgs gk = { key_,  Wk, bk, k, 1.0f,   1 };
    GemmArgs gv = { value, Wv, bv, v, 1.0f,   2 };
    gemm_qkv<<<dim3(DD / 128, MM / 128, 3), 256>>>(gq, gk, gv);

    // Attention
    attn_bf16<<<dim3(SS / 64, BB * HH), 128>>>(q, k, v, x);

    // Output projection -> d_out
    GemmArgs go = { x, Wo, bo, out, 1.0f, 0 };
    gemm_one<<<dim3(DD / 128, MM / 128), 256>>>(go);
}

// round 8
// speedup vs baseline: 2.9582x; 1.2020x over previous
#include <cuda_runtime.h>
#include <cuda_bf16.h>
#include <cuda_fp16.h>
#include <math.h>
#include <stdint.h>

// Problem constants
#define BB   4
#define SS   2048
#define DD   1024
#define HH   16
#define DKK  64
#define MM   (BB*SS)          // 8192 rows

// Scratch: Q,K in [B,H,S,DK]; V in [B,H,DK,S] (dk-major!); X in [B,S,D]
__device__ float g_q[(size_t)BB*HH*SS*DKK];
__device__ float g_k[(size_t)BB*HH*SS*DKK];
__device__ float g_v[(size_t)BB*HH*DKK*SS];
__device__ float g_x[(size_t)BB*SS*DD];

// ---------------------------------------------------------------------------
// bf16 helpers (GEMM path, 3-term)
// ---------------------------------------------------------------------------
__device__ __forceinline__ uint32_t packbf(__nv_bfloat16 x, __nv_bfloat16 y) {
    return (uint32_t)__bfloat16_as_ushort(x) |
           ((uint32_t)__bfloat16_as_ushort(y) << 16);
}
__device__ __forceinline__ void split2(float x, float y, uint32_t& h, uint32_t& l) {
    __nv_bfloat16 hx = __float2bfloat16(x);
    __nv_bfloat16 hy = __float2bfloat16(y);
    __nv_bfloat16 lx = __float2bfloat16(x - __bfloat162float(hx));
    __nv_bfloat16 ly = __float2bfloat16(y - __bfloat162float(hy));
    h = packbf(hx, hy);
    l = packbf(lx, ly);
}
// D(16x8,f32) += A(16x16,bf16) * B(16x8,bf16)
__device__ __forceinline__ void mma16(float* d, const uint32_t* a, const uint32_t* b) {
    asm("mma.sync.aligned.m16n8k16.row.col.f32.bf16.bf16.f32 "
        "{%0,%1,%2,%3}, {%4,%5,%6,%7}, {%8,%9}, {%0,%1,%2,%3};"
        : "+f"(d[0]), "+f"(d[1]), "+f"(d[2]), "+f"(d[3])
        : "r"(a[0]), "r"(a[1]), "r"(a[2]), "r"(a[3]),
          "r"(b[0]), "r"(b[1]));
}

// ---------------------------------------------------------------------------
// fp16 helpers (attention path, 2-term)
// ---------------------------------------------------------------------------
__device__ __forceinline__ uint32_t pack2h(float x, float y) {
    __half2 h = __floats2half2_rn(x, y);
    return *reinterpret_cast<uint32_t*>(&h);
}
__device__ __forceinline__ void split2h(float x, float y, uint32_t& h, uint32_t& l) {
    __half hx = __float2half_rn(x);
    __half hy = __float2half_rn(y);
    __half lx = __float2half_rn(x - __half2float(hx));
    __half ly = __float2half_rn(y - __half2float(hy));
    __half2 hh = __halves2half2(hx, hy);
    __half2 ll = __halves2half2(lx, ly);
    h = *reinterpret_cast<uint32_t*>(&hh);
    l = *reinterpret_cast<uint32_t*>(&ll);
}
// D(16x8,f32) += A(16x16,f16) * B(16x8,f16)
__device__ __forceinline__ void mma16h(float* d, const uint32_t* a, const uint32_t* b) {
    asm("mma.sync.aligned.m16n8k16.row.col.f32.f16.f16.f32 "
        "{%0,%1,%2,%3}, {%4,%5,%6,%7}, {%8,%9}, {%0,%1,%2,%3};"
        : "+f"(d[0]), "+f"(d[1]), "+f"(d[2]), "+f"(d[3])
        : "r"(a[0]), "r"(a[1]), "r"(a[2]), "r"(a[3]),
          "r"(b[0]), "r"(b[1]));
}

// ---------------------------------------------------------------------------
// bf16x3 SGEMM:  Y = (A @ W^T + bias) * alpha
// Block 128x128, BK=64, 256 threads (8 warps), warp tile 64x32.
// smem: 4 bf16x2 hi/lo planes, word stride 36 ((4r+q)%32 bijective).
// head_layout: 0 -> [M,N]; 1 -> [B,H,S,DK]; 2 -> [B,H,DK,S]
// ---------------------------------------------------------------------------
#define GW  36
#define GPW (128 * GW)
#define GSMEM_BYTES (4 * GPW * 4)     // 73728 B

struct GemmArgs {
    const float* A; const float* W; const float* bias;
    float* Y; float alpha; int head_layout;
};

__global__ __launch_bounds__(256, 2) void gemm_bf(GemmArgs ga, GemmArgs gb, GemmArgs gc)
{
    GemmArgs g = (blockIdx.z == 0) ? ga : ((blockIdx.z == 1) ? gb : gc);
    extern __shared__ uint32_t sp[];
    uint32_t* A0 = sp;
    uint32_t* A1 = sp + GPW;
    uint32_t* B0 = sp + 2 * GPW;
    uint32_t* B1 = sp + 3 * GPW;

    const int tid  = threadIdx.x;
    const int lane = tid & 31;
    const int wrp  = tid >> 5;
    const int wy   = wrp & 1;          // m-warp (0..1), 64 rows
    const int wx   = wrp >> 1;         // n-warp (0..3), 32 cols
    const int r    = lane >> 2;        // 0..7
    const int q    = lane & 3;         // 0..3
    const int bm   = blockIdx.y * 128;
    const int bn   = blockIdx.x * 128;

    float c[4][4][4];
    #pragma unroll
    for (int mt = 0; mt < 4; mt++)
        #pragma unroll
        for (int nt = 0; nt < 4; nt++)
            #pragma unroll
            for (int i = 0; i < 4; i++) c[mt][nt][i] = 0.0f;

    for (int kt = 0; kt < DD; kt += 64) {
        // Stage + split A/W tiles (128x64) into bf16 hi/lo planes.
        #pragma unroll
        for (int rr = 0; rr < 8; rr++) {
            int lin = tid + rr * 256;      // 0..2047
            int row = lin >> 4;            // 0..127
            int c4  = (lin & 15) << 2;     // 0..60
            int w0  = row * GW + (c4 >> 1);
            float4 va = *(const float4*)&g.A[(size_t)(bm + row) * DD + kt + c4];
            uint32_t h0, l0, h1, l1;
            split2(va.x, va.y, h0, l0);
            split2(va.z, va.w, h1, l1);
            *(uint2*)&A0[w0] = make_uint2(h0, h1);
            *(uint2*)&A1[w0] = make_uint2(l0, l1);
            float4 vb = *(const float4*)&g.W[(size_t)(bn + row) * DD + kt + c4];
            split2(vb.x, vb.y, h0, l0);
            split2(vb.z, vb.w, h1, l1);
            *(uint2*)&B0[w0] = make_uint2(h0, h1);
            *(uint2*)&B1[w0] = make_uint2(l0, l1);
        }
        __syncthreads();

        #pragma unroll
        for (int ks = 0; ks < 4; ks++) {
            const int koff = ks * 8;
            uint32_t bh[4][2], bl[4][2];
            #pragma unroll
            for (int nt = 0; nt < 4; nt++) {
                int idx = (wx * 32 + nt * 8 + r) * GW + koff + q;
                bh[nt][0] = B0[idx];
                bh[nt][1] = B0[idx + 4];
                bl[nt][0] = B1[idx];
                bl[nt][1] = B1[idx + 4];
            }
            #pragma unroll
            for (int mt = 0; mt < 4; mt++) {
                int idx0 = (wy * 64 + mt * 16 + r) * GW + koff + q;
                int idx1 = idx0 + 8 * GW;
                uint32_t ah[4], al[4];
                ah[0] = A0[idx0]; ah[1] = A0[idx1];
                ah[2] = A0[idx0 + 4]; ah[3] = A0[idx1 + 4];
                al[0] = A1[idx0]; al[1] = A1[idx1];
                al[2] = A1[idx0 + 4]; al[3] = A1[idx1 + 4];
                #pragma unroll
                for (int nt = 0; nt < 4; nt++) {
                    mma16(c[mt][nt], al, bh[nt]);
                    mma16(c[mt][nt], ah, bl[nt]);
                    mma16(c[mt][nt], ah, bh[nt]);
                }
            }
        }
        __syncthreads();
    }

    // Epilogue
    #pragma unroll
    for (int mt = 0; mt < 4; mt++) {
        #pragma unroll
        for (int nt = 0; nt < 4; nt++) {
            int n = bn + wx * 32 + nt * 8 + 2 * q;
            float b0 = g.bias[n], b1 = g.bias[n + 1];
            #pragma unroll
            for (int half = 0; half < 2; half++) {
                int m = bm + wy * 64 + mt * 16 + r + half * 8;
                float vx = (c[mt][nt][2 * half]     + b0) * g.alpha;
                float vy = (c[mt][nt][2 * half + 1] + b1) * g.alpha;
                if (g.head_layout == 0) {
                    *(float2*)&g.Y[(size_t)m * DD + n] = make_float2(vx, vy);
                } else {
                    int b  = m >> 11;         // / SS
                    int s  = m & (SS - 1);
                    int h  = n >> 6;          // / DK
                    int dk = n & 63;
                    if (g.head_layout == 1) {
                        *(float2*)&g.Y[(((size_t)(b * HH + h)) * SS + s) * DKK + dk]
                            = make_float2(vx, vy);
                    } else {
                        // [B,H,DK,S]
                        size_t base = ((size_t)(b * HH + h) * DKK + dk) * SS + s;
                        g.Y[base]      = vx;
                        g.Y[base + SS] = vy;
                    }
                }
            }
        }
    }
}

// ---------------------------------------------------------------------------
// fp16 2-term flash attention. One block = one (b,h) x 64-query tile.
// 128 threads (4 warps); warp owns 16 query rows x all 64 keys/dims.
// Q: 2-term fp16 registers. K: single hi plane (Q carries both terms).
// V: 2-term hi/lo planes. P: single-term fp16 packed straight from the
// QK^T accumulator registers (frag layout matches the PV A-fragment).
// ---------------------------------------------------------------------------
#define KW 36   // word stride: (4r+q)%32 bijective -> conflict-free frags

__global__ __launch_bounds__(128, 3) void attn_fp16(
    const float* __restrict__ Q,
    const float* __restrict__ Kh,
    const float* __restrict__ V,
    float* __restrict__ X)
{
    __shared__ uint32_t K0[64 * KW];
    __shared__ uint32_t V0[64 * KW], V1[64 * KW];

    const int tid  = threadIdx.x;
    const int lane = tid & 31;
    const int w    = tid >> 5;           // warp 0..3 -> query rows w*16..
    const int r    = lane >> 2;          // 0..7
    const int q    = lane & 3;           // 0..3
    const int qt   = blockIdx.x;         // 0..31
    const int bh   = blockIdx.y;         // 0..63
    const int h    = bh & (HH - 1);
    const int bb   = bh >> 4;

    const float* Qbase = Q + ((size_t)bh * SS + qt * 64 + w * 16) * DKK;
    const float* Kbase = Kh + (size_t)bh * SS * DKK;
    const float* Vbase = V + (size_t)bh * DKK * SS;   // [dk][s]

    // Preload Q fragments: 4 k-steps of 16 dims, fp16 hi/lo packed pairs.
    uint32_t qh[4][4], ql[4][4];
    #pragma unroll
    for (int kt = 0; kt < 4; kt++) {
        int k0 = kt * 16;
        float2 f0 = *(const float2*)&Qbase[(size_t)r * DKK + k0 + 2 * q];
        float2 f1 = *(const float2*)&Qbase[(size_t)(r + 8) * DKK + k0 + 2 * q];
        float2 f2 = *(const float2*)&Qbase[(size_t)r * DKK + k0 + 2 * q + 8];
        float2 f3 = *(const float2*)&Qbase[(size_t)(r + 8) * DKK + k0 + 2 * q + 8];
        split2h(f0.x, f0.y, qh[kt][0], ql[kt][0]);
        split2h(f1.x, f1.y, qh[kt][1], ql[kt][1]);
        split2h(f2.x, f2.y, qh[kt][2], ql[kt][2]);
        split2h(f3.x, f3.y, qh[kt][3], ql[kt][3]);
    }

    float o[8][4];
    #pragma unroll
    for (int dt = 0; dt < 8; dt++)
        #pragma unroll
        for (int i = 0; i < 4; i++) o[dt][i] = 0.0f;
    float mrow[2] = {-1e30f, -1e30f};
    float lrow[2] = {0.0f, 0.0f};

    for (int t = 0; t < SS / 64; t++) {
        __syncthreads();
        // Stage K (hi only) and V (hi/lo) tiles.
        #pragma unroll
        for (int rr = 0; rr < 8; rr++) {
            int lin = tid + rr * 128;     // 0..1023
            int row = lin >> 4;           // key for K, dk for V
            int c4  = (lin & 15) << 2;
            int w0  = row * KW + (c4 >> 1);
            float4 kv = *(const float4*)&Kbase[(size_t)(t * 64 + row) * DKK + c4];
            K0[w0]     = pack2h(kv.x, kv.y);
            K0[w0 + 1] = pack2h(kv.z, kv.w);
            float4 vv = *(const float4*)&Vbase[(size_t)row * SS + t * 64 + c4];
            uint32_t h0, l0, h1, l1;
            split2h(vv.x, vv.y, h0, l0);
            split2h(vv.z, vv.w, h1, l1);
            V0[w0]     = h0;
            V0[w0 + 1] = h1;
            V1[w0]     = l0;
            V1[w0 + 1] = l1;
        }
        __syncthreads();

        // ---- S = Q K^T (16 x 64 per warp): (qh + ql) * kh ----
        float s[8][4];
        #pragma unroll
        for (int nt = 0; nt < 8; nt++)
            #pragma unroll
            for (int i = 0; i < 4; i++) s[nt][i] = 0.0f;

        #pragma unroll
        for (int kt = 0; kt < 4; kt++) {
            const int koff = kt * 8;
            #pragma unroll
            for (int nt = 0; nt < 8; nt++) {
                int idx = (nt * 8 + r) * KW + koff + q;
                uint32_t kf[2];
                kf[0] = K0[idx];
                kf[1] = K0[idx + 4];
                mma16h(s[nt], ql[kt], kf);
                mma16h(s[nt], qh[kt], kf);
            }
        }

        // ---- online softmax (rows r / r+8; 4-lane row groups) ----
        #pragma unroll
        for (int half = 0; half < 2; half++) {
            float rm = -1e30f;
            #pragma unroll
            for (int nt = 0; nt < 8; nt++)
                rm = fmaxf(rm, fmaxf(s[nt][2 * half], s[nt][2 * half + 1]));
            rm = fmaxf(rm, __shfl_xor_sync(0xffffffffu, rm, 1));
            rm = fmaxf(rm, __shfl_xor_sync(0xffffffffu, rm, 2));
            float mnew  = fmaxf(mrow[half], rm);
            float scale = __expf(mrow[half] - mnew);
            float rs = 0.0f;
            #pragma unroll
            for (int nt = 0; nt < 8; nt++) {
                s[nt][2 * half]     = __expf(s[nt][2 * half] - mnew);
                s[nt][2 * half + 1] = __expf(s[nt][2 * half + 1] - mnew);
                rs += s[nt][2 * half] + s[nt][2 * half + 1];
            }
            rs += __shfl_xor_sync(0xffffffffu, rs, 1);
            rs += __shfl_xor_sync(0xffffffffu, rs, 2);
            lrow[half] = lrow[half] * scale + rs;
            mrow[half] = mnew;
            #pragma unroll
            for (int dt = 0; dt < 8; dt++) {
                o[dt][2 * half]     *= scale;
                o[dt][2 * half + 1] *= scale;
            }
        }

        // ---- O += P V : P single-term fp16 (in regs), V 2-term ----
        #pragma unroll
        for (int kt = 0; kt < 4; kt++) {
            uint32_t ph[4];
            ph[0] = pack2h(s[2 * kt][0],     s[2 * kt][1]);
            ph[1] = pack2h(s[2 * kt][2],     s[2 * kt][3]);
            ph[2] = pack2h(s[2 * kt + 1][0], s[2 * kt + 1][1]);
            ph[3] = pack2h(s[2 * kt + 1][2], s[2 * kt + 1][3]);
            #pragma unroll
            for (int dt = 0; dt < 8; dt++) {
                int idx = (dt * 8 + r) * KW + kt * 8 + q;
                uint32_t vh[2], vl[2];
                vh[0] = V0[idx]; vh[1] = V0[idx + 4];
                vl[0] = V1[idx]; vl[1] = V1[idx + 4];
                mma16h(o[dt], ph, vl);
                mma16h(o[dt], ph, vh);
            }
        }
    }

    // Epilogue: X[b][s][h*64+dk] = o / l  (float2 stores)
    float inv0 = 1.0f / lrow[0];
    float inv1 = 1.0f / lrow[1];
    float* Xb = X + ((size_t)bb * SS + qt * 64 + w * 16) * DD + h * DKK;
    #pragma unroll
    for (int dt = 0; dt < 8; dt++) {
        int col = dt * 8 + 2 * q;
        *(float2*)&Xb[(size_t)r * DD + col]
            = make_float2(o[dt][0] * inv0, o[dt][1] * inv0);
        *(float2*)&Xb[(size_t)(r + 8) * DD + col]
            = make_float2(o[dt][2] * inv1, o[dt][3] * inv1);
    }
}

// ---------------------------------------------------------------------------
extern "C" void kernel_launch(void* const* d_in, const int* in_sizes, int n_in,
                              void* d_out, int out_size)
{
    const float* query = (const float*)d_in[0];
    const float* key_  = (const float*)d_in[1];
    const float* value = (const float*)d_in[2];
    const float* Wq    = (const float*)d_in[3];
    const float* bq    = (const float*)d_in[4];
    const float* Wk    = (const float*)d_in[5];
    const float* bk    = (const float*)d_in[6];
    const float* Wv    = (const float*)d_in[7];
    const float* bv    = (const float*)d_in[8];
    const float* Wo    = (const float*)d_in[9];
    const float* bo    = (const float*)d_in[10];
    float* out = (float*)d_out;

    float *q, *k, *v, *x;
    cudaGetSymbolAddress((void**)&q, g_q);
    cudaGetSymbolAddress((void**)&k, g_k);
    cudaGetSymbolAddress((void**)&v, g_v);
    cudaGetSymbolAddress((void**)&x, g_x);

    cudaFuncSetAttribute(gemm_bf,
                         cudaFuncAttributeMaxDynamicSharedMemorySize, GSMEM_BYTES);

    // Fused Q/K/V projections (Q pre-scaled by 1/8; V -> dk-major)
    GemmArgs gq = { query, Wq, bq, q, 0.125f, 1 };
    GemmArgs gk = { key_,  Wk, bk, k, 1.0f,   1 };
    GemmArgs gv = { value, Wv, bv, v, 1.0f,   2 };
    gemm_bf<<<dim3(DD / 128, MM / 128, 3), 256, GSMEM_BYTES>>>(gq, gk, gv);

    // Attention (fp16 2-term mma.sync)
    attn_fp16<<<dim3(SS / 64, BB * HH), 128>>>(q, k, v, x);

    // Output projection -> d_out
    GemmArgs go = { x, Wo, bo, out, 1.0f, 0 };
    gemm_bf<<<dim3(DD / 128, MM / 128, 1), 256, GSMEM_BYTES>>>(go, go, go);
}

// round 9
// speedup vs baseline: 3.8953x; 1.3168x over previous
#include <cuda_runtime.h>
#include <cuda_fp16.h>
#include <math.h>
#include <stdint.h>

// Problem constants
#define BB   4
#define SS   2048
#define DD   1024
#define HH   16
#define DKK  64
#define MM   (BB*SS)          // 8192 rows

// Scratch: Q,K in [B,H,S,DK]; V in [B,H,DK,S] (dk-major!); X in [B,S,D]
__device__ float g_q[(size_t)BB*HH*SS*DKK];
__device__ float g_k[(size_t)BB*HH*SS*DKK];
__device__ float g_v[(size_t)BB*HH*DKK*SS];
__device__ float g_x[(size_t)BB*SS*DD];

// ---------------------------------------------------------------------------
// fp16 helpers
// ---------------------------------------------------------------------------
__device__ __forceinline__ uint32_t pack2h(float x, float y) {
    __half2 h = __floats2half2_rn(x, y);
    return *reinterpret_cast<uint32_t*>(&h);
}
__device__ __forceinline__ void split2h(float x, float y, uint32_t& h, uint32_t& l) {
    __half hx = __float2half_rn(x);
    __half hy = __float2half_rn(y);
    __half lx = __float2half_rn(x - __half2float(hx));
    __half ly = __float2half_rn(y - __half2float(hy));
    __half2 hh = __halves2half2(hx, hy);
    __half2 ll = __halves2half2(lx, ly);
    h = *reinterpret_cast<uint32_t*>(&hh);
    l = *reinterpret_cast<uint32_t*>(&ll);
}
// D(16x8,f32) += A(16x16,f16) * B(16x8,f16)
__device__ __forceinline__ void mma16h(float* d, const uint32_t* a, const uint32_t* b) {
    asm("mma.sync.aligned.m16n8k16.row.col.f32.f16.f16.f32 "
        "{%0,%1,%2,%3}, {%4,%5,%6,%7}, {%8,%9}, {%0,%1,%2,%3};"
        : "+f"(d[0]), "+f"(d[1]), "+f"(d[2]), "+f"(d[3])
        : "r"(a[0]), "r"(a[1]), "r"(a[2]), "r"(a[3]),
          "r"(b[0]), "r"(b[1]));
}

// ---------------------------------------------------------------------------
// fp16 2-mma SGEMM:  Y = (A @ W^T + bias) * alpha
// Block 128x128, BK=64, 256 threads (8 warps), warp tile 64x32.
// A: 2-term (hi/lo interleaved uint2 -> LDS.64 frag loads).
// W: single-term fp16 (rounding error ~2^-12, RSS-negligible vs 1e-3 gate).
// head_layout: 0 -> [M,N]; 1 -> [B,H,S,DK]; 2 -> [B,H,DK,S]
// ---------------------------------------------------------------------------
#define GA2 36                    // A row stride in uint2 (4r+q bijective mod16)
#define GB1 36                    // B row stride in uint32
#define A_U2 (128 * GA2)
#define B_U1 (128 * GB1)
#define GSMEM_BYTES (A_U2 * 8 + B_U1 * 4)   // 36864 + 18432 = 55296

struct GemmArgs {
    const float* A; const float* W; const float* bias;
    float* Y; float alpha; int head_layout;
};

__global__ __launch_bounds__(256, 2) void gemm_fp16(GemmArgs ga, GemmArgs gb, GemmArgs gc)
{
    GemmArgs g = (blockIdx.z == 0) ? ga : ((blockIdx.z == 1) ? gb : gc);
    extern __shared__ uint32_t sp[];
    uint2*    Au = (uint2*)sp;                    // interleaved {hi, lo} pairs
    uint32_t* Bu = sp + A_U2 * 2;                 // hi pairs only

    const int tid  = threadIdx.x;
    const int lane = tid & 31;
    const int wrp  = tid >> 5;
    const int wy   = wrp & 1;          // m-warp (0..1), 64 rows
    const int wx   = wrp >> 1;         // n-warp (0..3), 32 cols
    const int r    = lane >> 2;        // 0..7
    const int q    = lane & 3;         // 0..3
    const int bm   = blockIdx.y * 128;
    const int bn   = blockIdx.x * 128;

    float c[4][4][4];
    #pragma unroll
    for (int mt = 0; mt < 4; mt++)
        #pragma unroll
        for (int nt = 0; nt < 4; nt++)
            #pragma unroll
            for (int i = 0; i < 4; i++) c[mt][nt][i] = 0.0f;

    for (int kt = 0; kt < DD; kt += 64) {
        // Stage A (split 2-term, interleaved) and W (1-term) tiles, 128x64.
        #pragma unroll
        for (int rr = 0; rr < 8; rr++) {
            int lin = tid + rr * 256;      // 0..2047
            int row = lin >> 4;            // 0..127
            int c4  = (lin & 15) << 2;     // 0..60 (k elems)
            int p   = c4 >> 1;             // pair index (even)
            float4 va = *(const float4*)&g.A[(size_t)(bm + row) * DD + kt + c4];
            uint32_t h0, l0, h1, l1;
            split2h(va.x, va.y, h0, l0);
            split2h(va.z, va.w, h1, l1);
            *(uint4*)&Au[row * GA2 + p] = make_uint4(h0, l0, h1, l1);
            float4 vb = *(const float4*)&g.W[(size_t)(bn + row) * DD + kt + c4];
            *(uint2*)&Bu[row * GB1 + p] =
                make_uint2(pack2h(vb.x, vb.y), pack2h(vb.z, vb.w));
        }
        __syncthreads();

        #pragma unroll
        for (int ks = 0; ks < 4; ks++) {
            const int koff = ks * 8;
            uint32_t bh[4][2];
            #pragma unroll
            for (int nt = 0; nt < 4; nt++) {
                int idx = (wx * 32 + nt * 8 + r) * GB1 + koff + q;
                bh[nt][0] = Bu[idx];
                bh[nt][1] = Bu[idx + 4];
            }
            #pragma unroll
            for (int mt = 0; mt < 4; mt++) {
                int i0 = (wy * 64 + mt * 16 + r) * GA2 + koff + q;
                int i1 = i0 + 8 * GA2;
                uint2 u0 = Au[i0];
                uint2 u1 = Au[i1];
                uint2 u2 = Au[i0 + 4];
                uint2 u3 = Au[i1 + 4];
                uint32_t ah[4] = {u0.x, u1.x, u2.x, u3.x};
                uint32_t al[4] = {u0.y, u1.y, u2.y, u3.y};
                #pragma unroll
                for (int nt = 0; nt < 4; nt++) {
                    mma16h(c[mt][nt], al, bh[nt]);
                    mma16h(c[mt][nt], ah, bh[nt]);
                }
            }
        }
        __syncthreads();
    }

    // Epilogue
    #pragma unroll
    for (int mt = 0; mt < 4; mt++) {
        #pragma unroll
        for (int nt = 0; nt < 4; nt++) {
            int n = bn + wx * 32 + nt * 8 + 2 * q;
            float b0 = g.bias[n], b1 = g.bias[n + 1];
            #pragma unroll
            for (int half = 0; half < 2; half++) {
                int m = bm + wy * 64 + mt * 16 + r + half * 8;
                float vx = (c[mt][nt][2 * half]     + b0) * g.alpha;
                float vy = (c[mt][nt][2 * half + 1] + b1) * g.alpha;
                if (g.head_layout == 0) {
                    *(float2*)&g.Y[(size_t)m * DD + n] = make_float2(vx, vy);
                } else {
                    int b  = m >> 11;         // / SS
                    int s  = m & (SS - 1);
                    int h  = n >> 6;          // / DK
                    int dk = n & 63;
                    if (g.head_layout == 1) {
                        *(float2*)&g.Y[(((size_t)(b * HH + h)) * SS + s) * DKK + dk]
                            = make_float2(vx, vy);
                    } else {
                        // [B,H,DK,S]
                        size_t base = ((size_t)(b * HH + h) * DKK + dk) * SS + s;
                        g.Y[base]      = vx;
                        g.Y[base + SS] = vy;
                    }
                }
            }
        }
    }
}

// ---------------------------------------------------------------------------
// fp16 1-term flash attention. One block = one (b,h) x 64-query tile.
// 128 threads (4 warps); warp owns 16 query rows x all 64 keys/dims.
// Q, K, V, P all single-term fp16 (score abs-err ~3e-4; p rel-err ~2^-12;
// RSS within the 1e-3 gate). QK^T: 1 mma/chunk; PV: 1 mma/chunk.
// ---------------------------------------------------------------------------
#define KW 36   // word stride: (4r+q)%32 bijective -> conflict-free frags

__global__ __launch_bounds__(128, 4) void attn_fp16(
    const float* __restrict__ Q,
    const float* __restrict__ Kh,
    const float* __restrict__ V,
    float* __restrict__ X)
{
    __shared__ uint32_t K0[64 * KW];
    __shared__ uint32_t V0[64 * KW];

    const int tid  = threadIdx.x;
    const int lane = tid & 31;
    const int w    = tid >> 5;           // warp 0..3 -> query rows w*16..
    const int r    = lane >> 2;          // 0..7
    const int q    = lane & 3;           // 0..3
    const int qt   = blockIdx.x;         // 0..31
    const int bh   = blockIdx.y;         // 0..63
    const int h    = bh & (HH - 1);
    const int bb   = bh >> 4;

    const float* Qbase = Q + ((size_t)bh * SS + qt * 64 + w * 16) * DKK;
    const float* Kbase = Kh + (size_t)bh * SS * DKK;
    const float* Vbase = V + (size_t)bh * DKK * SS;   // [dk][s]

    // Preload Q fragments: 4 k-steps of 16 dims, single-term fp16 pairs.
    uint32_t qh[4][4];
    #pragma unroll
    for (int kt = 0; kt < 4; kt++) {
        int k0 = kt * 16;
        float2 f0 = *(const float2*)&Qbase[(size_t)r * DKK + k0 + 2 * q];
        float2 f1 = *(const float2*)&Qbase[(size_t)(r + 8) * DKK + k0 + 2 * q];
        float2 f2 = *(const float2*)&Qbase[(size_t)r * DKK + k0 + 2 * q + 8];
        float2 f3 = *(const float2*)&Qbase[(size_t)(r + 8) * DKK + k0 + 2 * q + 8];
        qh[kt][0] = pack2h(f0.x, f0.y);
        qh[kt][1] = pack2h(f1.x, f1.y);
        qh[kt][2] = pack2h(f2.x, f2.y);
        qh[kt][3] = pack2h(f3.x, f3.y);
    }

    float o[8][4];
    #pragma unroll
    for (int dt = 0; dt < 8; dt++)
        #pragma unroll
        for (int i = 0; i < 4; i++) o[dt][i] = 0.0f;
    float mrow[2] = {-1e30f, -1e30f};
    float lrow[2] = {0.0f, 0.0f};

    for (int t = 0; t < SS / 64; t++) {
        __syncthreads();
        // Stage K and V tiles (single-term fp16 pairs).
        #pragma unroll
        for (int rr = 0; rr < 8; rr++) {
            int lin = tid + rr * 128;     // 0..1023
            int row = lin >> 4;           // key for K, dk for V
            int c4  = (lin & 15) << 2;
            int w0  = row * KW + (c4 >> 1);
            float4 kv = *(const float4*)&Kbase[(size_t)(t * 64 + row) * DKK + c4];
            *(uint2*)&K0[w0] = make_uint2(pack2h(kv.x, kv.y), pack2h(kv.z, kv.w));
            float4 vv = *(const float4*)&Vbase[(size_t)row * SS + t * 64 + c4];
            *(uint2*)&V0[w0] = make_uint2(pack2h(vv.x, vv.y), pack2h(vv.z, vv.w));
        }
        __syncthreads();

        // ---- S = Q K^T (16 x 64 per warp), 1 mma per 16-k chunk ----
        float s[8][4];
        #pragma unroll
        for (int nt = 0; nt < 8; nt++)
            #pragma unroll
            for (int i = 0; i < 4; i++) s[nt][i] = 0.0f;

        #pragma unroll
        for (int kt = 0; kt < 4; kt++) {
            const int koff = kt * 8;
            #pragma unroll
            for (int nt = 0; nt < 8; nt++) {
                int idx = (nt * 8 + r) * KW + koff + q;
                uint32_t kf[2];
                kf[0] = K0[idx];
                kf[1] = K0[idx + 4];
                mma16h(s[nt], qh[kt], kf);
            }
        }

        // ---- online softmax (rows r / r+8; 4-lane row groups) ----
        #pragma unroll
        for (int half = 0; half < 2; half++) {
            float rm = -1e30f;
            #pragma unroll
            for (int nt = 0; nt < 8; nt++)
                rm = fmaxf(rm, fmaxf(s[nt][2 * half], s[nt][2 * half + 1]));
            rm = fmaxf(rm, __shfl_xor_sync(0xffffffffu, rm, 1));
            rm = fmaxf(rm, __shfl_xor_sync(0xffffffffu, rm, 2));
            float mnew  = fmaxf(mrow[half], rm);
            float scale = __expf(mrow[half] - mnew);
            float rs = 0.0f;
            #pragma unroll
            for (int nt = 0; nt < 8; nt++) {
                s[nt][2 * half]     = __expf(s[nt][2 * half] - mnew);
                s[nt][2 * half + 1] = __expf(s[nt][2 * half + 1] - mnew);
                rs += s[nt][2 * half] + s[nt][2 * half + 1];
            }
            rs += __shfl_xor_sync(0xffffffffu, rs, 1);
            rs += __shfl_xor_sync(0xffffffffu, rs, 2);
            lrow[half] = lrow[half] * scale + rs;
            mrow[half] = mnew;
            #pragma unroll
            for (int dt = 0; dt < 8; dt++) {
                o[dt][2 * half]     *= scale;
                o[dt][2 * half + 1] *= scale;
            }
        }

        // ---- O += P V : P single-term fp16 (straight from QK regs) ----
        #pragma unroll
        for (int kt = 0; kt < 4; kt++) {
            uint32_t ph[4];
            ph[0] = pack2h(s[2 * kt][0],     s[2 * kt][1]);
            ph[1] = pack2h(s[2 * kt][2],     s[2 * kt][3]);
            ph[2] = pack2h(s[2 * kt + 1][0], s[2 * kt + 1][1]);
            ph[3] = pack2h(s[2 * kt + 1][2], s[2 * kt + 1][3]);
            #pragma unroll
            for (int dt = 0; dt < 8; dt++) {
                int idx = (dt * 8 + r) * KW + kt * 8 + q;
                uint32_t vh[2];
                vh[0] = V0[idx];
                vh[1] = V0[idx + 4];
                mma16h(o[dt], ph, vh);
            }
        }
    }

    // Epilogue: X[b][s][h*64+dk] = o / l  (float2 stores)
    float inv0 = 1.0f / lrow[0];
    float inv1 = 1.0f / lrow[1];
    float* Xb = X + ((size_t)bb * SS + qt * 64 + w * 16) * DD + h * DKK;
    #pragma unroll
    for (int dt = 0; dt < 8; dt++) {
        int col = dt * 8 + 2 * q;
        *(float2*)&Xb[(size_t)r * DD + col]
            = make_float2(o[dt][0] * inv0, o[dt][1] * inv0);
        *(float2*)&Xb[(size_t)(r + 8) * DD + col]
            = make_float2(o[dt][2] * inv1, o[dt][3] * inv1);
    }
}

// ---------------------------------------------------------------------------
extern "C" void kernel_launch(void* const* d_in, const int* in_sizes, int n_in,
                              void* d_out, int out_size)
{
    const float* query = (const float*)d_in[0];
    const float* key_  = (const float*)d_in[1];
    const float* value = (const float*)d_in[2];
    const float* Wq    = (const float*)d_in[3];
    const float* bq    = (const float*)d_in[4];
    const float* Wk    = (const float*)d_in[5];
    const float* bk    = (const float*)d_in[6];
    const float* Wv    = (const float*)d_in[7];
    const float* bv    = (const float*)d_in[8];
    const float* Wo    = (const float*)d_in[9];
    const float* bo    = (const float*)d_in[10];
    float* out = (float*)d_out;

    float *q, *k, *v, *x;
    cudaGetSymbolAddress((void**)&q, g_q);
    cudaGetSymbolAddress((void**)&k, g_k);
    cudaGetSymbolAddress((void**)&v, g_v);
    cudaGetSymbolAddress((void**)&x, g_x);

    cudaFuncSetAttribute(gemm_fp16,
                         cudaFuncAttributeMaxDynamicSharedMemorySize, GSMEM_BYTES);

    // Fused Q/K/V projections (Q pre-scaled by 1/8; V -> dk-major)
    GemmArgs gq = { query, Wq, bq, q, 0.125f, 1 };
    GemmArgs gk = { key_,  Wk, bk, k, 1.0f,   1 };
    GemmArgs gv = { value, Wv, bv, v, 1.0f,   2 };
    gemm_fp16<<<dim3(DD / 128, MM / 128, 3), 256, GSMEM_BYTES>>>(gq, gk, gv);

    // Attention (fp16 1-term mma.sync)
    attn_fp16<<<dim3(SS / 64, BB * HH), 128>>>(q, k, v, x);

    // Output projection -> d_out
    GemmArgs go = { x, Wo, bo, out, 1.0f, 0 };
    gemm_fp16<<<dim3(DD / 128, MM / 128, 1), 256, GSMEM_BYTES>>>(go, go, go);
}

// round 10
// speedup vs baseline: 4.7130x; 1.2099x over previous
#include <cuda_runtime.h>
#include <cuda_fp16.h>
#include <math.h>
#include <stdint.h>

// Problem constants
#define BB   4
#define SS   2048
#define DD   1024
#define HH   16
#define DKK  64
#define MM   (BB*SS)          // 8192 rows

// ---------------------------------------------------------------------------
// Pre-converted gmem planes
//  g_ahl[z] : inputs (z=0 query,1 key,2 value) as interleaved {hi,lo} fp16
//             pairs: uint2 per 2 k-elems, [M][K/2]
//  g_wh[z]  : weights (0 Wq,1 Wk,2 Wv,3 Wo) 1-term fp16 pairs [N][K/2] u32
//  g_q16/k16: projected Q,K fp16 [B,H,S,DK/2] u32 pairs
//  g_v16    : projected V fp16 [B,H,DK,S] halves (u32-pair aligned)
//  g_xhl    : attention out X as {hi,lo} pairs [M][D/2]
// ---------------------------------------------------------------------------
__device__ uint2    g_ahl[3][(size_t)MM * (DD / 2)];
__device__ uint32_t g_wh[4][(size_t)DD * (DD / 2)];
__device__ uint32_t g_q16[(size_t)BB * HH * SS * (DKK / 2)];
__device__ uint32_t g_k16[(size_t)BB * HH * SS * (DKK / 2)];
__device__ uint32_t g_v16[(size_t)BB * HH * DKK * (SS / 2)];
__device__ uint2    g_xhl[(size_t)MM * (DD / 2)];

// ---------------------------------------------------------------------------
// helpers
// ---------------------------------------------------------------------------
__device__ __forceinline__ uint32_t smem_u32(const void* p) {
    uint32_t a;
    asm("{ .reg .u64 t; cvta.to.shared.u64 t, %1; cvt.u32.u64 %0, t; }"
        : "=r"(a) : "l"(p));
    return a;
}
__device__ __forceinline__ uint32_t pack2h(float x, float y) {
    __half2 h = __floats2half2_rn(x, y);
    return *reinterpret_cast<uint32_t*>(&h);
}
__device__ __forceinline__ void split2h(float x, float y, uint32_t& h, uint32_t& l) {
    __half hx = __float2half_rn(x);
    __half hy = __float2half_rn(y);
    __half lx = __float2half_rn(x - __half2float(hx));
    __half ly = __float2half_rn(y - __half2float(hy));
    __half2 hh = __halves2half2(hx, hy);
    __half2 ll = __halves2half2(lx, ly);
    h = *reinterpret_cast<uint32_t*>(&hh);
    l = *reinterpret_cast<uint32_t*>(&ll);
}
// D(16x8,f32) += A(16x16,f16) * B(16x8,f16)
__device__ __forceinline__ void mma16h(float* d, const uint32_t* a, const uint32_t* b) {
    asm("mma.sync.aligned.m16n8k16.row.col.f32.f16.f16.f32 "
        "{%0,%1,%2,%3}, {%4,%5,%6,%7}, {%8,%9}, {%0,%1,%2,%3};"
        : "+f"(d[0]), "+f"(d[1]), "+f"(d[2]), "+f"(d[3])
        : "r"(a[0]), "r"(a[1]), "r"(a[2]), "r"(a[3]),
          "r"(b[0]), "r"(b[1]));
}
__device__ __forceinline__ void cpa16(uint32_t dst, const void* src) {
    asm volatile("cp.async.cg.shared.global [%0], [%1], 16;"
                 :: "r"(dst), "l"(src) : "memory");
}
#define CP_COMMIT() asm volatile("cp.async.commit_group;" ::: "memory")

// ---------------------------------------------------------------------------
// convert kernels (run once per launch, bandwidth-bound)
// ---------------------------------------------------------------------------
__global__ __launch_bounds__(256) void cvt_in(const float* __restrict__ q,
                                              const float* __restrict__ k,
                                              const float* __restrict__ v)
{
    const float* src = (blockIdx.z == 0) ? q : ((blockIdx.z == 1) ? k : v);
    uint4* dst = (uint4*)g_ahl[blockIdx.z];
    size_t i = (size_t)blockIdx.x * 256 + threadIdx.x;   // float4 index
    float4 f = ((const float4*)src)[i];
    uint32_t h0, l0, h1, l1;
    split2h(f.x, f.y, h0, l0);
    split2h(f.z, f.w, h1, l1);
    dst[i] = make_uint4(h0, l0, h1, l1);
}

__global__ __launch_bounds__(256) void cvt_w(const float* __restrict__ wq,
                                             const float* __restrict__ wk,
                                             const float* __restrict__ wv,
                                             const float* __restrict__ wo)
{
    const float* src = (blockIdx.z == 0) ? wq :
                       (blockIdx.z == 1) ? wk :
                       (blockIdx.z == 2) ? wv : wo;
    uint2* dst = (uint2*)g_wh[blockIdx.z];
    size_t i = (size_t)blockIdx.x * 256 + threadIdx.x;   // float4 index
    float4 f = ((const float4*)src)[i];
    dst[i] = make_uint2(pack2h(f.x, f.y), pack2h(f.z, f.w));
}

// ---------------------------------------------------------------------------
// fp16 2-mma SGEMM with cp.async double buffer:
//   Y = (A @ W^T + bias) * alpha
// Block 128x128, BK=32, 256 threads (8 warps), warp tile 64x32.
// A: pre-split {hi,lo} uint2 pairs (gmem) -> pure copy staging.
// W: 1-term fp16 pairs (gmem) -> pure copy staging.
// y_sel: 0 -> g_q16 [B,H,S,DK] fp16; 1 -> g_k16; 2 -> g_v16 [B,H,DK,S] fp16;
//        3 -> Yout fp32 [M,N]
// ---------------------------------------------------------------------------
#define AST2 20                       // A row stride in uint2
#define BST1 20                       // B row stride in uint32
#define A_STAGE_U32 (128 * AST2 * 2)  // 5120 u32 = 20480 B
#define B_STAGE_U32 (128 * BST1)      // 2560 u32 = 10240 B
#define GSMEM_BYTES ((2 * A_STAGE_U32 + 2 * B_STAGE_U32) * 4)   // 61440

struct GemmArgs {
    int a_sel;            // 0..2 -> g_ahl[z], 3 -> g_xhl
    int w_sel;            // 0..3 -> g_wh[z]
    const float* bias;
    float* Yout;          // used when y_sel == 3
    float alpha;
    int y_sel;
};

__global__ __launch_bounds__(256, 2) void gemm_fp16(GemmArgs ga, GemmArgs gb, GemmArgs gc)
{
    GemmArgs g = (blockIdx.z == 0) ? ga : ((blockIdx.z == 1) ? gb : gc);
    const uint2*    gA = (g.a_sel < 3) ? g_ahl[g.a_sel] : g_xhl;
    const uint32_t* gW = g_wh[g.w_sel];

    extern __shared__ uint32_t sp[];
    uint2*    As[2] = { (uint2*)sp, (uint2*)sp + 128 * AST2 };
    uint32_t* Bs[2] = { sp + 2 * A_STAGE_U32,
                        sp + 2 * A_STAGE_U32 + B_STAGE_U32 };
    const uint32_t sbase = smem_u32(sp);

    const int tid  = threadIdx.x;
    const int lane = tid & 31;
    const int wrp  = tid >> 5;
    const int wy   = wrp & 1;          // m-warp (0..1), 64 rows
    const int wx   = wrp >> 1;         // n-warp (0..3), 32 cols
    const int r    = lane >> 2;        // 0..7
    const int q    = lane & 3;         // 0..3
    const int bm   = blockIdx.y * 128;
    const int bn   = blockIdx.x * 128;

    // cp.async staging roles (per thread: 4 A-chunks + 2 B-chunks of 16B)
    const int arow[4] = { (tid + 0)   >> 3, (tid + 256) >> 3,
                          (tid + 512) >> 3, (tid + 768) >> 3 };
    const int acol    = tid & 7;                       // same for all 4
    const int brow[2] = { (tid + 0) >> 2, (tid + 256) >> 2 };
    const int bcol    = tid & 3;

    float c[4][4][4];
    #pragma unroll
    for (int mt = 0; mt < 4; mt++)
        #pragma unroll
        for (int nt = 0; nt < 4; nt++)
            #pragma unroll
            for (int i = 0; i < 4; i++) c[mt][nt][i] = 0.0f;

    // issue stage for k-tile it into buffer s
    auto issue = [&](int it, int s) {
        uint32_t aB = sbase + s * (A_STAGE_U32 * 4);
        uint32_t bB = sbase + 2 * A_STAGE_U32 * 4 + s * (B_STAGE_U32 * 4);
        #pragma unroll
        for (int i = 0; i < 4; i++) {
            int row = arow[i];
            cpa16(aB + (uint32_t)(row * AST2 + acol * 2) * 8,
                  gA + (size_t)(bm + row) * (DD / 2) + it * 16 + acol * 2);
        }
        #pragma unroll
        for (int i = 0; i < 2; i++) {
            int row = brow[i];
            cpa16(bB + (uint32_t)(row * BST1 + bcol * 4) * 4,
                  gW + (size_t)(bn + row) * (DD / 2) + it * 16 + bcol * 4);
        }
        CP_COMMIT();
    };

    issue(0, 0);
    const int NT = DD / 32;           // 32 k-tiles

    for (int it = 0; it < NT; it++) {
        const int s = it & 1;
        if (it + 1 < NT) issue(it + 1, (it + 1) & 1);
        if (it + 1 < NT) { asm volatile("cp.async.wait_group 1;" ::: "memory"); }
        else             { asm volatile("cp.async.wait_group 0;" ::: "memory"); }
        __syncthreads();

        const uint2*    Au = As[s];
        const uint32_t* Bu = Bs[s];
        #pragma unroll
        for (int ks = 0; ks < 2; ks++) {
            const int koff = ks * 8;
            uint32_t bh[4][2];
            #pragma unroll
            for (int nt = 0; nt < 4; nt++) {
                int idx = (wx * 32 + nt * 8 + r) * BST1 + koff + q;
                bh[nt][0] = Bu[idx];
                bh[nt][1] = Bu[idx + 4];
            }
            #pragma unroll
            for (int mt = 0; mt < 4; mt++) {
                int i0 = (wy * 64 + mt * 16 + r) * AST2 + koff + q;
                int i1 = i0 + 8 * AST2;
                uint2 u0 = Au[i0];
                uint2 u1 = Au[i1];
                uint2 u2 = Au[i0 + 4];
                uint2 u3 = Au[i1 + 4];
                uint32_t ah[4] = {u0.x, u1.x, u2.x, u3.x};
                uint32_t al[4] = {u0.y, u1.y, u2.y, u3.y};
                #pragma unroll
                for (int nt = 0; nt < 4; nt++) {
                    mma16h(c[mt][nt], al, bh[nt]);
                    mma16h(c[mt][nt], ah, bh[nt]);
                }
            }
        }
        __syncthreads();
    }

    // Epilogue
    #pragma unroll
    for (int mt = 0; mt < 4; mt++) {
        #pragma unroll
        for (int nt = 0; nt < 4; nt++) {
            int n = bn + wx * 32 + nt * 8 + 2 * q;
            float b0 = g.bias[n], b1 = g.bias[n + 1];
            #pragma unroll
            for (int half = 0; half < 2; half++) {
                int m = bm + wy * 64 + mt * 16 + r + half * 8;
                float vx = (c[mt][nt][2 * half]     + b0) * g.alpha;
                float vy = (c[mt][nt][2 * half + 1] + b1) * g.alpha;
                if (g.y_sel == 3) {
                    *(float2*)&g.Yout[(size_t)m * DD + n] = make_float2(vx, vy);
                } else {
                    int b  = m >> 11;         // / SS
                    int s  = m & (SS - 1);
                    int h  = n >> 6;          // / DK
                    int dk = n & 63;
                    if (g.y_sel == 0) {
                        g_q16[(((size_t)(b * HH + h)) * SS + s) * (DKK / 2) + (dk >> 1)]
                            = pack2h(vx, vy);
                    } else if (g.y_sel == 1) {
                        g_k16[(((size_t)(b * HH + h)) * SS + s) * (DKK / 2) + (dk >> 1)]
                            = pack2h(vx, vy);
                    } else {
                        __half* dst = (__half*)g_v16 +
                            ((size_t)(b * HH + h) * DKK + dk) * SS + s;
                        dst[0]  = __float2half_rn(vx);
                        dst[SS] = __float2half_rn(vy);
                    }
                }
            }
        }
    }
}

// ---------------------------------------------------------------------------
// fp16 flash attention with cp.async double-buffered K/V.
// One block = one (b,h) x 64-query tile; 128 threads (4 warps).
// Q/K/V already fp16 in gmem (pure-copy staging). X written as {hi,lo} pairs.
// ---------------------------------------------------------------------------
#define KW 36                          // u32 row stride ((4r+q)%32 bijective)
#define KV_STAGE_U32 (2 * 64 * KW)     // K plane + V plane = 4608 u32

__global__ __launch_bounds__(128, 4) void attn_fp16()
{
    __shared__ uint32_t SH[2 * KV_STAGE_U32];   // 36864 B

    const int tid  = threadIdx.x;
    const int lane = tid & 31;
    const int w    = tid >> 5;           // warp 0..3 -> query rows w*16..
    const int r    = lane >> 2;          // 0..7
    const int q    = lane & 3;           // 0..3
    const int qt   = blockIdx.x;         // 0..31
    const int bh   = blockIdx.y;         // 0..63
    const int h    = bh & (HH - 1);
    const int bb   = bh >> 4;

    const uint32_t* Qb = g_q16 + ((size_t)bh * SS + qt * 64 + w * 16) * (DKK / 2);
    const uint32_t* Kb = g_k16 + (size_t)bh * SS * (DKK / 2);
    const uint32_t* Vb = g_v16 + (size_t)bh * DKK * (SS / 2);
    const uint32_t sbase = smem_u32(SH);

    // Preload Q fragments (u32 pairs, direct fp16 loads)
    uint32_t qh[4][4];
    #pragma unroll
    for (int kt = 0; kt < 4; kt++) {
        qh[kt][0] = Qb[(size_t)r * 32 + kt * 8 + q];
        qh[kt][1] = Qb[(size_t)(r + 8) * 32 + kt * 8 + q];
        qh[kt][2] = Qb[(size_t)r * 32 + kt * 8 + q + 4];
        qh[kt][3] = Qb[(size_t)(r + 8) * 32 + kt * 8 + q + 4];
    }

    // staging roles: 8 x 16B chunks per thread (4 K + 4 V)
    const int krow[4] = { (tid + 0)   >> 3, (tid + 128) >> 3,
                          (tid + 256) >> 3, (tid + 384) >> 3 };
    const int kcol    = tid & 7;

    auto issue = [&](int t, int s) {
        uint32_t kB = sbase + s * (KV_STAGE_U32 * 4);
        uint32_t vB = kB + 64 * KW * 4;
        #pragma unroll
        for (int i = 0; i < 4; i++) {
            int row = krow[i];
            cpa16(kB + (uint32_t)(row * KW + kcol * 4) * 4,
                  Kb + (size_t)(t * 64 + row) * 32 + kcol * 4);
            cpa16(vB + (uint32_t)(row * KW + kcol * 4) * 4,
                  Vb + (size_t)row * (SS / 2) + t * 32 + kcol * 4);
        }
        CP_COMMIT();
    };

    float o[8][4];
    #pragma unroll
    for (int dt = 0; dt < 8; dt++)
        #pragma unroll
        for (int i = 0; i < 4; i++) o[dt][i] = 0.0f;
    float mrow[2] = {-1e30f, -1e30f};
    float lrow[2] = {0.0f, 0.0f};

    issue(0, 0);
    const int NT = SS / 64;              // 32 tiles

    for (int t = 0; t < NT; t++) {
        const int s = t & 1;
        if (t + 1 < NT) issue(t + 1, (t + 1) & 1);
        if (t + 1 < NT) { asm volatile("cp.async.wait_group 1;" ::: "memory"); }
        else            { asm volatile("cp.async.wait_group 0;" ::: "memory"); }
        __syncthreads();

        const uint32_t* K0 = SH + s * KV_STAGE_U32;
        const uint32_t* V0 = K0 + 64 * KW;

        // ---- S = Q K^T (16 x 64 per warp) ----
        float sc[8][4];
        #pragma unroll
        for (int nt = 0; nt < 8; nt++)
            #pragma unroll
            for (int i = 0; i < 4; i++) sc[nt][i] = 0.0f;

        #pragma unroll
        for (int kt = 0; kt < 4; kt++) {
            const int koff = kt * 8;
            #pragma unroll
            for (int nt = 0; nt < 8; nt++) {
                int idx = (nt * 8 + r) * KW + koff + q;
                uint32_t kf[2];
                kf[0] = K0[idx];
                kf[1] = K0[idx + 4];
                mma16h(sc[nt], qh[kt], kf);
            }
        }

        // ---- online softmax (rows r / r+8; 4-lane row groups) ----
        #pragma unroll
        for (int half = 0; half < 2; half++) {
            float rm = -1e30f;
            #pragma unroll
            for (int nt = 0; nt < 8; nt++)
                rm = fmaxf(rm, fmaxf(sc[nt][2 * half], sc[nt][2 * half + 1]));
            rm = fmaxf(rm, __shfl_xor_sync(0xffffffffu, rm, 1));
            rm = fmaxf(rm, __shfl_xor_sync(0xffffffffu, rm, 2));
            float mnew  = fmaxf(mrow[half], rm);
            float scale = __expf(mrow[half] - mnew);
            float rs = 0.0f;
            #pragma unroll
            for (int nt = 0; nt < 8; nt++) {
                sc[nt][2 * half]     = __expf(sc[nt][2 * half] - mnew);
                sc[nt][2 * half + 1] = __expf(sc[nt][2 * half + 1] - mnew);
                rs += sc[nt][2 * half] + sc[nt][2 * half + 1];
            }
            rs += __shfl_xor_sync(0xffffffffu, rs, 1);
            rs += __shfl_xor_sync(0xffffffffu, rs, 2);
            lrow[half] = lrow[half] * scale + rs;
            mrow[half] = mnew;
            #pragma unroll
            for (int dt = 0; dt < 8; dt++) {
                o[dt][2 * half]     *= scale;
                o[dt][2 * half + 1] *= scale;
            }
        }

        // ---- O += P V (P packed straight from QK accumulators) ----
        #pragma unroll
        for (int kt = 0; kt < 4; kt++) {
            uint32_t ph[4];
            ph[0] = pack2h(sc[2 * kt][0],     sc[2 * kt][1]);
            ph[1] = pack2h(sc[2 * kt][2],     sc[2 * kt][3]);
            ph[2] = pack2h(sc[2 * kt + 1][0], sc[2 * kt + 1][1]);
            ph[3] = pack2h(sc[2 * kt + 1][2], sc[2 * kt + 1][3]);
            #pragma unroll
            for (int dt = 0; dt < 8; dt++) {
                int idx = (dt * 8 + r) * KW + kt * 8 + q;
                uint32_t vh[2];
                vh[0] = V0[idx];
                vh[1] = V0[idx + 4];
                mma16h(o[dt], ph, vh);
            }
        }
        __syncthreads();
    }

    // Epilogue: X as {hi,lo} uint2 pairs at [m][(h*64+col)/2]
    float inv0 = 1.0f / lrow[0];
    float inv1 = 1.0f / lrow[1];
    uint2* Xb = g_xhl + ((size_t)bb * SS + qt * 64 + w * 16) * (DD / 2) + h * 32;
    #pragma unroll
    for (int dt = 0; dt < 8; dt++) {
        int cp = (dt * 8 + 2 * q) >> 1;   // uint2 index within head
        uint32_t hh, ll;
        split2h(o[dt][0] * inv0, o[dt][1] * inv0, hh, ll);
        Xb[(size_t)r * (DD / 2) + cp] = make_uint2(hh, ll);
        split2h(o[dt][2] * inv1, o[dt][3] * inv1, hh, ll);
        Xb[(size_t)(r + 8) * (DD / 2) + cp] = make_uint2(hh, ll);
    }
}

// ---------------------------------------------------------------------------
extern "C" void kernel_launch(void* const* d_in, const int* in_sizes, int n_in,
                              void* d_out, int out_size)
{
    const float* query = (const float*)d_in[0];
    const float* key_  = (const float*)d_in[1];
    const float* value = (const float*)d_in[2];
    const float* Wq    = (const float*)d_in[3];
    const float* bq    = (const float*)d_in[4];
    const float* Wk    = (const float*)d_in[5];
    const float* bk    = (const float*)d_in[6];
    const float* Wv    = (const float*)d_in[7];
    const float* bv    = (const float*)d_in[8];
    const float* Wo    = (const float*)d_in[9];
    const float* bo    = (const float*)d_in[10];
    float* out = (float*)d_out;

    cudaFuncSetAttribute(gemm_fp16,
                         cudaFuncAttributeMaxDynamicSharedMemorySize, GSMEM_BYTES);

    // One-time (per launch) conversions
    cvt_in<<<dim3(MM * DD / 4 / 256, 1, 3), 256>>>(query, key_, value);
    cvt_w<<<dim3(DD * DD / 4 / 256, 1, 4), 256>>>(Wq, Wk, Wv, Wo);

    // Fused Q/K/V projections (Q pre-scaled by 1/8; V -> dk-major fp16)
    GemmArgs gq = { 0, 0, bq, nullptr, 0.125f, 0 };
    GemmArgs gk = { 1, 1, bk, nullptr, 1.0f,   1 };
    GemmArgs gv = { 2, 2, bv, nullptr, 1.0f,   2 };
    gemm_fp16<<<dim3(DD / 128, MM / 128, 3), 256, GSMEM_BYTES>>>(gq, gk, gv);

    // Attention (fp16 mma.sync, cp.async double buffer)
    attn_fp16<<<dim3(SS / 64, BB * HH), 128>>>();

    // Output projection -> d_out (fp32)
    GemmArgs go = { 3, 3, bo, out, 1.0f, 3 };
    gemm_fp16<<<dim3(DD / 128, MM / 128, 1), 256, GSMEM_BYTES>>>(go, go, go);
}

// round 13
// speedup vs baseline: 4.9836x; 1.0574x over previous
#include <cuda_runtime.h>
#include <cuda_fp16.h>
#include <math.h>
#include <stdint.h>

// Problem constants
#define BB   4
#define SS   2048
#define DD   1024
#define HH   16
#define DKK  64
#define MM   (BB*SS)          // 8192 rows

// ---------------------------------------------------------------------------
// Pre-converted gmem planes
//  g_ahl[z] : inputs as interleaved {hi,lo} fp16 pairs (uint2/2 elems) [M][K/2]
//  g_wh[z]  : weights 1-term fp16 pairs, PERMUTED pair layout [N][K/2] u32
//  g_q16/k16: projected Q,K fp16 [B,H,S,DK/2] u32 pairs, PERMUTED
//  g_v16    : projected V fp16 [B,H,DK,S] halves, key-pairs PERMUTED
//  g_xhl    : attention out X as {hi,lo} pairs [M][D/2] (NOT permuted)
// Permuted pair layout (PPL): within each 8-pair (16-elem) chunk, position
//  2j holds logical pair j, position 2j+1 holds logical pair j+4. Then the
//  mma fragment {pair q, pair q+4} is ONE aligned 8-byte load at pos 2q.
// ---------------------------------------------------------------------------
__device__ __align__(16) uint2    g_ahl[3][(size_t)MM * (DD / 2)];
__device__ __align__(16) uint32_t g_wh[4][(size_t)DD * (DD / 2)];
__device__ __align__(16) uint32_t g_q16[(size_t)BB * HH * SS * (DKK / 2)];
__device__ __align__(16) uint32_t g_k16[(size_t)BB * HH * SS * (DKK / 2)];
__device__ __align__(16) uint32_t g_v16[(size_t)BB * HH * DKK * (SS / 2)];
__device__ __align__(16) uint2    g_xhl[(size_t)MM * (DD / 2)];

// ---------------------------------------------------------------------------
// helpers
// ---------------------------------------------------------------------------
__device__ __forceinline__ uint32_t smem_u32(const void* p) {
    uint32_t a;
    asm("{ .reg .u64 t; cvta.to.shared.u64 t, %1; cvt.u32.u64 %0, t; }"
        : "=r"(a) : "l"(p));
    return a;
}
__device__ __forceinline__ uint32_t pack2h(float x, float y) {
    __half2 h = __floats2half2_rn(x, y);
    return *reinterpret_cast<uint32_t*>(&h);
}
__device__ __forceinline__ void split2h(float x, float y, uint32_t& h, uint32_t& l) {
    __half hx = __float2half_rn(x);
    __half hy = __float2half_rn(y);
    __half lx = __float2half_rn(x - __half2float(hx));
    __half ly = __float2half_rn(y - __half2float(hy));
    __half2 hh = __halves2half2(hx, hy);
    __half2 ll = __halves2half2(lx, ly);
    h = *reinterpret_cast<uint32_t*>(&hh);
    l = *reinterpret_cast<uint32_t*>(&ll);
}
__device__ __forceinline__ float ex2(float x) {
    float y;
    asm("ex2.approx.f32 %0, %1;" : "=f"(y) : "f"(x));
    return y;
}
// D(16x8,f32) += A(16x16,f16) * B(16x8,f16)
__device__ __forceinline__ void mma16h(float* d, const uint32_t* a, const uint32_t* b) {
    asm("mma.sync.aligned.m16n8k16.row.col.f32.f16.f16.f32 "
        "{%0,%1,%2,%3}, {%4,%5,%6,%7}, {%8,%9}, {%0,%1,%2,%3};"
        : "+f"(d[0]), "+f"(d[1]), "+f"(d[2]), "+f"(d[3])
        : "r"(a[0]), "r"(a[1]), "r"(a[2]), "r"(a[3]),
          "r"(b[0]), "r"(b[1]));
}
__device__ __forceinline__ void cpa16(uint32_t dst, const void* src) {
    asm volatile("cp.async.cg.shared.global [%0], [%1], 16;"
                 :: "r"(dst), "l"(src) : "memory");
}
#define CP_COMMIT() asm volatile("cp.async.commit_group;" ::: "memory")

// ---------------------------------------------------------------------------
// convert kernels
// ---------------------------------------------------------------------------
__global__ __launch_bounds__(256) void cvt_in(const float* __restrict__ q,
                                              const float* __restrict__ k,
                                              const float* __restrict__ v)
{
    const float* src = (blockIdx.z == 0) ? q : ((blockIdx.z == 1) ? k : v);
    uint4* dst = (uint4*)g_ahl[blockIdx.z];
    size_t i = (size_t)blockIdx.x * 256 + threadIdx.x;   // float4 index
    float4 f = ((const float4*)src)[i];
    uint32_t h0, l0, h1, l1;
    split2h(f.x, f.y, h0, l0);
    split2h(f.z, f.w, h1, l1);
    dst[i] = make_uint4(h0, l0, h1, l1);
}

// weights -> 1-term fp16 pairs in PPL (per 16-elem chunk)
__global__ __launch_bounds__(256) void cvt_w(const float* __restrict__ wq,
                                             const float* __restrict__ wk,
                                             const float* __restrict__ wv,
                                             const float* __restrict__ wo)
{
    const float* src = (blockIdx.z == 0) ? wq :
                       (blockIdx.z == 1) ? wk :
                       (blockIdx.z == 2) ? wv : wo;
    uint4* dst = (uint4*)g_wh[blockIdx.z];
    size_t ci = (size_t)blockIdx.x * 256 + threadIdx.x;  // 16-elem chunk index
    const float4* s4 = (const float4*)src + ci * 4;
    float4 f0 = s4[0], f1 = s4[1], f2 = s4[2], f3 = s4[3];
    // positions: [L0, L4, L1, L5, L2, L6, L3, L7]
    dst[ci * 2]     = make_uint4(pack2h(f0.x, f0.y), pack2h(f2.x, f2.y),
                                 pack2h(f0.z, f0.w), pack2h(f2.z, f2.w));
    dst[ci * 2 + 1] = make_uint4(pack2h(f1.x, f1.y), pack2h(f3.x, f3.y),
                                 pack2h(f1.z, f1.w), pack2h(f3.z, f3.w));
}

// ---------------------------------------------------------------------------
// fp16 2-mma SGEMM with cp.async double buffer:
//   Y = (A @ W^T + bias) * alpha
// Block 128x128, BK=32, 256 threads (8 warps), warp tile 64x32.
// A: {hi,lo} uint2 pairs (stride 20 u2, LDS.64 frags).
// W: PPL 1-term fp16 (stride 24 u32, rows hold 16 u32, LDS.64 frags).
// y_sel: 0 -> g_q16 (PPL); 1 -> g_k16 (PPL); 2 -> g_v16 (PPL keys);
//        3 -> Yout fp32 [M,N]
// ---------------------------------------------------------------------------
#define AST2 20                       // A row stride in uint2
#define BST1 24                       // B row stride in uint32 (rows = 16 u32)
#define A_STAGE_U32 (128 * AST2 * 2)  // 5120 u32
#define B_STAGE_U32 (128 * BST1)      // 3072 u32
#define GSMEM_BYTES ((2 * A_STAGE_U32 + 2 * B_STAGE_U32) * 4)   // 65536

struct GemmArgs {
    int a_sel;            // 0..2 -> g_ahl[z], 3 -> g_xhl
    int w_sel;            // 0..3 -> g_wh[z]
    const float* bias;
    float* Yout;          // used when y_sel == 3
    float alpha;
    int y_sel;
};

__global__ __launch_bounds__(256, 2) void gemm_fp16(GemmArgs ga, GemmArgs gb, GemmArgs gc)
{
    GemmArgs g = (blockIdx.z == 0) ? ga : ((blockIdx.z == 1) ? gb : gc);
    const uint2*    gA = (g.a_sel < 3) ? g_ahl[g.a_sel] : g_xhl;
    const uint32_t* gW = g_wh[g.w_sel];

    extern __shared__ uint32_t sp[];
    uint2*    As[2] = { (uint2*)sp, (uint2*)sp + 128 * AST2 };
    uint32_t* Bs[2] = { sp + 2 * A_STAGE_U32,
                        sp + 2 * A_STAGE_U32 + B_STAGE_U32 };
    const uint32_t sbase = smem_u32(sp);

    const int tid  = threadIdx.x;
    const int lane = tid & 31;
    const int wrp  = tid >> 5;
    const int wy   = wrp & 1;          // m-warp (0..1), 64 rows
    const int wx   = wrp >> 1;         // n-warp (0..3), 32 cols
    const int r    = lane >> 2;        // 0..7
    const int q    = lane & 3;         // 0..3
    const int bm   = blockIdx.y * 128;
    const int bn   = blockIdx.x * 128;

    const int arow[4] = { (tid + 0)   >> 3, (tid + 256) >> 3,
                          (tid + 512) >> 3, (tid + 768) >> 3 };
    const int acol    = tid & 7;
    const int brow[2] = { (tid + 0) >> 2, (tid + 256) >> 2 };
    const int bcol    = tid & 3;

    float c[4][4][4];
    #pragma unroll
    for (int mt = 0; mt < 4; mt++)
        #pragma unroll
        for (int nt = 0; nt < 4; nt++)
            #pragma unroll
            for (int i = 0; i < 4; i++) c[mt][nt][i] = 0.0f;

    auto issue = [&](int it, int s) {
        uint32_t aB = sbase + s * (A_STAGE_U32 * 4);
        uint32_t bB = sbase + 2 * A_STAGE_U32 * 4 + s * (B_STAGE_U32 * 4);
        #pragma unroll
        for (int i = 0; i < 4; i++) {
            int row = arow[i];
            cpa16(aB + (uint32_t)(row * AST2 + acol * 2) * 8,
                  gA + (size_t)(bm + row) * (DD / 2) + it * 16 + acol * 2);
        }
        #pragma unroll
        for (int i = 0; i < 2; i++) {
            int row = brow[i];
            cpa16(bB + (uint32_t)(row * BST1 + bcol * 4) * 4,
                  gW + (size_t)(bn + row) * (DD / 2) + it * 16 + bcol * 4);
        }
        CP_COMMIT();
    };

    issue(0, 0);
    const int NT = DD / 32;           // 32 k-tiles

    for (int it = 0; it < NT; it++) {
        const int s = it & 1;
        if (it + 1 < NT) issue(it + 1, (it + 1) & 1);
        if (it + 1 < NT) { asm volatile("cp.async.wait_group 1;" ::: "memory"); }
        else             { asm volatile("cp.async.wait_group 0;" ::: "memory"); }
        __syncthreads();

        const uint2*    Au = As[s];
        const uint32_t* Bu = Bs[s];
        #pragma unroll
        for (int ks = 0; ks < 2; ks++) {
            const int koff = ks * 8;
            uint32_t bh[4][2];
            #pragma unroll
            for (int nt = 0; nt < 4; nt++) {
                uint2 bb = *(const uint2*)&Bu[(wx * 32 + nt * 8 + r) * BST1 + koff + 2 * q];
                bh[nt][0] = bb.x;
                bh[nt][1] = bb.y;
            }
            #pragma unroll
            for (int mt = 0; mt < 4; mt++) {
                int i0 = (wy * 64 + mt * 16 + r) * AST2 + koff + q;
                int i1 = i0 + 8 * AST2;
                uint2 u0 = Au[i0];
                uint2 u1 = Au[i1];
                uint2 u2 = Au[i0 + 4];
                uint2 u3 = Au[i1 + 4];
                uint32_t ah[4] = {u0.x, u1.x, u2.x, u3.x};
                uint32_t al[4] = {u0.y, u1.y, u2.y, u3.y};
                #pragma unroll
                for (int nt = 0; nt < 4; nt++) {
                    mma16h(c[mt][nt], al, bh[nt]);
                    mma16h(c[mt][nt], ah, bh[nt]);
                }
            }
        }
        __syncthreads();
    }

    // Epilogue
    #pragma unroll
    for (int mt = 0; mt < 4; mt++) {
        #pragma unroll
        for (int nt = 0; nt < 4; nt++) {
            int n = bn + wx * 32 + nt * 8 + 2 * q;
            float b0 = g.bias[n], b1 = g.bias[n + 1];
            #pragma unroll
            for (int half = 0; half < 2; half++) {
                int m = bm + wy * 64 + mt * 16 + r + half * 8;
                float vx = (c[mt][nt][2 * half]     + b0) * g.alpha;
                float vy = (c[mt][nt][2 * half + 1] + b1) * g.alpha;
                if (g.y_sel == 3) {
                    *(float2*)&g.Yout[(size_t)m * DD + n] = make_float2(vx, vy);
                } else {
                    int b  = m >> 11;         // / SS
                    int s  = m & (SS - 1);
                    int h  = n >> 6;          // / DK
                    int dk = n & 63;
                    if (g.y_sel <= 1) {
                        // permuted pair index within the 32-pair row
                        int pl  = dk >> 1;
                        int w_  = pl & 7;
                        int pos = (w_ < 4) ? 2 * w_ : 2 * (w_ - 4) + 1;
                        int pp  = ((pl >> 3) << 3) + pos;
                        uint32_t* dst = (g.y_sel == 0) ? g_q16 : g_k16;
                        dst[(((size_t)(b * HH + h)) * SS + s) * (DKK / 2) + pp]
                            = pack2h(vx, vy);
                    } else {
                        // V [dk][s], key position permuted within 16-key chunks
                        int pl  = s >> 1, lo = s & 1;
                        int w_  = pl & 7;
                        int pos = (w_ < 4) ? 2 * w_ : 2 * (w_ - 4) + 1;
                        int sp_ = ((pl >> 3) << 4) + (pos << 1) + lo;
                        __half* dst = (__half*)g_v16 +
                            ((size_t)(b * HH + h) * DKK + dk) * SS + sp_;
                        dst[0]  = __float2half_rn(vx);
                        dst[SS] = __float2half_rn(vy);
                    }
                }
            }
        }
    }
}

// ---------------------------------------------------------------------------
// fp16 flash attention, KT=128 key tiles, cp.async double buffer.
// One block = one (b,h) x 64-query tile; 128 threads (4 warps).
// Scores kept in log2 domain (log2e folded into Q projection) -> ex2 softmax.
// K plane: 128 keys x 32 u32 data, stride 36 (>= 32: NO row overlap).
// V plane: 64 dk x 64 u32 data, stride 72.
// ---------------------------------------------------------------------------
#define KST 36
#define VST 72
#define K_PLANE (128 * KST)            // 4608 u32
#define V_PLANE (64 * VST)             // 4608 u32
#define KV_STAGE (K_PLANE + V_PLANE)   // 9216 u32
#define ASMEM_BYTES (2 * KV_STAGE * 4) // 73728

__global__ __launch_bounds__(128, 3) void attn_fp16()
{
    extern __shared__ uint32_t SH[];

    const int tid  = threadIdx.x;
    const int lane = tid & 31;
    const int w    = tid >> 5;           // warp 0..3 -> query rows w*16..
    const int r    = lane >> 2;          // 0..7
    const int q    = lane & 3;           // 0..3
    const int qt   = blockIdx.x;         // 0..31
    const int bh   = blockIdx.y;         // 0..63
    const int h    = bh & (HH - 1);
    const int bb   = bh >> 4;

    const uint32_t* Qb = g_q16 + ((size_t)bh * SS + qt * 64 + w * 16) * (DKK / 2);
    const uint32_t* Kb = g_k16 + (size_t)bh * SS * (DKK / 2);
    const uint32_t* Vb = g_v16 + (size_t)bh * DKK * (SS / 2);
    const uint32_t sbase = smem_u32(SH);

    // Preload Q fragments (PPL: one uint2 = {pair q, pair q+4})
    uint32_t qh[4][4];
    #pragma unroll
    for (int kt = 0; kt < 4; kt++) {
        uint2 a0 = *(const uint2*)&Qb[(size_t)r * 32 + kt * 8 + 2 * q];
        uint2 a1 = *(const uint2*)&Qb[(size_t)(r + 8) * 32 + kt * 8 + 2 * q];
        qh[kt][0] = a0.x; qh[kt][2] = a0.y;
        qh[kt][1] = a1.x; qh[kt][3] = a1.y;
    }

    auto issue = [&](int t, int s) {
        uint32_t kB = sbase + s * (KV_STAGE * 4);
        uint32_t vB = kB + K_PLANE * 4;
        #pragma unroll
        for (int i = 0; i < 8; i++) {
            int c  = tid + i * 128;
            int kr = c >> 3, kc = c & 7;
            cpa16(kB + (uint32_t)(kr * KST + kc * 4) * 4,
                  Kb + (size_t)(t * 128 + kr) * 32 + kc * 4);
            int vr = c >> 4, vc = c & 15;
            cpa16(vB + (uint32_t)(vr * VST + vc * 4) * 4,
                  Vb + (size_t)vr * (SS / 2) + t * 64 + vc * 4);
        }
        CP_COMMIT();
    };

    float o[8][4];
    #pragma unroll
    for (int dt = 0; dt < 8; dt++)
        #pragma unroll
        for (int i = 0; i < 4; i++) o[dt][i] = 0.0f;
    float mrow[2] = {-1e30f, -1e30f};
    float lrow[2] = {0.0f, 0.0f};

    issue(0, 0);
    const int NT = SS / 128;             // 16 tiles

    for (int t = 0; t < NT; t++) {
        const int s = t & 1;
        if (t + 1 < NT) issue(t + 1, (t + 1) & 1);
        if (t + 1 < NT) { asm volatile("cp.async.wait_group 1;" ::: "memory"); }
        else            { asm volatile("cp.async.wait_group 0;" ::: "memory"); }
        __syncthreads();

        const uint32_t* K0 = SH + s * KV_STAGE;
        const uint32_t* V0 = K0 + K_PLANE;

        // ---- S = Q K^T (16 x 128 per warp) ----
        float sc[16][4];
        #pragma unroll
        for (int nt = 0; nt < 16; nt++)
            #pragma unroll
            for (int i = 0; i < 4; i++) sc[nt][i] = 0.0f;

        #pragma unroll
        for (int kt = 0; kt < 4; kt++) {
            const int koff = kt * 8;
            #pragma unroll
            for (int nt = 0; nt < 16; nt++) {
                uint2 kk = *(const uint2*)&K0[(nt * 8 + r) * KST + koff + 2 * q];
                uint32_t kf[2] = { kk.x, kk.y };
                mma16h(sc[nt], qh[kt], kf);
            }
        }

        // ---- online softmax in log2 domain (rows r / r+8) ----
        #pragma unroll
        for (int half = 0; half < 2; half++) {
            float rm = -1e30f;
            #pragma unroll
            for (int nt = 0; nt < 16; nt++)
                rm = fmaxf(rm, fmaxf(sc[nt][2 * half], sc[nt][2 * half + 1]));
            rm = fmaxf(rm, __shfl_xor_sync(0xffffffffu, rm, 1));
            rm = fmaxf(rm, __shfl_xor_sync(0xffffffffu, rm, 2));
            float mnew  = fmaxf(mrow[half], rm);
            float scale = ex2(mrow[half] - mnew);
            float rs = 0.0f;
            #pragma unroll
            for (int nt = 0; nt < 16; nt++) {
                sc[nt][2 * half]     = ex2(sc[nt][2 * half] - mnew);
                sc[nt][2 * half + 1] = ex2(sc[nt][2 * half + 1] - mnew);
                rs += sc[nt][2 * half] + sc[nt][2 * half + 1];
            }
            rs += __shfl_xor_sync(0xffffffffu, rs, 1);
            rs += __shfl_xor_sync(0xffffffffu, rs, 2);
            lrow[half] = lrow[half] * scale + rs;
            mrow[half] = mnew;
            #pragma unroll
            for (int dt = 0; dt < 8; dt++) {
                o[dt][2 * half]     *= scale;
                o[dt][2 * half + 1] *= scale;
            }
        }

        // ---- O += P V (P packed straight from score accumulators) ----
        #pragma unroll
        for (int kt = 0; kt < 8; kt++) {
            uint32_t ph[4];
            ph[0] = pack2h(sc[2 * kt][0],     sc[2 * kt][1]);
            ph[1] = pack2h(sc[2 * kt][2],     sc[2 * kt][3]);
            ph[2] = pack2h(sc[2 * kt + 1][0], sc[2 * kt + 1][1]);
            ph[3] = pack2h(sc[2 * kt + 1][2], sc[2 * kt + 1][3]);
            #pragma unroll
            for (int dt = 0; dt < 8; dt++) {
                uint2 vv = *(const uint2*)&V0[(dt * 8 + r) * VST + kt * 8 + 2 * q];
                uint32_t vh[2] = { vv.x, vv.y };
                mma16h(o[dt], ph, vh);
            }
        }
        __syncthreads();
    }

    // Epilogue: X as {hi,lo} uint2 pairs (A-plane layout, NOT permuted)
    float inv0 = 1.0f / lrow[0];
    float inv1 = 1.0f / lrow[1];
    uint2* Xb = g_xhl + ((size_t)bb * SS + qt * 64 + w * 16) * (DD / 2) + h * 32;
    #pragma unroll
    for (int dt = 0; dt < 8; dt++) {
        int cp = (dt * 8 + 2 * q) >> 1;   // uint2 index within head
        uint32_t hh, ll;
        split2h(o[dt][0] * inv0, o[dt][1] * inv0, hh, ll);
        Xb[(size_t)r * (DD / 2) + cp] = make_uint2(hh, ll);
        split2h(o[dt][2] * inv1, o[dt][3] * inv1, hh, ll);
        Xb[(size_t)(r + 8) * (DD / 2) + cp] = make_uint2(hh, ll);
    }
}

// ---------------------------------------------------------------------------
extern "C" void kernel_launch(void* const* d_in, const int* in_sizes, int n_in,
                              void* d_out, int out_size)
{
    const float* query = (const float*)d_in[0];
    const float* key_  = (const float*)d_in[1];
    const float* value = (const float*)d_in[2];
    const float* Wq    = (const float*)d_in[3];
    const float* bq    = (const float*)d_in[4];
    const float* Wk    = (const float*)d_in[5];
    const float* bk    = (const float*)d_in[6];
    const float* Wv    = (const float*)d_in[7];
    const float* bv    = (const float*)d_in[8];
    const float* Wo    = (const float*)d_in[9];
    const float* bo    = (const float*)d_in[10];
    float* out = (float*)d_out;

    cudaFuncSetAttribute(gemm_fp16,
                         cudaFuncAttributeMaxDynamicSharedMemorySize, GSMEM_BYTES);
    cudaFuncSetAttribute(attn_fp16,
                         cudaFuncAttributeMaxDynamicSharedMemorySize, ASMEM_BYTES);

    // One-time (per launch) conversions
    cvt_in<<<dim3(MM * DD / 4 / 256, 1, 3), 256>>>(query, key_, value);
    cvt_w<<<dim3(DD * DD / 16 / 256, 1, 4), 256>>>(Wq, Wk, Wv, Wo);

    // Fused Q/K/V projections.
    // Q alpha = (1/8) * log2(e): scores come out in log2 domain.
    GemmArgs gq = { 0, 0, bq, nullptr, 0.18033688f, 0 };
    GemmArgs gk = { 1, 1, bk, nullptr, 1.0f,        1 };
    GemmArgs gv = { 2, 2, bv, nullptr, 1.0f,        2 };
    gemm_fp16<<<dim3(DD / 128, MM / 128, 3), 256, GSMEM_BYTES>>>(gq, gk, gv);

    // Attention (fp16 mma.sync, KT=128, ex2 softmax)
    attn_fp16<<<dim3(SS / 64, BB * HH), 128, ASMEM_BYTES>>>();

    // Output projection -> d_out (fp32)
    GemmArgs go = { 3, 3, bo, out, 1.0f, 3 };
    gemm_fp16<<<dim3(DD / 128, MM / 128, 1), 256, GSMEM_BYTES>>>(go, go, go);
}

// round 14
// speedup vs baseline: 5.4232x; 1.0882x over previous
#include <cuda_runtime.h>
#include <cuda_fp16.h>
#include <math.h>
#include <stdint.h>

// Problem constants
#define BB   4
#define SS   2048
#define DD   1024
#define HH   16
#define DKK  64
#define MM   (BB*SS)          // 8192 rows

// ---------------------------------------------------------------------------
// Pre-converted gmem planes
//  g_ahl[z] : inputs as interleaved {hi,lo} fp16 pairs (uint2/2 elems) [M][K/2]
//  g_wh[z]  : weights 1-term fp16 pairs, PERMUTED pair layout [N][K/2] u32
//  g_q16/k16: projected Q,K fp16 [B,H,S,DK/2] u32 pairs, PERMUTED
//  g_v16    : projected V fp16 [B,H,DK,S] halves, key-pairs PERMUTED
//  g_xhl    : attention out X as {hi,lo} pairs [M][D/2] (NOT permuted)
// Permuted pair layout (PPL): within each 8-pair (16-elem) chunk, position
//  2j holds logical pair j, position 2j+1 holds logical pair j+4. Then the
//  mma fragment {pair q, pair q+4} is ONE aligned 8-byte load at pos 2q.
// ---------------------------------------------------------------------------
__device__ __align__(16) uint2    g_ahl[3][(size_t)MM * (DD / 2)];
__device__ __align__(16) uint32_t g_wh[4][(size_t)DD * (DD / 2)];
__device__ __align__(16) uint32_t g_q16[(size_t)BB * HH * SS * (DKK / 2)];
__device__ __align__(16) uint32_t g_k16[(size_t)BB * HH * SS * (DKK / 2)];
__device__ __align__(16) uint32_t g_v16[(size_t)BB * HH * DKK * (SS / 2)];
__device__ __align__(16) uint2    g_xhl[(size_t)MM * (DD / 2)];

// ---------------------------------------------------------------------------
// helpers
// ---------------------------------------------------------------------------
__device__ __forceinline__ uint32_t smem_u32(const void* p) {
    uint32_t a;
    asm("{ .reg .u64 t; cvta.to.shared.u64 t, %1; cvt.u32.u64 %0, t; }"
        : "=r"(a) : "l"(p));
    return a;
}
__device__ __forceinline__ uint32_t pack2h(float x, float y) {
    __half2 h = __floats2half2_rn(x, y);
    return *reinterpret_cast<uint32_t*>(&h);
}
__device__ __forceinline__ void split2h(float x, float y, uint32_t& h, uint32_t& l) {
    __half hx = __float2half_rn(x);
    __half hy = __float2half_rn(y);
    __half lx = __float2half_rn(x - __half2float(hx));
    __half ly = __float2half_rn(y - __half2float(hy));
    __half2 hh = __halves2half2(hx, hy);
    __half2 ll = __halves2half2(lx, ly);
    h = *reinterpret_cast<uint32_t*>(&hh);
    l = *reinterpret_cast<uint32_t*>(&ll);
}
__device__ __forceinline__ float ex2(float x) {
    float y;
    asm("ex2.approx.f32 %0, %1;" : "=f"(y) : "f"(x));
    return y;
}
// D(16x8,f32) += A(16x16,f16) * B(16x8,f16)
__device__ __forceinline__ void mma16h(float* d, const uint32_t* a, const uint32_t* b) {
    asm("mma.sync.aligned.m16n8k16.row.col.f32.f16.f16.f32 "
        "{%0,%1,%2,%3}, {%4,%5,%6,%7}, {%8,%9}, {%0,%1,%2,%3};"
        : "+f"(d[0]), "+f"(d[1]), "+f"(d[2]), "+f"(d[3])
        : "r"(a[0]), "r"(a[1]), "r"(a[2]), "r"(a[3]),
          "r"(b[0]), "r"(b[1]));
}
__device__ __forceinline__ void cpa16(uint32_t dst, const void* src) {
    asm volatile("cp.async.cg.shared.global [%0], [%1], 16;"
                 :: "r"(dst), "l"(src) : "memory");
}
#define CP_COMMIT() asm volatile("cp.async.commit_group;" ::: "memory")

// ---------------------------------------------------------------------------
// convert kernels
// ---------------------------------------------------------------------------
__global__ __launch_bounds__(256) void cvt_in(const float* __restrict__ q,
                                              const float* __restrict__ k,
                                              const float* __restrict__ v)
{
    const float* src = (blockIdx.z == 0) ? q : ((blockIdx.z == 1) ? k : v);
    uint4* dst = (uint4*)g_ahl[blockIdx.z];
    size_t i = (size_t)blockIdx.x * 256 + threadIdx.x;   // float4 index
    float4 f = ((const float4*)src)[i];
    uint32_t h0, l0, h1, l1;
    split2h(f.x, f.y, h0, l0);
    split2h(f.z, f.w, h1, l1);
    dst[i] = make_uint4(h0, l0, h1, l1);
}

// weights -> 1-term fp16 pairs in PPL (per 16-elem chunk)
__global__ __launch_bounds__(256) void cvt_w(const float* __restrict__ wq,
                                             const float* __restrict__ wk,
                                             const float* __restrict__ wv,
                                             const float* __restrict__ wo)
{
    const float* src = (blockIdx.z == 0) ? wq :
                       (blockIdx.z == 1) ? wk :
                       (blockIdx.z == 2) ? wv : wo;
    uint4* dst = (uint4*)g_wh[blockIdx.z];
    size_t ci = (size_t)blockIdx.x * 256 + threadIdx.x;  // 16-elem chunk index
    const float4* s4 = (const float4*)src + ci * 4;
    float4 f0 = s4[0], f1 = s4[1], f2 = s4[2], f3 = s4[3];
    // positions: [L0, L4, L1, L5, L2, L6, L3, L7]
    dst[ci * 2]     = make_uint4(pack2h(f0.x, f0.y), pack2h(f2.x, f2.y),
                                 pack2h(f0.z, f0.w), pack2h(f2.z, f2.w));
    dst[ci * 2 + 1] = make_uint4(pack2h(f1.x, f1.y), pack2h(f3.x, f3.y),
                                 pack2h(f1.z, f1.w), pack2h(f3.z, f3.w));
}

// ---------------------------------------------------------------------------
// fp16 2-mma SGEMM with cp.async double buffer:
//   Y = (A @ W^T + bias) * alpha
// Block 128x128, BK=32, 256 threads (8 warps), warp tile 64x32.
// A: {hi,lo} uint2 pairs (stride 20 u2, LDS.64 frags, (4r+q)%16 bijective).
// W: PPL 1-term fp16 (stride 24 u32, rows hold 16 u32, LDS.64 frags).
// y_sel: 0 -> g_q16 (PPL); 1 -> g_k16 (PPL); 2 -> g_v16 (PPL keys);
//        3 -> Yout fp32 [M,N]
// ---------------------------------------------------------------------------
#define AST2 20                       // A row stride in uint2
#define BST1 24                       // B row stride in uint32 (rows = 16 u32)
#define A_STAGE_U32 (128 * AST2 * 2)  // 5120 u32
#define B_STAGE_U32 (128 * BST1)      // 3072 u32
#define GSMEM_BYTES ((2 * A_STAGE_U32 + 2 * B_STAGE_U32) * 4)   // 65536

struct GemmArgs {
    int a_sel;            // 0..2 -> g_ahl[z], 3 -> g_xhl
    int w_sel;            // 0..3 -> g_wh[z]
    const float* bias;
    float* Yout;          // used when y_sel == 3
    float alpha;
    int y_sel;
};

__global__ __launch_bounds__(256, 2) void gemm_fp16(GemmArgs ga, GemmArgs gb, GemmArgs gc)
{
    GemmArgs g = (blockIdx.z == 0) ? ga : ((blockIdx.z == 1) ? gb : gc);
    const uint2*    gA = (g.a_sel < 3) ? g_ahl[g.a_sel] : g_xhl;
    const uint32_t* gW = g_wh[g.w_sel];

    extern __shared__ uint32_t sp[];
    uint2*    As[2] = { (uint2*)sp, (uint2*)sp + 128 * AST2 };
    uint32_t* Bs[2] = { sp + 2 * A_STAGE_U32,
                        sp + 2 * A_STAGE_U32 + B_STAGE_U32 };
    const uint32_t sbase = smem_u32(sp);

    const int tid  = threadIdx.x;
    const int lane = tid & 31;
    const int wrp  = tid >> 5;
    const int wy   = wrp & 1;          // m-warp (0..1), 64 rows
    const int wx   = wrp >> 1;         // n-warp (0..3), 32 cols
    const int r    = lane >> 2;        // 0..7
    const int q    = lane & 3;         // 0..3
    const int bm   = blockIdx.y * 128;
    const int bn   = blockIdx.x * 128;

    const int arow[4] = { (tid + 0)   >> 3, (tid + 256) >> 3,
                          (tid + 512) >> 3, (tid + 768) >> 3 };
    const int acol    = tid & 7;
    const int brow[2] = { (tid + 0) >> 2, (tid + 256) >> 2 };
    const int bcol    = tid & 3;

    float c[4][4][4];
    #pragma unroll
    for (int mt = 0; mt < 4; mt++)
        #pragma unroll
        for (int nt = 0; nt < 4; nt++)
            #pragma unroll
            for (int i = 0; i < 4; i++) c[mt][nt][i] = 0.0f;

    auto issue = [&](int it, int s) {
        uint32_t aB = sbase + s * (A_STAGE_U32 * 4);
        uint32_t bB = sbase + 2 * A_STAGE_U32 * 4 + s * (B_STAGE_U32 * 4);
        #pragma unroll
        for (int i = 0; i < 4; i++) {
            int row = arow[i];
            cpa16(aB + (uint32_t)(row * AST2 + acol * 2) * 8,
                  gA + (size_t)(bm + row) * (DD / 2) + it * 16 + acol * 2);
        }
        #pragma unroll
        for (int i = 0; i < 2; i++) {
            int row = brow[i];
            cpa16(bB + (uint32_t)(row * BST1 + bcol * 4) * 4,
                  gW + (size_t)(bn + row) * (DD / 2) + it * 16 + bcol * 4);
        }
        CP_COMMIT();
    };

    issue(0, 0);
    const int NT = DD / 32;           // 32 k-tiles

    for (int it = 0; it < NT; it++) {
        const int s = it & 1;
        if (it + 1 < NT) issue(it + 1, (it + 1) & 1);
        if (it + 1 < NT) { asm volatile("cp.async.wait_group 1;" ::: "memory"); }
        else             { asm volatile("cp.async.wait_group 0;" ::: "memory"); }
        __syncthreads();

        const uint2*    Au = As[s];
        const uint32_t* Bu = Bs[s];
        #pragma unroll
        for (int ks = 0; ks < 2; ks++) {
            const int koff = ks * 8;
            uint32_t bh[4][2];
            #pragma unroll
            for (int nt = 0; nt < 4; nt++) {
                uint2 bb = *(const uint2*)&Bu[(wx * 32 + nt * 8 + r) * BST1 + koff + 2 * q];
                bh[nt][0] = bb.x;
                bh[nt][1] = bb.y;
            }
            #pragma unroll
            for (int mt = 0; mt < 4; mt++) {
                int i0 = (wy * 64 + mt * 16 + r) * AST2 + koff + q;
                int i1 = i0 + 8 * AST2;
                uint2 u0 = Au[i0];
                uint2 u1 = Au[i1];
                uint2 u2 = Au[i0 + 4];
                uint2 u3 = Au[i1 + 4];
                uint32_t ah[4] = {u0.x, u1.x, u2.x, u3.x};
                uint32_t al[4] = {u0.y, u1.y, u2.y, u3.y};
                #pragma unroll
                for (int nt = 0; nt < 4; nt++) {
                    mma16h(c[mt][nt], al, bh[nt]);
                    mma16h(c[mt][nt], ah, bh[nt]);
                }
            }
        }
        __syncthreads();
    }

    // Epilogue
    #pragma unroll
    for (int mt = 0; mt < 4; mt++) {
        #pragma unroll
        for (int nt = 0; nt < 4; nt++) {
            int n = bn + wx * 32 + nt * 8 + 2 * q;
            float b0 = g.bias[n], b1 = g.bias[n + 1];
            #pragma unroll
            for (int half = 0; half < 2; half++) {
                int m = bm + wy * 64 + mt * 16 + r + half * 8;
                float vx = (c[mt][nt][2 * half]     + b0) * g.alpha;
                float vy = (c[mt][nt][2 * half + 1] + b1) * g.alpha;
                if (g.y_sel == 3) {
                    *(float2*)&g.Yout[(size_t)m * DD + n] = make_float2(vx, vy);
                } else {
                    int b  = m >> 11;         // / SS
                    int s  = m & (SS - 1);
                    int h  = n >> 6;          // / DK
                    int dk = n & 63;
                    if (g.y_sel <= 1) {
                        // permuted pair index within the 32-pair row
                        int pl  = dk >> 1;
                        int w_  = pl & 7;
                        int pos = (w_ < 4) ? 2 * w_ : 2 * (w_ - 4) + 1;
                        int pp  = ((pl >> 3) << 3) + pos;
                        uint32_t* dst = (g.y_sel == 0) ? g_q16 : g_k16;
                        dst[(((size_t)(b * HH + h)) * SS + s) * (DKK / 2) + pp]
                            = pack2h(vx, vy);
                    } else {
                        // V [dk][s], key position permuted within 16-key chunks
                        int pl  = s >> 1, lo = s & 1;
                        int w_  = pl & 7;
                        int pos = (w_ < 4) ? 2 * w_ : 2 * (w_ - 4) + 1;
                        int sp_ = ((pl >> 3) << 4) + (pos << 1) + lo;
                        __half* dst = (__half*)g_v16 +
                            ((size_t)(b * HH + h) * DKK + dk) * SS + sp_;
                        dst[0]  = __float2half_rn(vx);
                        dst[SS] = __float2half_rn(vy);
                    }
                }
            }
        }
    }
}

// ---------------------------------------------------------------------------
// fp16 flash attention, KT=64 key tiles, cp.async double buffer.
// One block = one (b,h) x 64-query tile; 128 threads (4 warps).
// Scores kept in log2 domain (log2e folded into Q projection) -> ex2 softmax.
// K plane: 64 keys x 32 u32 data, stride 40 (40%32==8 -> LDS.64 conflict-free).
// V plane: 64 dk x 32 u32 data (64 keys), stride 40.
// ---------------------------------------------------------------------------
#define KST 40
#define K_PLANE (64 * KST)             // 2560 u32
#define KV_STAGE (2 * K_PLANE)         // 5120 u32
#define ASMEM_BYTES (2 * KV_STAGE * 4) // 40960

__global__ __launch_bounds__(128, 4) void attn_fp16()
{
    extern __shared__ uint32_t SH[];

    const int tid  = threadIdx.x;
    const int lane = tid & 31;
    const int w    = tid >> 5;           // warp 0..3 -> query rows w*16..
    const int r    = lane >> 2;          // 0..7
    const int q    = lane & 3;           // 0..3
    const int qt   = blockIdx.x;         // 0..31
    const int bh   = blockIdx.y;         // 0..63
    const int h    = bh & (HH - 1);
    const int bb   = bh >> 4;

    const uint32_t* Qb = g_q16 + ((size_t)bh * SS + qt * 64 + w * 16) * (DKK / 2);
    const uint32_t* Kb = g_k16 + (size_t)bh * SS * (DKK / 2);
    const uint32_t* Vb = g_v16 + (size_t)bh * DKK * (SS / 2);
    const uint32_t sbase = smem_u32(SH);

    // Preload Q fragments (PPL: one uint2 = {pair q, pair q+4})
    uint32_t qh[4][4];
    #pragma unroll
    for (int kt = 0; kt < 4; kt++) {
        uint2 a0 = *(const uint2*)&Qb[(size_t)r * 32 + kt * 8 + 2 * q];
        uint2 a1 = *(const uint2*)&Qb[(size_t)(r + 8) * 32 + kt * 8 + 2 * q];
        qh[kt][0] = a0.x; qh[kt][2] = a0.y;
        qh[kt][1] = a1.x; qh[kt][3] = a1.y;
    }

    // staging: 8 x 16B chunks per thread (4 K rows-halves + 4 V)
    auto issue = [&](int t, int s) {
        uint32_t kB = sbase + s * (KV_STAGE * 4);
        uint32_t vB = kB + K_PLANE * 4;
        #pragma unroll
        for (int i = 0; i < 4; i++) {
            int c  = tid + i * 128;       // 0..511
            int rw = c >> 3, cc = c & 7;  // row 0..63, 16B chunk 0..7
            cpa16(kB + (uint32_t)(rw * KST + cc * 4) * 4,
                  Kb + (size_t)(t * 64 + rw) * 32 + cc * 4);
            cpa16(vB + (uint32_t)(rw * KST + cc * 4) * 4,
                  Vb + (size_t)rw * (SS / 2) + t * 32 + cc * 4);
        }
        CP_COMMIT();
    };

    float o[8][4];
    #pragma unroll
    for (int dt = 0; dt < 8; dt++)
        #pragma unroll
        for (int i = 0; i < 4; i++) o[dt][i] = 0.0f;
    float mrow[2] = {-1e30f, -1e30f};
    float lrow[2] = {0.0f, 0.0f};

    issue(0, 0);
    const int NT = SS / 64;              // 32 tiles

    for (int t = 0; t < NT; t++) {
        const int s = t & 1;
        if (t + 1 < NT) issue(t + 1, (t + 1) & 1);
        if (t + 1 < NT) { asm volatile("cp.async.wait_group 1;" ::: "memory"); }
        else            { asm volatile("cp.async.wait_group 0;" ::: "memory"); }
        __syncthreads();

        const uint32_t* K0 = SH + s * KV_STAGE;
        const uint32_t* V0 = K0 + K_PLANE;

        // ---- S = Q K^T (16 x 64 per warp) ----
        float sc[8][4];
        #pragma unroll
        for (int nt = 0; nt < 8; nt++)
            #pragma unroll
            for (int i = 0; i < 4; i++) sc[nt][i] = 0.0f;

        #pragma unroll
        for (int kt = 0; kt < 4; kt++) {
            const int koff = kt * 8;
            #pragma unroll
            for (int nt = 0; nt < 8; nt++) {
                uint2 kk = *(const uint2*)&K0[(nt * 8 + r) * KST + koff + 2 * q];
                uint32_t kf[2] = { kk.x, kk.y };
                mma16h(sc[nt], qh[kt], kf);
            }
        }

        // ---- online softmax in log2 domain (rows r / r+8) ----
        #pragma unroll
        for (int half = 0; half < 2; half++) {
            float rm = -1e30f;
            #pragma unroll
            for (int nt = 0; nt < 8; nt++)
                rm = fmaxf(rm, fmaxf(sc[nt][2 * half], sc[nt][2 * half + 1]));
            rm = fmaxf(rm, __shfl_xor_sync(0xffffffffu, rm, 1));
            rm = fmaxf(rm, __shfl_xor_sync(0xffffffffu, rm, 2));
            float mnew  = fmaxf(mrow[half], rm);
            float scale = ex2(mrow[half] - mnew);
            float rs = 0.0f;
            #pragma unroll
            for (int nt = 0; nt < 8; nt++) {
                sc[nt][2 * half]     = ex2(sc[nt][2 * half] - mnew);
                sc[nt][2 * half + 1] = ex2(sc[nt][2 * half + 1] - mnew);
                rs += sc[nt][2 * half] + sc[nt][2 * half + 1];
            }
            rs += __shfl_xor_sync(0xffffffffu, rs, 1);
            rs += __shfl_xor_sync(0xffffffffu, rs, 2);
            lrow[half] = lrow[half] * scale + rs;
            mrow[half] = mnew;
            #pragma unroll
            for (int dt = 0; dt < 8; dt++) {
                o[dt][2 * half]     *= scale;
                o[dt][2 * half + 1] *= scale;
            }
        }

        // ---- O += P V (P packed straight from score accumulators) ----
        #pragma unroll
        for (int kt = 0; kt < 4; kt++) {
            uint32_t ph[4];
            ph[0] = pack2h(sc[2 * kt][0],     sc[2 * kt][1]);
            ph[1] = pack2h(sc[2 * kt][2],     sc[2 * kt][3]);
            ph[2] = pack2h(sc[2 * kt + 1][0], sc[2 * kt + 1][1]);
            ph[3] = pack2h(sc[2 * kt + 1][2], sc[2 * kt + 1][3]);
            #pragma unroll
            for (int dt = 0; dt < 8; dt++) {
                uint2 vv = *(const uint2*)&V0[(dt * 8 + r) * KST + kt * 8 + 2 * q];
                uint32_t vh[2] = { vv.x, vv.y };
                mma16h(o[dt], ph, vh);
            }
        }
        __syncthreads();
    }

    // Epilogue: X as {hi,lo} uint2 pairs (A-plane layout, NOT permuted)
    float inv0 = 1.0f / lrow[0];
    float inv1 = 1.0f / lrow[1];
    uint2* Xb = g_xhl + ((size_t)bb * SS + qt * 64 + w * 16) * (DD / 2) + h * 32;
    #pragma unroll
    for (int dt = 0; dt < 8; dt++) {
        int cp = (dt * 8 + 2 * q) >> 1;   // uint2 index within head
        uint32_t hh, ll;
        split2h(o[dt][0] * inv0, o[dt][1] * inv0, hh, ll);
        Xb[(size_t)r * (DD / 2) + cp] = make_uint2(hh, ll);
        split2h(o[dt][2] * inv1, o[dt][3] * inv1, hh, ll);
        Xb[(size_t)(r + 8) * (DD / 2) + cp] = make_uint2(hh, ll);
    }
}

// ---------------------------------------------------------------------------
extern "C" void kernel_launch(void* const* d_in, const int* in_sizes, int n_in,
                              void* d_out, int out_size)
{
    const float* query = (const float*)d_in[0];
    const float* key_  = (const float*)d_in[1];
    const float* value = (const float*)d_in[2];
    const float* Wq    = (const float*)d_in[3];
    const float* bq    = (const float*)d_in[4];
    const float* Wk    = (const float*)d_in[5];
    const float* bk    = (const float*)d_in[6];
    const float* Wv    = (const float*)d_in[7];
    const float* bv    = (const float*)d_in[8];
    const float* Wo    = (const float*)d_in[9];
    const float* bo    = (const float*)d_in[10];
    float* out = (float*)d_out;

    cudaFuncSetAttribute(gemm_fp16,
                         cudaFuncAttributeMaxDynamicSharedMemorySize, GSMEM_BYTES);
    cudaFuncSetAttribute(attn_fp16,
                         cudaFuncAttributeMaxDynamicSharedMemorySize, ASMEM_BYTES);

    // One-time (per launch) conversions
    cvt_in<<<dim3(MM * DD / 4 / 256, 1, 3), 256>>>(query, key_, value);
    cvt_w<<<dim3(DD * DD / 16 / 256, 1, 4), 256>>>(Wq, Wk, Wv, Wo);

    // Fused Q/K/V projections.
    // Q alpha = (1/8) * log2(e): scores come out in log2 domain.
    GemmArgs gq = { 0, 0, bq, nullptr, 0.18033688f, 0 };
    GemmArgs gk = { 1, 1, bk, nullptr, 1.0f,        1 };
    GemmArgs gv = { 2, 2, bv, nullptr, 1.0f,        2 };
    gemm_fp16<<<dim3(DD / 128, MM / 128, 3), 256, GSMEM_BYTES>>>(gq, gk, gv);

    // Attention (fp16 mma.sync, KT=64, ex2 softmax, conflict-free LDS.64)
    attn_fp16<<<dim3(SS / 64, BB * HH), 128, ASMEM_BYTES>>>();

    // Output projection -> d_out (fp32)
    GemmArgs go = { 3, 3, bo, out, 1.0f, 3 };
    gemm_fp16<<<dim3(DD / 128, MM / 128, 1), 256, GSMEM_BYTES>>>(go, go, go);
}

// round 15
// speedup vs baseline: 5.4558x; 1.0060x over previous
#include <cuda_runtime.h>
#include <cuda_fp16.h>
#include <math.h>
#include <stdint.h>

// Problem constants
#define BB   4
#define SS   2048
#define DD   1024
#define HH   16
#define DKK  64
#define MM   (BB*SS)          // 8192 rows

// ---------------------------------------------------------------------------
// Pre-converted gmem planes
//  g_ahl[z] : inputs as {hi,lo} fp16 pair uint2s, PPL-ordered within each
//             16-elem chunk: [p0,p4,p1,p5,p2,p6,p3,p7]  -> A frag = 1 uint4
//  g_wh[z]  : weights 1-term fp16 pairs, PPL [N][K/2] u32
//  g_q16/k16: projected Q,K fp16 [B,H,S,DK/2] u32 pairs, PPL
//  g_v16    : projected V fp16 [B,H,DK,S] halves, key-pairs PPL
//  g_xhl    : attention out X as {hi,lo} pair uint2s, PPL (A-plane format)
// ---------------------------------------------------------------------------
__device__ __align__(16) uint2    g_ahl[3][(size_t)MM * (DD / 2)];
__device__ __align__(16) uint32_t g_wh[4][(size_t)DD * (DD / 2)];
__device__ __align__(16) uint32_t g_q16[(size_t)BB * HH * SS * (DKK / 2)];
__device__ __align__(16) uint32_t g_k16[(size_t)BB * HH * SS * (DKK / 2)];
__device__ __align__(16) uint32_t g_v16[(size_t)BB * HH * DKK * (SS / 2)];
__device__ __align__(16) uint2    g_xhl[(size_t)MM * (DD / 2)];

// ---------------------------------------------------------------------------
// helpers
// ---------------------------------------------------------------------------
__device__ __forceinline__ uint32_t smem_u32(const void* p) {
    uint32_t a;
    asm("{ .reg .u64 t; cvta.to.shared.u64 t, %1; cvt.u32.u64 %0, t; }"
        : "=r"(a) : "l"(p));
    return a;
}
__device__ __forceinline__ uint32_t pack2h(float x, float y) {
    __half2 h = __floats2half2_rn(x, y);
    return *reinterpret_cast<uint32_t*>(&h);
}
__device__ __forceinline__ void split2h(float x, float y, uint32_t& h, uint32_t& l) {
    __half hx = __float2half_rn(x);
    __half hy = __float2half_rn(y);
    __half lx = __float2half_rn(x - __half2float(hx));
    __half ly = __float2half_rn(y - __half2float(hy));
    __half2 hh = __halves2half2(hx, hy);
    __half2 ll = __halves2half2(lx, ly);
    h = *reinterpret_cast<uint32_t*>(&hh);
    l = *reinterpret_cast<uint32_t*>(&ll);
}
__device__ __forceinline__ float ex2(float x) {
    float y;
    asm("ex2.approx.f32 %0, %1;" : "=f"(y) : "f"(x));
    return y;
}
// D(16x8,f32) += A(16x16,f16) * B(16x8,f16)
__device__ __forceinline__ void mma16h(float* d, const uint32_t* a, const uint32_t* b) {
    asm("mma.sync.aligned.m16n8k16.row.col.f32.f16.f16.f32 "
        "{%0,%1,%2,%3}, {%4,%5,%6,%7}, {%8,%9}, {%0,%1,%2,%3};"
        : "+f"(d[0]), "+f"(d[1]), "+f"(d[2]), "+f"(d[3])
        : "r"(a[0]), "r"(a[1]), "r"(a[2]), "r"(a[3]),
          "r"(b[0]), "r"(b[1]));
}
__device__ __forceinline__ void cpa16(uint32_t dst, const void* src) {
    asm volatile("cp.async.cg.shared.global [%0], [%1], 16;"
                 :: "r"(dst), "l"(src) : "memory");
}
#define CP_COMMIT() asm volatile("cp.async.commit_group;" ::: "memory")

// ---------------------------------------------------------------------------
// convert kernels
// ---------------------------------------------------------------------------
// inputs -> {hi,lo} pair uint2s, PPL within each 16-elem chunk:
// uint2 positions [p0,p4,p1,p5,p2,p6,p3,p7]
__global__ __launch_bounds__(256) void cvt_in(const float* __restrict__ q,
                                              const float* __restrict__ k,
                                              const float* __restrict__ v)
{
    const float* src = (blockIdx.z == 0) ? q : ((blockIdx.z == 1) ? k : v);
    uint4* dst = (uint4*)g_ahl[blockIdx.z];
    size_t ci = (size_t)blockIdx.x * 256 + threadIdx.x;  // 16-elem chunk index
    const float4* s4 = (const float4*)src + ci * 4;
    float4 f0 = s4[0], f1 = s4[1], f2 = s4[2], f3 = s4[3];
    uint32_t h0,l0,h1,l1,h2,l2,h3,l3,h4,l4,h5,l5,h6,l6,h7,l7;
    split2h(f0.x, f0.y, h0, l0); split2h(f0.z, f0.w, h1, l1);
    split2h(f1.x, f1.y, h2, l2); split2h(f1.z, f1.w, h3, l3);
    split2h(f2.x, f2.y, h4, l4); split2h(f2.z, f2.w, h5, l5);
    split2h(f3.x, f3.y, h6, l6); split2h(f3.z, f3.w, h7, l7);
    dst[ci * 4 + 0] = make_uint4(h0, l0, h4, l4);
    dst[ci * 4 + 1] = make_uint4(h1, l1, h5, l5);
    dst[ci * 4 + 2] = make_uint4(h2, l2, h6, l6);
    dst[ci * 4 + 3] = make_uint4(h3, l3, h7, l7);
}

// weights -> 1-term fp16 pairs in PPL (per 16-elem chunk)
__global__ __launch_bounds__(256) void cvt_w(const float* __restrict__ wq,
                                             const float* __restrict__ wk,
                                             const float* __restrict__ wv,
                                             const float* __restrict__ wo)
{
    const float* src = (blockIdx.z == 0) ? wq :
                       (blockIdx.z == 1) ? wk :
                       (blockIdx.z == 2) ? wv : wo;
    uint4* dst = (uint4*)g_wh[blockIdx.z];
    size_t ci = (size_t)blockIdx.x * 256 + threadIdx.x;  // 16-elem chunk index
    const float4* s4 = (const float4*)src + ci * 4;
    float4 f0 = s4[0], f1 = s4[1], f2 = s4[2], f3 = s4[3];
    // positions: [L0, L4, L1, L5, L2, L6, L3, L7]
    dst[ci * 2]     = make_uint4(pack2h(f0.x, f0.y), pack2h(f2.x, f2.y),
                                 pack2h(f0.z, f0.w), pack2h(f2.z, f2.w));
    dst[ci * 2 + 1] = make_uint4(pack2h(f1.x, f1.y), pack2h(f3.x, f3.y),
                                 pack2h(f1.z, f1.w), pack2h(f3.z, f3.w));
}

// ---------------------------------------------------------------------------
// fp16 2-mma SGEMM with cp.async double buffer:
//   Y = (A @ W^T + bias) * alpha
// Block 128x128, BK=32, 256 threads (8 warps), warp tile 64x32.
// A: PPL {hi,lo} uint2s -> fragment = ONE uint4 LDS.128 per row-half.
//    smem stride 12 uint4/row (12%8==4 -> conflict-free 8-lane phases).
// W: PPL 1-term fp16 (stride 24 u32, LDS.64 frags).
// y_sel: 0 -> g_q16 (PPL); 1 -> g_k16 (PPL); 2 -> g_v16 (PPL keys);
//        3 -> Yout fp32 [M,N]
// ---------------------------------------------------------------------------
#define AST4 12                       // A row stride in uint4
#define BST1 24                       // B row stride in uint32 (rows = 16 u32)
#define A_STAGE_U4 (128 * AST4)       // 1536 uint4 = 24576 B
#define B_STAGE_U32 (128 * BST1)      // 3072 u32  = 12288 B
#define GSMEM_BYTES (2 * A_STAGE_U4 * 16 + 2 * B_STAGE_U32 * 4)  // 73728

struct GemmArgs {
    int a_sel;            // 0..2 -> g_ahl[z], 3 -> g_xhl
    int w_sel;            // 0..3 -> g_wh[z]
    const float* bias;
    float* Yout;          // used when y_sel == 3
    float alpha;
    int y_sel;
};

__global__ __launch_bounds__(256, 2) void gemm_fp16(GemmArgs ga, GemmArgs gb, GemmArgs gc)
{
    GemmArgs g = (blockIdx.z == 0) ? ga : ((blockIdx.z == 1) ? gb : gc);
    const uint4*    gA = (const uint4*)((g.a_sel < 3) ? g_ahl[g.a_sel] : g_xhl);
    const uint32_t* gW = g_wh[g.w_sel];

    extern __shared__ uint32_t sp[];
    const uint4* As[2] = { (const uint4*)sp, (const uint4*)sp + A_STAGE_U4 };
    const uint32_t* Bs[2] = { sp + 2 * A_STAGE_U4 * 4,
                              sp + 2 * A_STAGE_U4 * 4 + B_STAGE_U32 };
    const uint32_t sbase = smem_u32(sp);

    const int tid  = threadIdx.x;
    const int lane = tid & 31;
    const int wrp  = tid >> 5;
    const int wy   = wrp & 1;          // m-warp (0..1), 64 rows
    const int wx   = wrp >> 1;         // n-warp (0..3), 32 cols
    const int r    = lane >> 2;        // 0..7
    const int q    = lane & 3;         // 0..3
    const int bm   = blockIdx.y * 128;
    const int bn   = blockIdx.x * 128;

    const int arow[4] = { (tid + 0)   >> 3, (tid + 256) >> 3,
                          (tid + 512) >> 3, (tid + 768) >> 3 };
    const int acol    = tid & 7;                 // uint4 chunk 0..7
    const int brow[2] = { (tid + 0) >> 2, (tid + 256) >> 2 };
    const int bcol    = tid & 3;

    float c[4][4][4];
    #pragma unroll
    for (int mt = 0; mt < 4; mt++)
        #pragma unroll
        for (int nt = 0; nt < 4; nt++)
            #pragma unroll
            for (int i = 0; i < 4; i++) c[mt][nt][i] = 0.0f;

    auto issue = [&](int it, int s) {
        uint32_t aB = sbase + s * (A_STAGE_U4 * 16);
        uint32_t bB = sbase + 2 * A_STAGE_U4 * 16 + s * (B_STAGE_U32 * 4);
        #pragma unroll
        for (int i = 0; i < 4; i++) {
            int row = arow[i];
            cpa16(aB + (uint32_t)(row * AST4 + acol) * 16,
                  gA + (size_t)(bm + row) * (DD / 4) + it * 8 + acol);
        }
        #pragma unroll
        for (int i = 0; i < 2; i++) {
            int row = brow[i];
            cpa16(bB + (uint32_t)(row * BST1 + bcol * 4) * 4,
                  gW + (size_t)(bn + row) * (DD / 2) + it * 16 + bcol * 4);
        }
        CP_COMMIT();
    };

    issue(0, 0);
    const int NT = DD / 32;           // 32 k-tiles

    for (int it = 0; it < NT; it++) {
        const int s = it & 1;
        if (it + 1 < NT) issue(it + 1, (it + 1) & 1);
        if (it + 1 < NT) { asm volatile("cp.async.wait_group 1;" ::: "memory"); }
        else             { asm volatile("cp.async.wait_group 0;" ::: "memory"); }
        __syncthreads();

        const uint4*    Au = As[s];
        const uint32_t* Bu = Bs[s];
        #pragma unroll
        for (int ks = 0; ks < 2; ks++) {
            uint32_t bh[4][2];
            #pragma unroll
            for (int nt = 0; nt < 4; nt++) {
                uint2 bb = *(const uint2*)&Bu[(wx * 32 + nt * 8 + r) * BST1 + ks * 8 + 2 * q];
                bh[nt][0] = bb.x;
                bh[nt][1] = bb.y;
            }
            #pragma unroll
            for (int mt = 0; mt < 4; mt++) {
                int i0 = (wy * 64 + mt * 16 + r) * AST4 + ks * 4 + q;
                uint4 u0 = Au[i0];
                uint4 u1 = Au[i0 + 8 * AST4];
                uint32_t ah[4] = {u0.x, u1.x, u0.z, u1.z};
                uint32_t al[4] = {u0.y, u1.y, u0.w, u1.w};
                #pragma unroll
                for (int nt = 0; nt < 4; nt++) {
                    mma16h(c[mt][nt], al, bh[nt]);
                    mma16h(c[mt][nt], ah, bh[nt]);
                }
            }
        }
        __syncthreads();
    }

    // Epilogue
    #pragma unroll
    for (int mt = 0; mt < 4; mt++) {
        #pragma unroll
        for (int nt = 0; nt < 4; nt++) {
            int n = bn + wx * 32 + nt * 8 + 2 * q;
            float b0 = g.bias[n], b1 = g.bias[n + 1];
            #pragma unroll
            for (int half = 0; half < 2; half++) {
                int m = bm + wy * 64 + mt * 16 + r + half * 8;
                float vx = (c[mt][nt][2 * half]     + b0) * g.alpha;
                float vy = (c[mt][nt][2 * half + 1] + b1) * g.alpha;
                if (g.y_sel == 3) {
                    *(float2*)&g.Yout[(size_t)m * DD + n] = make_float2(vx, vy);
                } else {
                    int b  = m >> 11;         // / SS
                    int s  = m & (SS - 1);
                    int h  = n >> 6;          // / DK
                    int dk = n & 63;
                    if (g.y_sel <= 1) {
                        // PPL pair index within the 32-pair row
                        int pl  = dk >> 1;
                        int w_  = pl & 7;
                        int pos = (w_ < 4) ? 2 * w_ : 2 * (w_ - 4) + 1;
                        int pp  = ((pl >> 3) << 3) + pos;
                        uint32_t* dst = (g.y_sel == 0) ? g_q16 : g_k16;
                        dst[(((size_t)(b * HH + h)) * SS + s) * (DKK / 2) + pp]
                            = pack2h(vx, vy);
                    } else {
                        // V [dk][s], key position PPL within 16-key chunks
                        int pl  = s >> 1, lo = s & 1;
                        int w_  = pl & 7;
                        int pos = (w_ < 4) ? 2 * w_ : 2 * (w_ - 4) + 1;
                        int sp_ = ((pl >> 3) << 4) + (pos << 1) + lo;
                        __half* dst = (__half*)g_v16 +
                            ((size_t)(b * HH + h) * DKK + dk) * SS + sp_;
                        dst[0]  = __float2half_rn(vx);
                        dst[SS] = __float2half_rn(vy);
                    }
                }
            }
        }
    }
}

// ---------------------------------------------------------------------------
// fp16 flash attention, KT=64, cp.async double buffer, ex2-domain softmax.
// Denominator accumulated BY MMA (ones-column trick, o9) — no per-tile row
// sums. O-rescale is ballot-guarded (runs only when a row max increases).
// K/V planes: 64 rows x 32 u32 data, stride 40 (LDS.64 conflict-free).
// ---------------------------------------------------------------------------
#define KST 40
#define K_PLANE (64 * KST)             // 2560 u32
#define KV_STAGE (2 * K_PLANE)         // 5120 u32
#define ASMEM_BYTES (2 * KV_STAGE * 4) // 40960

__global__ __launch_bounds__(128, 4) void attn_fp16()
{
    extern __shared__ uint32_t SH[];

    const int tid  = threadIdx.x;
    const int lane = tid & 31;
    const int w    = tid >> 5;           // warp 0..3 -> query rows w*16..
    const int r    = lane >> 2;          // 0..7
    const int q    = lane & 3;           // 0..3
    const int qt   = blockIdx.x;         // 0..31
    const int bh   = blockIdx.y;         // 0..63
    const int h    = bh & (HH - 1);
    const int bb   = bh >> 4;

    const uint32_t* Qb = g_q16 + ((size_t)bh * SS + qt * 64 + w * 16) * (DKK / 2);
    const uint32_t* Kb = g_k16 + (size_t)bh * SS * (DKK / 2);
    const uint32_t* Vb = g_v16 + (size_t)bh * DKK * (SS / 2);
    const uint32_t sbase = smem_u32(SH);

    // Preload Q fragments (PPL: one uint2 = {pair q, pair q+4})
    uint32_t qh[4][4];
    #pragma unroll
    for (int kt = 0; kt < 4; kt++) {
        uint2 a0 = *(const uint2*)&Qb[(size_t)r * 32 + kt * 8 + 2 * q];
        uint2 a1 = *(const uint2*)&Qb[(size_t)(r + 8) * 32 + kt * 8 + 2 * q];
        qh[kt][0] = a0.x; qh[kt][2] = a0.y;
        qh[kt][1] = a1.x; qh[kt][3] = a1.y;
    }

    auto issue = [&](int t, int s) {
        uint32_t kB = sbase + s * (KV_STAGE * 4);
        uint32_t vB = kB + K_PLANE * 4;
        #pragma unroll
        for (int i = 0; i < 4; i++) {
            int c  = tid + i * 128;       // 0..511
            int rw = c >> 3, cc = c & 7;  // row 0..63, 16B chunk 0..7
            cpa16(kB + (uint32_t)(rw * KST + cc * 4) * 4,
                  Kb + (size_t)(t * 64 + rw) * 32 + cc * 4);
            cpa16(vB + (uint32_t)(rw * KST + cc * 4) * 4,
                  Vb + (size_t)rw * (SS / 2) + t * 32 + cc * 4);
        }
        CP_COMMIT();
    };

    float o[8][4];
    #pragma unroll
    for (int dt = 0; dt < 8; dt++)
        #pragma unroll
        for (int i = 0; i < 4; i++) o[dt][i] = 0.0f;
    float o9[4] = {0.0f, 0.0f, 0.0f, 0.0f};     // denominator accumulator
    float mrow[2] = {-1e30f, -1e30f};
    const uint32_t ones2 = 0x3C003C00u;          // fp16 {1,1}

    issue(0, 0);
    const int NT = SS / 64;              // 32 tiles

    for (int t = 0; t < NT; t++) {
        const int s = t & 1;
        if (t + 1 < NT) issue(t + 1, (t + 1) & 1);
        if (t + 1 < NT) { asm volatile("cp.async.wait_group 1;" ::: "memory"); }
        else            { asm volatile("cp.async.wait_group 0;" ::: "memory"); }
        __syncthreads();

        const uint32_t* K0 = SH + s * KV_STAGE;
        const uint32_t* V0 = K0 + K_PLANE;

        // ---- S = Q K^T (16 x 64 per warp) ----
        float sc[8][4];
        #pragma unroll
        for (int nt = 0; nt < 8; nt++)
            #pragma unroll
            for (int i = 0; i < 4; i++) sc[nt][i] = 0.0f;

        #pragma unroll
        for (int kt = 0; kt < 4; kt++) {
            const int koff = kt * 8;
            #pragma unroll
            for (int nt = 0; nt < 8; nt++) {
                uint2 kk = *(const uint2*)&K0[(nt * 8 + r) * KST + koff + 2 * q];
                uint32_t kf[2] = { kk.x, kk.y };
                mma16h(sc[nt], qh[kt], kf);
            }
        }

        // ---- online softmax (log2 domain); rescale only on max increase ----
        #pragma unroll
        for (int half = 0; half < 2; half++) {
            float rm = -1e30f;
            #pragma unroll
            for (int nt = 0; nt < 8; nt++)
                rm = fmaxf(rm, fmaxf(sc[nt][2 * half], sc[nt][2 * half + 1]));
            rm = fmaxf(rm, __shfl_xor_sync(0xffffffffu, rm, 1));
            rm = fmaxf(rm, __shfl_xor_sync(0xffffffffu, rm, 2));
            if (__ballot_sync(0xffffffffu, rm > mrow[half])) {
                float mnew  = fmaxf(mrow[half], rm);
                float scale = ex2(mrow[half] - mnew);   // ==1 where no update
                #pragma unroll
                for (int dt = 0; dt < 8; dt++) {
                    o[dt][2 * half]     *= scale;
                    o[dt][2 * half + 1] *= scale;
                }
                o9[2 * half]     *= scale;
                o9[2 * half + 1] *= scale;
                mrow[half] = mnew;
            }
            #pragma unroll
            for (int nt = 0; nt < 8; nt++) {
                sc[nt][2 * half]     = ex2(sc[nt][2 * half] - mrow[half]);
                sc[nt][2 * half + 1] = ex2(sc[nt][2 * half + 1] - mrow[half]);
            }
        }

        // ---- O += P V ; o9 += P * ones (denominator) ----
        #pragma unroll
        for (int kt = 0; kt < 4; kt++) {
            uint32_t ph[4];
            ph[0] = pack2h(sc[2 * kt][0],     sc[2 * kt][1]);
            ph[1] = pack2h(sc[2 * kt][2],     sc[2 * kt][3]);
            ph[2] = pack2h(sc[2 * kt + 1][0], sc[2 * kt + 1][1]);
            ph[3] = pack2h(sc[2 * kt + 1][2], sc[2 * kt + 1][3]);
            #pragma unroll
            for (int dt = 0; dt < 8; dt++) {
                uint2 vv = *(const uint2*)&V0[(dt * 8 + r) * KST + kt * 8 + 2 * q];
                uint32_t vh[2] = { vv.x, vv.y };
                mma16h(o[dt], ph, vh);
            }
            uint32_t of[2] = { ones2, ones2 };
            mma16h(o9, ph, of);
        }
        __syncthreads();
    }

    // Epilogue: X as {hi,lo} uint2 pairs in PPL (A-plane format)
    float inv0 = 1.0f / o9[0];
    float inv1 = 1.0f / o9[2];
    uint2* Xb = g_xhl + ((size_t)bb * SS + qt * 64 + w * 16) * (DD / 2) + h * 32;
    #pragma unroll
    for (int dt = 0; dt < 8; dt++) {
        int cp  = dt * 4 + q;               // logical pair index 0..31
        int w_  = cp & 7;
        int pos = (w_ < 4) ? 2 * w_ : 2 * (w_ - 4) + 1;
        int pp  = ((cp >> 3) << 3) + pos;   // PPL position
        uint32_t hh, ll;
        split2h(o[dt][0] * inv0, o[dt][1] * inv0, hh, ll);
        Xb[(size_t)r * (DD / 2) + pp] = make_uint2(hh, ll);
        split2h(o[dt][2] * inv1, o[dt][3] * inv1, hh, ll);
        Xb[(size_t)(r + 8) * (DD / 2) + pp] = make_uint2(hh, ll);
    }
}

// ---------------------------------------------------------------------------
extern "C" void kernel_launch(void* const* d_in, const int* in_sizes, int n_in,
                              void* d_out, int out_size)
{
    const float* query = (const float*)d_in[0];
    const float* key_  = (const float*)d_in[1];
    const float* value = (const float*)d_in[2];
    const float* Wq    = (const float*)d_in[3];
    const float* bq    = (const float*)d_in[4];
    const float* Wk    = (const float*)d_in[5];
    const float* bk    = (const float*)d_in[6];
    const float* Wv    = (const float*)d_in[7];
    const float* bv    = (const float*)d_in[8];
    const float* Wo    = (const float*)d_in[9];
    const float* bo    = (const float*)d_in[10];
    float* out = (float*)d_out;

    cudaFuncSetAttribute(gemm_fp16,
                         cudaFuncAttributeMaxDynamicSharedMemorySize, GSMEM_BYTES);
    cudaFuncSetAttribute(attn_fp16,
                         cudaFuncAttributeMaxDynamicSharedMemorySize, ASMEM_BYTES);

    // One-time (per launch) conversions
    cvt_in<<<dim3(MM * DD / 16 / 256, 1, 3), 256>>>(query, key_, value);
    cvt_w<<<dim3(DD * DD / 16 / 256, 1, 4), 256>>>(Wq, Wk, Wv, Wo);

    // Fused Q/K/V projections.
    // Q alpha = (1/8) * log2(e): scores come out in log2 domain.
    GemmArgs gq = { 0, 0, bq, nullptr, 0.18033688f, 0 };
    GemmArgs gk = { 1, 1, bk, nullptr, 1.0f,        1 };
    GemmArgs gv = { 2, 2, bv, nullptr, 1.0f,        2 };
    gemm_fp16<<<dim3(DD / 128, MM / 128, 3), 256, GSMEM_BYTES>>>(gq, gk, gv);

    // Attention (fp16 mma.sync, ones-column denominator, guarded rescale)
    attn_fp16<<<dim3(SS / 64, BB * HH), 128, ASMEM_BYTES>>>();

    // Output projection -> d_out (fp32)
    GemmArgs go = { 3, 3, bo, out, 1.0f, 3 };
    gemm_fp16<<<dim3(DD / 128, MM / 128, 1), 256, GSMEM_BYTES>>>(go, go, go);
}

// round 17
// speedup vs baseline: 6.1070x; 1.1194x over previous
#include <cuda_runtime.h>
#include <cuda_fp16.h>
#include <math.h>
#include <stdint.h>

// Problem constants
#define BB   4
#define SS   2048
#define DD   1024
#define HH   16
#define DKK  64
#define MM   (BB*SS)          // 8192 rows

// ---------------------------------------------------------------------------
// Pre-converted gmem planes
//  g_ahl[z] : inputs as {hi,lo} fp16 pair uint2s, PPL within 16-elem chunks
//  g_wh[z]  : weights 1-term fp16 pairs, PPL [N][K/2] u32
//  g_q16/k16: projected Q,K fp16 [B,H,S,DK/2] u32 pairs, PPL
//  g_v16    : projected V fp16 [B,H,DK,S] halves, key-pairs PPL
//  g_x1     : attention out X as 1-term fp16 pairs, PPL [M][D/2] u32
// PPL: within each 8-pair (16-elem) chunk, position 2j holds pair j,
//      position 2j+1 holds pair j+4 -> mma frag {q, q+4} = one 8B load.
// ---------------------------------------------------------------------------
__device__ __align__(16) uint2    g_ahl[3][(size_t)MM * (DD / 2)];
__device__ __align__(16) uint32_t g_wh[4][(size_t)DD * (DD / 2)];
__device__ __align__(16) uint32_t g_q16[(size_t)BB * HH * SS * (DKK / 2)];
__device__ __align__(16) uint32_t g_k16[(size_t)BB * HH * SS * (DKK / 2)];
__device__ __align__(16) uint32_t g_v16[(size_t)BB * HH * DKK * (SS / 2)];
__device__ __align__(16) uint32_t g_x1[(size_t)MM * (DD / 2)];

// ---------------------------------------------------------------------------
// helpers
// ---------------------------------------------------------------------------
__device__ __forceinline__ uint32_t smem_u32(const void* p) {
    uint32_t a;
    asm("{ .reg .u64 t; cvta.to.shared.u64 t, %1; cvt.u32.u64 %0, t; }"
        : "=r"(a) : "l"(p));
    return a;
}
__device__ __forceinline__ uint32_t pack2h(float x, float y) {
    __half2 h = __floats2half2_rn(x, y);
    return *reinterpret_cast<uint32_t*>(&h);
}
__device__ __forceinline__ void split2h(float x, float y, uint32_t& h, uint32_t& l) {
    __half hx = __float2half_rn(x);
    __half hy = __float2half_rn(y);
    __half lx = __float2half_rn(x - __half2float(hx));
    __half ly = __float2half_rn(y - __half2float(hy));
    __half2 hh = __halves2half2(hx, hy);
    __half2 ll = __halves2half2(lx, ly);
    h = *reinterpret_cast<uint32_t*>(&hh);
    l = *reinterpret_cast<uint32_t*>(&ll);
}
__device__ __forceinline__ float ex2(float x) {
    float y;
    asm("ex2.approx.f32 %0, %1;" : "=f"(y) : "f"(x));
    return y;
}
// D(16x8,f32) += A(16x16,f16) * B(16x8,f16)
__device__ __forceinline__ void mma16h(float* d, const uint32_t* a, const uint32_t* b) {
    asm("mma.sync.aligned.m16n8k16.row.col.f32.f16.f16.f32 "
        "{%0,%1,%2,%3}, {%4,%5,%6,%7}, {%8,%9}, {%0,%1,%2,%3};"
        : "+f"(d[0]), "+f"(d[1]), "+f"(d[2]), "+f"(d[3])
        : "r"(a[0]), "r"(a[1]), "r"(a[2]), "r"(a[3]),
          "r"(b[0]), "r"(b[1]));
}
__device__ __forceinline__ void cpa16(uint32_t dst, const void* src) {
    asm volatile("cp.async.cg.shared.global [%0], [%1], 16;"
                 :: "r"(dst), "l"(src) : "memory");
}
#define CP_COMMIT() asm volatile("cp.async.commit_group;" ::: "memory")

// ---------------------------------------------------------------------------
// merged convert kernel: z=0..2 inputs -> g_ahl (PPL {hi,lo});
//                        z=3..6 weights -> g_wh (PPL 1-term)
// ---------------------------------------------------------------------------
#define CVT_IN_BLOCKS (MM * DD / 16 / 256)   // 2048
#define CVT_W_BLOCKS  (DD * DD / 16 / 256)   // 256

__global__ __launch_bounds__(256) void cvt_all(
    const float* __restrict__ q, const float* __restrict__ k,
    const float* __restrict__ v, const float* __restrict__ wq,
    const float* __restrict__ wk, const float* __restrict__ wv,
    const float* __restrict__ wo)
{
    int z = blockIdx.z;
    if (z < 3) {
        const float* src = (z == 0) ? q : ((z == 1) ? k : v);
        uint4* dst = (uint4*)g_ahl[z];
        size_t ci = (size_t)blockIdx.x * 256 + threadIdx.x;
        const float4* s4 = (const float4*)src + ci * 4;
        float4 f0 = s4[0], f1 = s4[1], f2 = s4[2], f3 = s4[3];
        uint32_t h0,l0,h1,l1,h2,l2,h3,l3,h4,l4,h5,l5,h6,l6,h7,l7;
        split2h(f0.x, f0.y, h0, l0); split2h(f0.z, f0.w, h1, l1);
        split2h(f1.x, f1.y, h2, l2); split2h(f1.z, f1.w, h3, l3);
        split2h(f2.x, f2.y, h4, l4); split2h(f2.z, f2.w, h5, l5);
        split2h(f3.x, f3.y, h6, l6); split2h(f3.z, f3.w, h7, l7);
        dst[ci * 4 + 0] = make_uint4(h0, l0, h4, l4);
        dst[ci * 4 + 1] = make_uint4(h1, l1, h5, l5);
        dst[ci * 4 + 2] = make_uint4(h2, l2, h6, l6);
        dst[ci * 4 + 3] = make_uint4(h3, l3, h7, l7);
    } else {
        if (blockIdx.x >= CVT_W_BLOCKS) return;
        const float* src = (z == 3) ? wq : (z == 4) ? wk : (z == 5) ? wv : wo;
        uint4* dst = (uint4*)g_wh[z - 3];
        size_t ci = (size_t)blockIdx.x * 256 + threadIdx.x;
        const float4* s4 = (const float4*)src + ci * 4;
        float4 f0 = s4[0], f1 = s4[1], f2 = s4[2], f3 = s4[3];
        dst[ci * 2]     = make_uint4(pack2h(f0.x, f0.y), pack2h(f2.x, f2.y),
                                     pack2h(f0.z, f0.w), pack2h(f2.z, f2.w));
        dst[ci * 2 + 1] = make_uint4(pack2h(f1.x, f1.y), pack2h(f3.x, f3.y),
                                     pack2h(f1.z, f1.w), pack2h(f3.z, f3.w));
    }
}

// ---------------------------------------------------------------------------
// fp16 SGEMM with cp.async double buffer:  Y = (A @ W^T + bias) * alpha
// Block 128x128, BK=32, 256 threads (8 warps), warp tile 64x32.
// QKV mode (y_sel 0..2): A = PPL {hi,lo} uint4 (2 mma); W = PPL 1-term.
// OUT mode (y_sel 3):    A = PPL 1-term u32 (g_x1), W 1-term -> 1 mma.
// ---------------------------------------------------------------------------
#define AST4 12                       // A(2t) row stride in uint4
#define BST1 24                       // 1-term row stride in uint32
#define A_STAGE_U4 (128 * AST4)       // 1536 uint4 = 24576 B
#define B_STAGE_U32 (128 * BST1)      // 3072 u32  = 12288 B
#define GSMEM_BYTES (2 * A_STAGE_U4 * 16 + 2 * B_STAGE_U32 * 4)  // 73728

struct GemmArgs {
    int a_sel;            // 0..2 -> g_ahl[z], 3 -> g_x1 (1-term)
    int w_sel;            // 0..3 -> g_wh[z]
    const float* bias;
    float* Yout;          // used when y_sel == 3
    float alpha;
    int y_sel;
};

__global__ __launch_bounds__(256, 2) void gemm_fp16(GemmArgs ga, GemmArgs gb, GemmArgs gc)
{
    GemmArgs g = (blockIdx.z == 0) ? ga : ((blockIdx.z == 1) ? gb : gc);
    const bool a1t = (g.a_sel == 3);
    const uint4*    gA  = (const uint4*)g_ahl[a1t ? 0 : g.a_sel];
    const uint32_t* gA1 = g_x1;
    const uint32_t* gW  = g_wh[g.w_sel];

    extern __shared__ uint32_t sp[];
    const uint32_t sbase = smem_u32(sp);

    const int tid  = threadIdx.x;
    const int lane = tid & 31;
    const int wrp  = tid >> 5;
    const int wy   = wrp & 1;          // m-warp (0..1), 64 rows
    const int wx   = wrp >> 1;         // n-warp (0..3), 32 cols
    const int r    = lane >> 2;        // 0..7
    const int q    = lane & 3;         // 0..3
    const int bm   = blockIdx.y * 128;
    const int bn   = blockIdx.x * 128;

    float c[4][4][4];
    #pragma unroll
    for (int mt = 0; mt < 4; mt++)
        #pragma unroll
        for (int nt = 0; nt < 4; nt++)
            #pragma unroll
            for (int i = 0; i < 4; i++) c[mt][nt][i] = 0.0f;

    auto issue = [&](int it, int s) {
        uint32_t aB = sbase + s * (A_STAGE_U4 * 16);
        uint32_t bB = sbase + 2 * A_STAGE_U4 * 16 + s * (B_STAGE_U32 * 4);
        if (!a1t) {
            #pragma unroll
            for (int i = 0; i < 4; i++) {
                int row = (tid + i * 256) >> 3;
                int col = tid & 7;
                cpa16(aB + (uint32_t)(row * AST4 + col) * 16,
                      gA + (size_t)(bm + row) * (DD / 4) + it * 8 + col);
            }
        } else {
            #pragma unroll
            for (int i = 0; i < 2; i++) {
                int row = (tid + i * 256) >> 2;
                int col = tid & 3;
                cpa16(aB + (uint32_t)(row * BST1 + col * 4) * 4,
                      gA1 + (size_t)(bm + row) * (DD / 2) + it * 16 + col * 4);
            }
        }
        #pragma unroll
        for (int i = 0; i < 2; i++) {
            int row = (tid + i * 256) >> 2;
            int col = tid & 3;
            cpa16(bB + (uint32_t)(row * BST1 + col * 4) * 4,
                  gW + (size_t)(bn + row) * (DD / 2) + it * 16 + col * 4);
        }
        CP_COMMIT();
    };

    issue(0, 0);
    const int NT = DD / 32;           // 32 k-tiles

    for (int it = 0; it < NT; it++) {
        const int s = it & 1;
        if (it + 1 < NT) issue(it + 1, (it + 1) & 1);
        if (it + 1 < NT) { asm volatile("cp.async.wait_group 1;" ::: "memory"); }
        else             { asm volatile("cp.async.wait_group 0;" ::: "memory"); }
        __syncthreads();

        const uint4*    Au  = (const uint4*)sp + s * A_STAGE_U4;
        const uint32_t* Au1 = sp + s * (A_STAGE_U4 * 4);
        const uint32_t* Bu  = sp + 2 * A_STAGE_U4 * 4 + s * B_STAGE_U32;
        #pragma unroll
        for (int ks = 0; ks < 2; ks++) {
            uint32_t bh[4][2];
            #pragma unroll
            for (int nt = 0; nt < 4; nt++) {
                uint2 bb = *(const uint2*)&Bu[(wx * 32 + nt * 8 + r) * BST1 + ks * 8 + 2 * q];
                bh[nt][0] = bb.x;
                bh[nt][1] = bb.y;
            }
            if (!a1t) {
                #pragma unroll
                for (int mt = 0; mt < 4; mt++) {
                    int i0 = (wy * 64 + mt * 16 + r) * AST4 + ks * 4 + q;
                    uint4 u0 = Au[i0];
                    uint4 u1 = Au[i0 + 8 * AST4];
                    uint32_t ah[4] = {u0.x, u1.x, u0.z, u1.z};
                    uint32_t al[4] = {u0.y, u1.y, u0.w, u1.w};
                    #pragma unroll
                    for (int nt = 0; nt < 4; nt++) {
                        mma16h(c[mt][nt], al, bh[nt]);
                        mma16h(c[mt][nt], ah, bh[nt]);
                    }
                }
            } else {
                #pragma unroll
                for (int mt = 0; mt < 4; mt++) {
                    int i0 = (wy * 64 + mt * 16 + r) * BST1 + ks * 8 + 2 * q;
                    uint2 u0 = *(const uint2*)&Au1[i0];
                    uint2 u1 = *(const uint2*)&Au1[i0 + 8 * BST1];
                    uint32_t ah[4] = {u0.x, u1.x, u0.y, u1.y};
                    #pragma unroll
                    for (int nt = 0; nt < 4; nt++)
                        mma16h(c[mt][nt], ah, bh[nt]);
                }
            }
        }
        __syncthreads();
    }

    // Epilogue
    #pragma unroll
    for (int mt = 0; mt < 4; mt++) {
        #pragma unroll
        for (int nt = 0; nt < 4; nt++) {
            int n = bn + wx * 32 + nt * 8 + 2 * q;
            float b0 = g.bias[n], b1 = g.bias[n + 1];
            #pragma unroll
            for (int half = 0; half < 2; half++) {
                int m = bm + wy * 64 + mt * 16 + r + half * 8;
                float vx = (c[mt][nt][2 * half]     + b0) * g.alpha;
                float vy = (c[mt][nt][2 * half + 1] + b1) * g.alpha;
                if (g.y_sel == 3) {
                    *(float2*)&g.Yout[(size_t)m * DD + n] = make_float2(vx, vy);
                } else {
                    int b  = m >> 11;         // / SS
                    int s  = m & (SS - 1);
                    int h  = n >> 6;          // / DK
                    int dk = n & 63;
                    if (g.y_sel <= 1) {
                        int pl  = dk >> 1;
                        int w_  = pl & 7;
                        int pos = (w_ < 4) ? 2 * w_ : 2 * (w_ - 4) + 1;
                        int pp  = ((pl >> 3) << 3) + pos;
                        uint32_t* dst = (g.y_sel == 0) ? g_q16 : g_k16;
                        dst[(((size_t)(b * HH + h)) * SS + s) * (DKK / 2) + pp]
                            = pack2h(vx, vy);
                    } else {
                        int pl  = s >> 1, lo = s & 1;
                        int w_  = pl & 7;
                        int pos = (w_ < 4) ? 2 * w_ : 2 * (w_ - 4) + 1;
                        int sp_ = ((pl >> 3) << 4) + (pos << 1) + lo;
                        __half* dst = (__half*)g_v16 +
                            ((size_t)(b * HH + h) * DKK + dk) * SS + sp_;
                        dst[0]  = __float2half_rn(vx);
                        dst[SS] = __float2half_rn(vy);
                    }
                }
            }
        }
    }
}

// ---------------------------------------------------------------------------
// fp16 flash attention: 256 threads (8 warps), 128 queries per CTA, KT=64,
// cp.async double buffer, ex2-domain softmax, ones-column denominator,
// ballot-guarded rescale. K/V planes: 64 rows x 32 u32, stride 40.
// ---------------------------------------------------------------------------
#define KST 40
#define K_PLANE (64 * KST)             // 2560 u32
#define KV_STAGE (2 * K_PLANE)         // 5120 u32
#define ASMEM_BYTES (2 * KV_STAGE * 4) // 40960

__global__ __launch_bounds__(256, 2) void attn_fp16()
{
    extern __shared__ uint32_t SH[];

    const int tid  = threadIdx.x;
    const int lane = tid & 31;
    const int w    = tid >> 5;           // warp 0..7 -> query rows w*16..
    const int r    = lane >> 2;          // 0..7
    const int q    = lane & 3;           // 0..3
    const int qt   = blockIdx.x;         // 0..15 (128-query tiles)
    const int bh   = blockIdx.y;         // 0..63
    const int h    = bh & (HH - 1);
    const int bb   = bh >> 4;

    const uint32_t* Qb = g_q16 + ((size_t)bh * SS + qt * 128 + w * 16) * (DKK / 2);
    const uint32_t* Kb = g_k16 + (size_t)bh * SS * (DKK / 2);
    const uint32_t* Vb = g_v16 + (size_t)bh * DKK * (SS / 2);
    const uint32_t sbase = smem_u32(SH);

    // Preload Q fragments (PPL: one uint2 = {pair q, pair q+4})
    uint32_t qh[4][4];
    #pragma unroll
    for (int kt = 0; kt < 4; kt++) {
        uint2 a0 = *(const uint2*)&Qb[(size_t)r * 32 + kt * 8 + 2 * q];
        uint2 a1 = *(const uint2*)&Qb[(size_t)(r + 8) * 32 + kt * 8 + 2 * q];
        qh[kt][0] = a0.x; qh[kt][2] = a0.y;
        qh[kt][1] = a1.x; qh[kt][3] = a1.y;
    }

    // staging: K 512 + V 512 16B-chunks over 256 threads = 4 cpa16/thread
    auto issue = [&](int t, int s) {
        uint32_t kB = sbase + s * (KV_STAGE * 4);
        uint32_t vB = kB + K_PLANE * 4;
        #pragma unroll
        for (int i = 0; i < 2; i++) {
            int c  = tid + i * 256;       // 0..511
            int rw = c >> 3, cc = c & 7;  // row 0..63, chunk 0..7
            cpa16(kB + (uint32_t)(rw * KST + cc * 4) * 4,
                  Kb + (size_t)(t * 64 + rw) * 32 + cc * 4);
            cpa16(vB + (uint32_t)(rw * KST + cc * 4) * 4,
                  Vb + (size_t)rw * (SS / 2) + t * 32 + cc * 4);
        }
        CP_COMMIT();
    };

    float o[8][4];
    #pragma unroll
    for (int dt = 0; dt < 8; dt++)
        #pragma unroll
        for (int i = 0; i < 4; i++) o[dt][i] = 0.0f;
    float o9[4] = {0.0f, 0.0f, 0.0f, 0.0f};     // denominator accumulator
    float mrow[2] = {-1e30f, -1e30f};
    const uint32_t ones2 = 0x3C003C00u;          // fp16 {1,1}

    issue(0, 0);
    const int NT = SS / 64;              // 32 tiles

    for (int t = 0; t < NT; t++) {
        const int s = t & 1;
        if (t + 1 < NT) issue(t + 1, (t + 1) & 1);
        if (t + 1 < NT) { asm volatile("cp.async.wait_group 1;" ::: "memory"); }
        else            { asm volatile("cp.async.wait_group 0;" ::: "memory"); }
        __syncthreads();

        const uint32_t* K0 = SH + s * KV_STAGE;
        const uint32_t* V0 = K0 + K_PLANE;

        // ---- S = Q K^T (16 x 64 per warp) ----
        float sc[8][4];
        #pragma unroll
        for (int nt = 0; nt < 8; nt++)
            #pragma unroll
            for (int i = 0; i < 4; i++) sc[nt][i] = 0.0f;

        #pragma unroll
        for (int kt = 0; kt < 4; kt++) {
            const int koff = kt * 8;
            #pragma unroll
            for (int nt = 0; nt < 8; nt++) {
                uint2 kk = *(const uint2*)&K0[(nt * 8 + r) * KST + koff + 2 * q];
                uint32_t kf[2] = { kk.x, kk.y };
                mma16h(sc[nt], qh[kt], kf);
            }
        }

        // ---- online softmax (log2 domain); rescale only on max increase ----
        #pragma unroll
        for (int half = 0; half < 2; half++) {
            float rm = -1e30f;
            #pragma unroll
            for (int nt = 0; nt < 8; nt++)
                rm = fmaxf(rm, fmaxf(sc[nt][2 * half], sc[nt][2 * half + 1]));
            rm = fmaxf(rm, __shfl_xor_sync(0xffffffffu, rm, 1));
            rm = fmaxf(rm, __shfl_xor_sync(0xffffffffu, rm, 2));
            if (__ballot_sync(0xffffffffu, rm > mrow[half])) {
                float mnew  = fmaxf(mrow[half], rm);
                float scale = ex2(mrow[half] - mnew);   // ==1 where no update
                #pragma unroll
                for (int dt = 0; dt < 8; dt++) {
                    o[dt][2 * half]     *= scale;
                    o[dt][2 * half + 1] *= scale;
                }
                o9[2 * half]     *= scale;
                o9[2 * half + 1] *= scale;
                mrow[half] = mnew;
            }
            #pragma unroll
            for (int nt = 0; nt < 8; nt++) {
                sc[nt][2 * half]     = ex2(sc[nt][2 * half] - mrow[half]);
                sc[nt][2 * half + 1] = ex2(sc[nt][2 * half + 1] - mrow[half]);
            }
        }

        // ---- O += P V ; o9 += P * ones (denominator) ----
        #pragma unroll
        for (int kt = 0; kt < 4; kt++) {
            uint32_t ph[4];
            ph[0] = pack2h(sc[2 * kt][0],     sc[2 * kt][1]);
            ph[1] = pack2h(sc[2 * kt][2],     sc[2 * kt][3]);
            ph[2] = pack2h(sc[2 * kt + 1][0], sc[2 * kt + 1][1]);
            ph[3] = pack2h(sc[2 * kt + 1][2], sc[2 * kt + 1][3]);
            #pragma unroll
            for (int dt = 0; dt < 8; dt++) {
                uint2 vv = *(const uint2*)&V0[(dt * 8 + r) * KST + kt * 8 + 2 * q];
                uint32_t vh[2] = { vv.x, vv.y };
                mma16h(o[dt], ph, vh);
            }
            uint32_t of[2] = { ones2, ones2 };
            mma16h(o9, ph, of);
        }
        __syncthreads();
    }

    // Epilogue: X as 1-term fp16 pairs in PPL (out-proj A format)
    float inv0 = 1.0f / o9[0];
    float inv1 = 1.0f / o9[2];
    uint32_t* Xb = g_x1 + ((size_t)bb * SS + qt * 128 + w * 16) * (DD / 2) + h * 32;
    #pragma unroll
    for (int dt = 0; dt < 8; dt++) {
        int cp  = dt * 4 + q;               // logical pair index 0..31
        int w_  = cp & 7;
        int pos = (w_ < 4) ? 2 * w_ : 2 * (w_ - 4) + 1;
        int pp  = ((cp >> 3) << 3) + pos;   // PPL position
        Xb[(size_t)r * (DD / 2) + pp]       = pack2h(o[dt][0] * inv0, o[dt][1] * inv0);
        Xb[(size_t)(r + 8) * (DD / 2) + pp] = pack2h(o[dt][2] * inv1, o[dt][3] * inv1);
    }
}

// ---------------------------------------------------------------------------
extern "C" void kernel_launch(void* const* d_in, const int* in_sizes, int n_in,
                              void* d_out, int out_size)
{
    const float* query = (const float*)d_in[0];
    const float* key_  = (const float*)d_in[1];
    const float* value = (const float*)d_in[2];
    const float* Wq    = (const float*)d_in[3];
    const float* bq    = (const float*)d_in[4];
    const float* Wk    = (const float*)d_in[5];
    const float* bk    = (const float*)d_in[6];
    const float* Wv    = (const float*)d_in[7];
    const float* bv    = (const float*)d_in[8];
    const float* Wo    = (const float*)d_in[9];
    const float* bo    = (const float*)d_in[10];
    float* out = (float*)d_out;

    cudaFuncSetAttribute(gemm_fp16,
                         cudaFuncAttributeMaxDynamicSharedMemorySize, GSMEM_BYTES);
    cudaFuncSetAttribute(attn_fp16,
                         cudaFuncAttributeMaxDynamicSharedMemorySize, ASMEM_BYTES);

    // One merged conversion launch
    cvt_all<<<dim3(CVT_IN_BLOCKS, 1, 7), 256>>>(query, key_, value, Wq, Wk, Wv, Wo);

    // Fused Q/K/V projections.  Q alpha = (1/8)*log2(e) -> log2-domain scores.
    GemmArgs gq = { 0, 0, bq, nullptr, 0.18033688f, 0 };
    GemmArgs gk = { 1, 1, bk, nullptr, 1.0f,        1 };
    GemmArgs gv = { 2, 2, bv, nullptr, 1.0f,        2 };
    gemm_fp16<<<dim3(DD / 128, MM / 128, 3), 256, GSMEM_BYTES>>>(gq, gk, gv);

    // Attention (256 threads, 128 queries/CTA)
    attn_fp16<<<dim3(SS / 128, BB * HH), 256, ASMEM_BYTES>>>();

    // Output projection (1-term x 1-term) -> d_out (fp32)
    GemmArgs go = { 3, 3, bo, out, 1.0f, 3 };
    gemm_fp16<<<dim3(DD / 128, MM / 128, 1), 256, GSMEM_BYTES>>>(go, go, go);
}